// round 9
// baseline (speedup 1.0000x reference)
#include <cuda_runtime.h>
#include <cuda_bf16.h>
#include <stdint.h>

#define NNODES 40000
#define NEDGES 640000
#define NGRAPH 64
#define DIN    128
#define DH     256
#define DOUTC  128

#define SCAN_B 256
#define SCAN_NB ((NNODES + SCAN_B - 1) / SCAN_B)   // 157

// ---- scratch (no allocations allowed) ----
__device__ float g_bufA[NNODES * DH];
__device__ float g_bufB[NNODES * DH];
__device__ float g_dis[NNODES];
// CSR scratch
__device__ int   g_cnti[NNODES];
__device__ int   g_rowptr[NNODES + 1];
__device__ int   g_cursor[NNODES];
__device__ int2  g_epack[NEDGES];          // {src, coef-as-int}
__device__ int   g_bsum[SCAN_NB];
__device__ int   g_bpre[SCAN_NB];
// weights transposed to [NOUT, K] row-major, bf16 hi/lo split
__device__ __nv_bfloat16 g_w1_hi[DH * DIN];
__device__ __nv_bfloat16 g_w1_lo[DH * DIN];
__device__ __nv_bfloat16 g_w2_hi[DH * DH];
__device__ __nv_bfloat16 g_w2_lo[DH * DH];
__device__ __nv_bfloat16 g_w3_hi[DOUTC * DH];
__device__ __nv_bfloat16 g_w3_lo[DOUTC * DH];

// ---------------------------------------------------------------------------
// small utility kernels
// ---------------------------------------------------------------------------
__global__ void fill_kernel(float4* __restrict__ p, float v, int n4) {
    int i = blockIdx.x * blockDim.x + threadIdx.x;
    float4 f = make_float4(v, v, v, v);
    for (; i < n4; i += gridDim.x * blockDim.x) p[i] = f;
}

__device__ __forceinline__ void wsplit(const float* __restrict__ W,
                                       __nv_bfloat16* __restrict__ hi,
                                       __nv_bfloat16* __restrict__ lo,
                                       int K, int NOUT, int idx) {
    int k = idx / NOUT, n = idx - k * NOUT;
    float v = W[idx];
    __nv_bfloat16 h = __float2bfloat16(v);
    __nv_bfloat16 l = __float2bfloat16(v - __bfloat162float(h));
    hi[(size_t)n * K + k] = h;
    lo[(size_t)n * K + k] = l;
}

__global__ void prep_kernel(const float* __restrict__ W1, const float* __restrict__ W2,
                            const float* __restrict__ W3) {
    constexpr int E1 = DIN * DH;
    constexpr int E2 = E1 + DH * DH;
    constexpr int E3 = E2 + DH * DOUTC;
    constexpr int TOT = E3 + NNODES;
    int i = blockIdx.x * blockDim.x + threadIdx.x;
    for (; i < TOT; i += gridDim.x * blockDim.x) {
        if (i < E1)       wsplit(W1, g_w1_hi, g_w1_lo, DIN, DH, i);
        else if (i < E2)  wsplit(W2, g_w2_hi, g_w2_lo, DH, DH, i - E1);
        else if (i < E3)  wsplit(W3, g_w3_hi, g_w3_lo, DH, DOUTC, i - E2);
        else              g_cnti[i - E3] = 0;
    }
}

__global__ void hist_kernel(const int* __restrict__ dst, int E) {
    int e = blockIdx.x * blockDim.x + threadIdx.x;
    if (e < E) atomicAdd(&g_cnti[dst[e]], 1);
}

// ---------------------------------------------------------------------------
// three-phase scan of g_cnti -> g_rowptr / g_cursor (scan1 also emits dis)
// ---------------------------------------------------------------------------
__global__ void scan1_kernel() {
    __shared__ int s[SCAN_B];
    int i = blockIdx.x * SCAN_B + threadIdx.x;
    int v = (i < NNODES) ? g_cnti[i] : 0;
    if (i < NNODES) g_dis[i] = rsqrtf((float)v + 1.0f);
    s[threadIdx.x] = v;
    __syncthreads();
    for (int off = SCAN_B / 2; off > 0; off >>= 1) {
        if (threadIdx.x < off) s[threadIdx.x] += s[threadIdx.x + off];
        __syncthreads();
    }
    if (threadIdx.x == 0) g_bsum[blockIdx.x] = s[0];
}

__global__ void scan2_kernel() {
    __shared__ int s[SCAN_NB];
    int t = threadIdx.x;
    if (t < SCAN_NB) s[t] = g_bsum[t];
    __syncthreads();
    for (int off = 1; off < SCAN_NB; off <<= 1) {
        int v = 0;
        if (t < SCAN_NB && t >= off) v = s[t - off];
        __syncthreads();
        if (t < SCAN_NB && t >= off) s[t] += v;
        __syncthreads();
    }
    if (t < SCAN_NB) g_bpre[t] = (t == 0) ? 0 : s[t - 1];
    if (t == 0) g_rowptr[NNODES] = NEDGES;
}

__global__ void scan3_kernel() {
    __shared__ int s[SCAN_B];
    int i = blockIdx.x * SCAN_B + threadIdx.x;
    int t = threadIdx.x;
    int v0 = (i < NNODES) ? g_cnti[i] : 0;
    s[t] = v0;
    __syncthreads();
    for (int off = 1; off < SCAN_B; off <<= 1) {
        int v = (t >= off) ? s[t - off] : 0;
        __syncthreads();
        s[t] += v;
        __syncthreads();
    }
    if (i < NNODES) {
        int ex = g_bpre[blockIdx.x] + s[t] - v0;
        g_rowptr[i] = ex;
        g_cursor[i] = ex;
    }
}

__global__ void csrfill_kernel(const int* __restrict__ src, const int* __restrict__ dst,
                               int E) {
    int e = blockIdx.x * blockDim.x + threadIdx.x;
    if (e >= E) return;
    int s = src[e], d = dst[e];
    int p = atomicAdd(&g_cursor[d], 1);
    g_epack[p] = make_int2(s, __float_as_int(g_dis[s] * g_dis[d]));
}

// ---------------------------------------------------------------------------
// mma helper
// ---------------------------------------------------------------------------
__device__ __forceinline__ void mma16816(float* c, const uint32_t* a, const uint32_t* b) {
    asm volatile(
        "mma.sync.aligned.m16n8k16.row.col.f32.bf16.bf16.f32 "
        "{%0,%1,%2,%3}, {%4,%5,%6,%7}, {%8,%9}, {%0,%1,%2,%3};"
        : "+f"(c[0]), "+f"(c[1]), "+f"(c[2]), "+f"(c[3])
        : "r"(a[0]), "r"(a[1]), "r"(a[2]), "r"(a[3]), "r"(b[0]), "r"(b[1]));
}

__device__ __forceinline__ uint32_t bfpack(float x, float y) {
    __nv_bfloat16 h0 = __float2bfloat16(x);
    __nv_bfloat16 h1 = __float2bfloat16(y);
    return (uint32_t)__bfloat16_as_ushort(h0) | ((uint32_t)__bfloat16_as_ushort(h1) << 16);
}

// ---------------------------------------------------------------------------
// fused gather + 3xBF16 GEMM:  C[64-tile, NOUT] = propagate(h)[tile] @ W + bias (relu)
// grid 625 CTAs x 256 thr, 2 CTAs/SM -> gather (L2) overlaps MMA (tensor)
// phase 1: gather this CTA's 64 nodes into SMEM as bf16 hi/lo (full K)
// phase 2: per 32-k chunk, load W tile, mma.sync 3-way split
// ---------------------------------------------------------------------------
template <int K, int NOUT>
__global__ void __launch_bounds__(256, 2)
fused_gg_kernel(const float* __restrict__ h, const __nv_bfloat16* __restrict__ Whi,
                const __nv_bfloat16* __restrict__ Wlo, const float* __restrict__ bias,
                float* __restrict__ C) {
    extern __shared__ char smem[];
    constexpr int AP = K + 8;                 // padded A row (elements)
    __nv_bfloat16* AsH = (__nv_bfloat16*)smem;
    __nv_bfloat16* AsL = AsH + 64 * AP;
    __nv_bfloat16* BsH = AsL + 64 * AP;       // [NOUT][40]
    __nv_bfloat16* BsL = BsH + NOUT * 40;

    const int tid = threadIdx.x;
    const int wid = tid >> 5, lane = tid & 31;
    const int m0 = blockIdx.x * 64;

    // ---------------- phase 1: gather 64 nodes into SMEM ----------------
    {
        constexpr int HALVES = K / 128;
        for (int t = wid; t < 64 * HALVES; t += 8) {
            int nl  = t / HALVES;             // local node 0..63
            int n   = m0 + nl;
            int col = (t - nl * HALVES) * 128 + lane * 4;

            int p  = __ldg(&g_rowptr[n]);
            int p1 = __ldg(&g_rowptr[n + 1]);
            float4 acc = make_float4(0.f, 0.f, 0.f, 0.f);
            for (; p + 3 < p1; p += 4) {
                int2 e0 = __ldg(&g_epack[p]);
                int2 e1 = __ldg(&g_epack[p + 1]);
                int2 e2 = __ldg(&g_epack[p + 2]);
                int2 e3 = __ldg(&g_epack[p + 3]);
                float c0 = __int_as_float(e0.y), c1 = __int_as_float(e1.y);
                float c2 = __int_as_float(e2.y), c3 = __int_as_float(e3.y);
                float4 v0 = __ldg((const float4*)(h + (size_t)e0.x * K + col));
                float4 v1 = __ldg((const float4*)(h + (size_t)e1.x * K + col));
                float4 v2 = __ldg((const float4*)(h + (size_t)e2.x * K + col));
                float4 v3 = __ldg((const float4*)(h + (size_t)e3.x * K + col));
                acc.x += c0 * v0.x + c1 * v1.x + c2 * v2.x + c3 * v3.x;
                acc.y += c0 * v0.y + c1 * v1.y + c2 * v2.y + c3 * v3.y;
                acc.z += c0 * v0.z + c1 * v1.z + c2 * v2.z + c3 * v3.z;
                acc.w += c0 * v0.w + c1 * v1.w + c2 * v2.w + c3 * v3.w;
            }
            for (; p < p1; ++p) {
                int2 e = __ldg(&g_epack[p]);
                float c = __int_as_float(e.y);
                float4 v = __ldg((const float4*)(h + (size_t)e.x * K + col));
                acc.x += c * v.x; acc.y += c * v.y; acc.z += c * v.z; acc.w += c * v.w;
            }
            float dis = g_dis[n];
            float c2 = dis * dis;
            float4 hv = __ldg((const float4*)(h + (size_t)n * K + col));
            acc.x += c2 * hv.x; acc.y += c2 * hv.y;
            acc.z += c2 * hv.z; acc.w += c2 * hv.w;

            // split to hi/lo bf16 and store
            uint32_t hp0 = bfpack(acc.x, acc.y);
            uint32_t hp1 = bfpack(acc.z, acc.w);
            float2 hi0 = make_float2(__bfloat162float(__ushort_as_bfloat16((unsigned short)hp0)),
                                     __bfloat162float(__ushort_as_bfloat16((unsigned short)(hp0 >> 16))));
            float2 hi1 = make_float2(__bfloat162float(__ushort_as_bfloat16((unsigned short)hp1)),
                                     __bfloat162float(__ushort_as_bfloat16((unsigned short)(hp1 >> 16))));
            uint32_t lp0 = bfpack(acc.x - hi0.x, acc.y - hi0.y);
            uint32_t lp1 = bfpack(acc.z - hi1.x, acc.w - hi1.y);
            *(uint32_t*)&AsH[nl * AP + col]     = hp0;
            *(uint32_t*)&AsH[nl * AP + col + 2] = hp1;
            *(uint32_t*)&AsL[nl * AP + col]     = lp0;
            *(uint32_t*)&AsL[nl * AP + col + 2] = lp1;
        }
    }
    __syncthreads();

    // ---------------- phase 2: GEMM ----------------
    const int mw = (wid & 1) * 32;            // warp row offset (2 x 4 warp grid)
    const int nw = (wid >> 1) * 64;           // warp col offset
    const int ar = lane >> 2;
    const int ac = (lane & 3) * 2;

    float acc[2][8][4] = {};                  // 32x64 warp tile

    for (int kc = 0; kc < K / 32; ++kc) {
        // load W chunk: [NOUT rows][32 k] hi+lo
        {
            constexpr int NU4 = NOUT * 4;     // uint4 count per buffer
            #pragma unroll
            for (int it = 0; it < NU4 / 256; ++it) {
                int idx = tid + it * 256;
                int r  = idx >> 2;
                int c8 = (idx & 3) * 8;
                *(uint4*)&BsH[r * 40 + c8] =
                    *(const uint4*)(Whi + (size_t)r * K + kc * 32 + c8);
                *(uint4*)&BsL[r * 40 + c8] =
                    *(const uint4*)(Wlo + (size_t)r * K + kc * 32 + c8);
            }
        }
        __syncthreads();

        #pragma unroll
        for (int k16 = 0; k16 < 32; k16 += 16) {
            const int ka = kc * 32 + k16 + ac;
            uint32_t ah[2][4], al[2][4];
            #pragma unroll
            for (int mt = 0; mt < 2; ++mt) {
                int r = mw + mt * 16 + ar;
                ah[mt][0] = *(uint32_t*)&AsH[r * AP + ka];
                ah[mt][1] = *(uint32_t*)&AsH[(r + 8) * AP + ka];
                ah[mt][2] = *(uint32_t*)&AsH[r * AP + ka + 8];
                ah[mt][3] = *(uint32_t*)&AsH[(r + 8) * AP + ka + 8];
                al[mt][0] = *(uint32_t*)&AsL[r * AP + ka];
                al[mt][1] = *(uint32_t*)&AsL[(r + 8) * AP + ka];
                al[mt][2] = *(uint32_t*)&AsL[r * AP + ka + 8];
                al[mt][3] = *(uint32_t*)&AsL[(r + 8) * AP + ka + 8];
            }
            #pragma unroll
            for (int nt = 0; nt < 8; ++nt) {
                int rb = (nw + nt * 8 + ar) * 40 + k16 + ac;
                uint32_t bh[2], bl[2];
                bh[0] = *(uint32_t*)&BsH[rb];
                bh[1] = *(uint32_t*)&BsH[rb + 8];
                bl[0] = *(uint32_t*)&BsL[rb];
                bl[1] = *(uint32_t*)&BsL[rb + 8];
                #pragma unroll
                for (int mt = 0; mt < 2; ++mt) {
                    mma16816(acc[mt][nt], ah[mt], bh);
                    mma16816(acc[mt][nt], ah[mt], bl);
                    mma16816(acc[mt][nt], al[mt], bh);
                }
            }
        }
        __syncthreads();
    }

    // ---------------- epilogue: bias + relu ----------------
    #pragma unroll
    for (int mt = 0; mt < 2; ++mt) {
        int r0 = m0 + mw + mt * 16 + ar;
        #pragma unroll
        for (int nt = 0; nt < 8; ++nt) {
            int c = nw + nt * 8 + ac;
            float b0 = __ldg(&bias[c]), b1 = __ldg(&bias[c + 1]);
            float2 o0 = make_float2(fmaxf(acc[mt][nt][0] + b0, 0.f),
                                    fmaxf(acc[mt][nt][1] + b1, 0.f));
            float2 o1 = make_float2(fmaxf(acc[mt][nt][2] + b0, 0.f),
                                    fmaxf(acc[mt][nt][3] + b1, 0.f));
            *(float2*)(C + (size_t)r0 * NOUT + c) = o0;
            *(float2*)(C + (size_t)(r0 + 8) * NOUT + c) = o1;
        }
    }
}

// ---------------------------------------------------------------------------
// plain 3xBF16 GEMM (layer 3), pipelined, 128x128 tile (from R7)
// ---------------------------------------------------------------------------
template <int K, bool BRELU>
__global__ void __launch_bounds__(512)
mma_gemm_kernel(const float* __restrict__ A, const __nv_bfloat16* __restrict__ Whi,
                const __nv_bfloat16* __restrict__ Wlo, const float* __restrict__ bias,
                float* __restrict__ C, int N, int NOUT) {
    __shared__ __nv_bfloat16 AsH[128][40];
    __shared__ __nv_bfloat16 AsL[128][40];
    __shared__ __nv_bfloat16 BsH[128][40];
    __shared__ __nv_bfloat16 BsL[128][40];

    const int tid = threadIdx.x;
    const int wid = tid >> 5, lane = tid & 31;
    const int mw = (wid & 3) * 32;
    const int nw = (wid >> 2) * 32;
    const int m0 = blockIdx.y * 128;
    const int n0 = blockIdx.x * 128;

    float acc[2][4][4] = {};
    const int ar = lane >> 2;
    const int ac = (lane & 3) * 2;

    float2 va[4];
    uint4 vbh, vbl;
    const int br = tid >> 2;
    const int bc = (tid & 3) * 8;

    auto load_tile = [&](int kt) {
        #pragma unroll
        for (int it = 0; it < 4; ++it) {
            int idx = tid + it * 512;
            int r  = idx >> 4;
            int kp = (idx & 15) * 2;
            int rr = min(m0 + r, N - 1);
            va[it] = *(const float2*)(A + (size_t)rr * K + kt + kp);
        }
        vbh = *(const uint4*)(Whi + (size_t)(n0 + br) * K + kt + bc);
        vbl = *(const uint4*)(Wlo + (size_t)(n0 + br) * K + kt + bc);
    };
    auto store_tile = [&]() {
        #pragma unroll
        for (int it = 0; it < 4; ++it) {
            int idx = tid + it * 512;
            int r  = idx >> 4;
            int kp = (idx & 15) * 2;
            __nv_bfloat16 h0 = __float2bfloat16(va[it].x);
            __nv_bfloat16 h1 = __float2bfloat16(va[it].y);
            __nv_bfloat16 l0 = __float2bfloat16(va[it].x - __bfloat162float(h0));
            __nv_bfloat16 l1 = __float2bfloat16(va[it].y - __bfloat162float(h1));
            *(uint32_t*)&AsH[r][kp] = (uint32_t)__bfloat16_as_ushort(h0) |
                                      ((uint32_t)__bfloat16_as_ushort(h1) << 16);
            *(uint32_t*)&AsL[r][kp] = (uint32_t)__bfloat16_as_ushort(l0) |
                                      ((uint32_t)__bfloat16_as_ushort(l1) << 16);
        }
        *(uint4*)&BsH[br][bc] = vbh;
        *(uint4*)&BsL[br][bc] = vbl;
    };

    load_tile(0);
    store_tile();
    __syncthreads();

    for (int kt = 0; kt < K; kt += 32) {
        const bool more = (kt + 32) < K;
        if (more) load_tile(kt + 32);

        #pragma unroll
        for (int k16 = 0; k16 < 32; k16 += 16) {
            uint32_t ah[2][4], al[2][4];
            #pragma unroll
            for (int mt = 0; mt < 2; ++mt) {
                int r = mw + mt * 16 + ar;
                ah[mt][0] = *(uint32_t*)&AsH[r][k16 + ac];
                ah[mt][1] = *(uint32_t*)&AsH[r + 8][k16 + ac];
                ah[mt][2] = *(uint32_t*)&AsH[r][k16 + ac + 8];
                ah[mt][3] = *(uint32_t*)&AsH[r + 8][k16 + ac + 8];
                al[mt][0] = *(uint32_t*)&AsL[r][k16 + ac];
                al[mt][1] = *(uint32_t*)&AsL[r + 8][k16 + ac];
                al[mt][2] = *(uint32_t*)&AsL[r][k16 + ac + 8];
                al[mt][3] = *(uint32_t*)&AsL[r + 8][k16 + ac + 8];
            }
            uint32_t bh[4][2], bl[4][2];
            #pragma unroll
            for (int nt = 0; nt < 4; ++nt) {
                int r = nw + nt * 8 + ar;
                bh[nt][0] = *(uint32_t*)&BsH[r][k16 + ac];
                bh[nt][1] = *(uint32_t*)&BsH[r][k16 + ac + 8];
                bl[nt][0] = *(uint32_t*)&BsL[r][k16 + ac];
                bl[nt][1] = *(uint32_t*)&BsL[r][k16 + ac + 8];
            }
            #pragma unroll
            for (int mt = 0; mt < 2; ++mt)
                #pragma unroll
                for (int nt = 0; nt < 4; ++nt) {
                    mma16816(acc[mt][nt], ah[mt], bh[nt]);
                    mma16816(acc[mt][nt], ah[mt], bl[nt]);
                    mma16816(acc[mt][nt], al[mt], bh[nt]);
                }
        }
        if (more) {
            __syncthreads();
            store_tile();
            __syncthreads();
        }
    }

    #pragma unroll
    for (int mt = 0; mt < 2; ++mt) {
        int r0 = m0 + mw + mt * 16 + ar;
        #pragma unroll
        for (int nt = 0; nt < 4; ++nt) {
            int c = n0 + nw + nt * 8 + ac;
            float2 o0 = make_float2(acc[mt][nt][0], acc[mt][nt][1]);
            float2 o1 = make_float2(acc[mt][nt][2], acc[mt][nt][3]);
            if (BRELU) {
                float b0 = __ldg(&bias[c]), b1 = __ldg(&bias[c + 1]);
                o0.x = fmaxf(o0.x + b0, 0.f); o0.y = fmaxf(o0.y + b1, 0.f);
                o1.x = fmaxf(o1.x + b0, 0.f); o1.y = fmaxf(o1.y + b1, 0.f);
            }
            if (r0 < N)     *(float2*)(C + (size_t)r0 * NOUT + c) = o0;
            if (r0 + 8 < N) *(float2*)(C + (size_t)(r0 + 8) * NOUT + c) = o1;
        }
    }
}

// ---------------------------------------------------------------------------
// standalone gather (layer 3 epilogue): + bias, no relu
// ---------------------------------------------------------------------------
template <int H, bool RELU, bool BIAS>
__global__ void gather_kernel(const float* __restrict__ h, const float* __restrict__ bias,
                              float* __restrict__ out) {
    constexpr int HALVES = H / 128;
    int w = (blockIdx.x * blockDim.x + threadIdx.x) >> 5;
    int n = w / HALVES;
    if (n >= NNODES) return;
    int half = w - n * HALVES;
    int lane = threadIdx.x & 31;
    int col  = half * 128 + lane * 4;

    int p  = __ldg(&g_rowptr[n]);
    int p1 = __ldg(&g_rowptr[n + 1]);

    float4 acc = make_float4(0.f, 0.f, 0.f, 0.f);
    for (; p + 3 < p1; p += 4) {
        int2 e0 = __ldg(&g_epack[p]);
        int2 e1 = __ldg(&g_epack[p + 1]);
        int2 e2 = __ldg(&g_epack[p + 2]);
        int2 e3 = __ldg(&g_epack[p + 3]);
        float c0 = __int_as_float(e0.y), c1 = __int_as_float(e1.y);
        float c2 = __int_as_float(e2.y), c3 = __int_as_float(e3.y);
        float4 v0 = __ldg((const float4*)(h + (size_t)e0.x * H + col));
        float4 v1 = __ldg((const float4*)(h + (size_t)e1.x * H + col));
        float4 v2 = __ldg((const float4*)(h + (size_t)e2.x * H + col));
        float4 v3 = __ldg((const float4*)(h + (size_t)e3.x * H + col));
        acc.x += c0 * v0.x + c1 * v1.x + c2 * v2.x + c3 * v3.x;
        acc.y += c0 * v0.y + c1 * v1.y + c2 * v2.y + c3 * v3.y;
        acc.z += c0 * v0.z + c1 * v1.z + c2 * v2.z + c3 * v3.z;
        acc.w += c0 * v0.w + c1 * v1.w + c2 * v2.w + c3 * v3.w;
    }
    for (; p < p1; ++p) {
        int2 e = __ldg(&g_epack[p]);
        float c = __int_as_float(e.y);
        float4 v = __ldg((const float4*)(h + (size_t)e.x * H + col));
        acc.x += c * v.x; acc.y += c * v.y; acc.z += c * v.z; acc.w += c * v.w;
    }

    float dis = g_dis[n];
    float c2 = dis * dis;
    float4 hv = __ldg((const float4*)(h + (size_t)n * H + col));
    float4 r;
    r.x = acc.x + c2 * hv.x;
    r.y = acc.y + c2 * hv.y;
    r.z = acc.z + c2 * hv.z;
    r.w = acc.w + c2 * hv.w;
    if (BIAS) {
        float4 bv = __ldg((const float4*)(bias + col));
        r.x += bv.x; r.y += bv.y; r.z += bv.z; r.w += bv.w;
    }
    if (RELU) {
        r.x = fmaxf(r.x, 0.f); r.y = fmaxf(r.y, 0.f);
        r.z = fmaxf(r.z, 0.f); r.w = fmaxf(r.w, 0.f);
    }
    *(float4*)(out + (size_t)n * H + col) = r;
}

// ---------------------------------------------------------------------------
// pooling + fused finish
// ---------------------------------------------------------------------------
__global__ void pool_kernel(const float* __restrict__ ne, const int* __restrict__ batch,
                            float* __restrict__ gsum, int N) {
    int c  = threadIdx.x;
    int n0 = blockIdx.x * 256;
    int n1 = min(n0 + 256, N);
    float acc = 0.0f;
    int cur = -1;
    for (int n = n0; n < n1; ++n) {
        int g = __ldg(&batch[n]);
        if (g != cur) {
            if (cur >= 0) atomicAdd(&gsum[cur * DOUTC + c], acc);
            acc = 0.0f;
            cur = g;
        }
        acc += ne[(size_t)n * DOUTC + c];
    }
    if (cur >= 0) atomicAdd(&gsum[cur * DOUTC + c], acc);
}

__global__ void finish_kernel(const int* __restrict__ batch, float* __restrict__ gsum,
                              const float* __restrict__ Wc, const float* __restrict__ bc,
                              float* __restrict__ logit) {
    int g = blockIdx.x;
    __shared__ float cnt_s;
    __shared__ float row[DOUTC];
    if (threadIdx.x == 0) {
        int lo = 0, hi = NNODES;
        while (lo < hi) { int mid = (lo + hi) >> 1; if (__ldg(&batch[mid]) < g) lo = mid + 1; else hi = mid; }
        int lb = lo;
        lo = 0; hi = NNODES;
        while (lo < hi) { int mid = (lo + hi) >> 1; if (__ldg(&batch[mid]) <= g) lo = mid + 1; else hi = mid; }
        cnt_s = fmaxf((float)(lo - lb), 1.0f);
    }
    __syncthreads();
    int c = threadIdx.x;
    float v = gsum[g * DOUTC + c] / cnt_s;
    gsum[g * DOUTC + c] = v;
    row[c] = v;
    __syncthreads();
    if (c < 2) {
        float s = __ldg(&bc[c]);
        #pragma unroll 8
        for (int k = 0; k < DOUTC; ++k) s += row[k] * __ldg(&Wc[k * 2 + c]);
        logit[g * 2 + c] = s;
    }
}

// ---------------------------------------------------------------------------
// launch
// ---------------------------------------------------------------------------
extern "C" void kernel_launch(void* const* d_in, const int* in_sizes, int n_in,
                              void* d_out, int out_size) {
    const float* x     = (const float*)d_in[0];
    const int*   ei    = (const int*)d_in[1];
    const int*   batch = (const int*)d_in[2];
    const float* W_in  = (const float*)d_in[3];
    const float* b_in  = (const float*)d_in[4];
    const float* W_mid = (const float*)d_in[5];
    const float* b_mid = (const float*)d_in[6];
    const float* W_out = (const float*)d_in[7];
    const float* b_out = (const float*)d_in[8];
    const float* W_cls = (const float*)d_in[9];
    const float* b_cls = (const float*)d_in[10];

    const int* src = ei;
    const int* dst = ei + NEDGES;

    float *bufA, *bufB;
    __nv_bfloat16 *w1h, *w1l, *w2h, *w2l, *w3h, *w3l;
    cudaGetSymbolAddress((void**)&bufA, g_bufA);
    cudaGetSymbolAddress((void**)&bufB, g_bufB);
    cudaGetSymbolAddress((void**)&w1h, g_w1_hi);
    cudaGetSymbolAddress((void**)&w1l, g_w1_lo);
    cudaGetSymbolAddress((void**)&w2h, g_w2_hi);
    cudaGetSymbolAddress((void**)&w2l, g_w2_lo);
    cudaGetSymbolAddress((void**)&w3h, g_w3_hi);
    cudaGetSymbolAddress((void**)&w3l, g_w3_lo);

    float* node   = (float*)d_out;
    float* gsum   = node + (size_t)NNODES * DOUTC;
    float* logit  = gsum + NGRAPH * DOUTC;

    const int T = 256;

    // fused-kernel smem sizes
    const int SM1 = (64 * (DIN + 8) * 2 + 2 * DH * 40) * 2;   // 75,776 B
    const int SM2 = (64 * (DH + 8) * 2 + 2 * DH * 40) * 2;    // 108,544 B
    cudaFuncSetAttribute(fused_gg_kernel<DIN, DH>,
                         cudaFuncAttributeMaxDynamicSharedMemorySize, SM1);
    cudaFuncSetAttribute(fused_gg_kernel<DH, DH>,
                         cudaFuncAttributeMaxDynamicSharedMemorySize, SM2);

    // ----- prep (weights + zero counters) and CSR build -----
    prep_kernel<<<680, T>>>(W_in, W_mid, W_out);
    hist_kernel<<<(NEDGES + T - 1) / T, T>>>(dst, NEDGES);
    scan1_kernel<<<SCAN_NB, SCAN_B>>>();
    scan2_kernel<<<1, SCAN_B>>>();
    scan3_kernel<<<SCAN_NB, SCAN_B>>>();
    csrfill_kernel<<<(NEDGES + T - 1) / T, T>>>(src, dst, NEDGES);

    const int GB64 = NNODES / 64;   // 625

    // ----- layer 1: fused propagate(x) -> @W_in + b_in + relu -----
    fused_gg_kernel<DIN, DH><<<GB64, 256, SM1>>>(x, w1h, w1l, b_in, bufA);

    // ----- layer 2: fused propagate(h1) -> @W_mid + b_mid + relu -----
    fused_gg_kernel<DH, DH><<<GB64, 256, SM2>>>(bufA, w2h, w2l, b_mid, bufB);

    // ----- layer 3: GEMM, then propagate + bias (no relu) -----
    mma_gemm_kernel<DH, false><<<dim3(1, (NNODES + 127) / 128), 512>>>(
        bufB, w3h, w3l, nullptr, bufA, NNODES, DOUTC);
    gather_kernel<DOUTC, false, true><<<(NNODES * 32 + T - 1) / T, T>>>(bufA, b_out, node);

    // ----- mean pool + classifier -----
    fill_kernel<<<8, T>>>((float4*)gsum, 0.0f, NGRAPH * DOUTC / 4);
    pool_kernel<<<(NNODES + 255) / 256, 128>>>(node, batch, gsum, NNODES);
    finish_kernel<<<NGRAPH, DOUTC>>>(batch, gsum, W_cls, b_cls, logit);
}

// round 10
// speedup vs baseline: 1.2414x; 1.2414x over previous
#include <cuda_runtime.h>
#include <cuda_bf16.h>
#include <stdint.h>

#define NNODES 40000
#define NEDGES 640000
#define NGRAPH 64
#define DIN    128
#define DH     256
#define DOUTC  128

#define SCAN_B 256
#define SCAN_NB ((NNODES + SCAN_B - 1) / SCAN_B)   // 157

// ---- scratch (no allocations allowed) ----
__device__ float g_bufA[NNODES * DH];
__device__ float g_bufB[NNODES * DH];
__device__ float g_dis[NNODES];
// CSR scratch
__device__ int   g_cnti[NNODES];
__device__ int   g_rowptr[NNODES + 1];
__device__ int   g_cursor[NNODES];
__device__ int2  g_epack[NEDGES];          // {src, coef-as-int}
__device__ int   g_bsum[SCAN_NB];
// weights transposed to [NOUT, K] row-major, bf16 hi/lo split
__device__ __nv_bfloat16 g_w1_hi[DH * DIN];
__device__ __nv_bfloat16 g_w1_lo[DH * DIN];
__device__ __nv_bfloat16 g_w2_hi[DH * DH];
__device__ __nv_bfloat16 g_w2_lo[DH * DH];
__device__ __nv_bfloat16 g_w3_hi[DOUTC * DH];
__device__ __nv_bfloat16 g_w3_lo[DOUTC * DH];

// ---------------------------------------------------------------------------
// prep: weight transpose + bf16 split + zero degree counters
// ---------------------------------------------------------------------------
__device__ __forceinline__ void wsplit(const float* __restrict__ W,
                                       __nv_bfloat16* __restrict__ hi,
                                       __nv_bfloat16* __restrict__ lo,
                                       int K, int NOUT, int idx) {
    int k = idx / NOUT, n = idx - k * NOUT;
    float v = W[idx];
    __nv_bfloat16 h = __float2bfloat16(v);
    __nv_bfloat16 l = __float2bfloat16(v - __bfloat162float(h));
    hi[(size_t)n * K + k] = h;
    lo[(size_t)n * K + k] = l;
}

__global__ void prep_kernel(const float* __restrict__ W1, const float* __restrict__ W2,
                            const float* __restrict__ W3) {
    constexpr int E1 = DIN * DH;
    constexpr int E2 = E1 + DH * DH;
    constexpr int E3 = E2 + DH * DOUTC;
    constexpr int TOT = E3 + NNODES;
    int i = blockIdx.x * blockDim.x + threadIdx.x;
    for (; i < TOT; i += gridDim.x * blockDim.x) {
        if (i < E1)       wsplit(W1, g_w1_hi, g_w1_lo, DIN, DH, i);
        else if (i < E2)  wsplit(W2, g_w2_hi, g_w2_lo, DH, DH, i - E1);
        else if (i < E3)  wsplit(W3, g_w3_hi, g_w3_lo, DH, DOUTC, i - E2);
        else              g_cnti[i - E3] = 0;
    }
}

__global__ void hist_kernel(const int* __restrict__ dst, int E) {
    int e = blockIdx.x * blockDim.x + threadIdx.x;
    if (e < E) atomicAdd(&g_cnti[dst[e]], 1);
}

// ---------------------------------------------------------------------------
// scan phase 1: block sums (+ dis + gsum zeroing piggybacked)
// ---------------------------------------------------------------------------
__global__ void scan1_kernel(float4* __restrict__ gsum4) {
    __shared__ int s[SCAN_B];
    int i = blockIdx.x * SCAN_B + threadIdx.x;
    int v = (i < NNODES) ? g_cnti[i] : 0;
    if (i < NNODES) g_dis[i] = rsqrtf((float)v + 1.0f);
    if (i < NGRAPH * DOUTC / 4) gsum4[i] = make_float4(0.f, 0.f, 0.f, 0.f);
    s[threadIdx.x] = v;
    __syncthreads();
    for (int off = SCAN_B / 2; off > 0; off >>= 1) {
        if (threadIdx.x < off) s[threadIdx.x] += s[threadIdx.x + off];
        __syncthreads();
    }
    if (threadIdx.x == 0) g_bsum[blockIdx.x] = s[0];
}

// scan phase 2+3 fused: each block computes its own prefix of block sums,
// then does the in-block exclusive scan
__global__ void scan23_kernel() {
    __shared__ int s[SCAN_B];
    __shared__ int bpre_s;
    int t = threadIdx.x;
    int i = blockIdx.x * SCAN_B + t;

    // prefix of block sums for this block
    int v = (t < SCAN_NB && t < blockIdx.x) ? g_bsum[t] : 0;
    s[t] = v;
    __syncthreads();
    for (int off = SCAN_B / 2; off > 0; off >>= 1) {
        if (t < off) s[t] += s[t + off];
        __syncthreads();
    }
    if (t == 0) bpre_s = s[0];
    __syncthreads();
    int bpre = bpre_s;
    __syncthreads();

    // in-block inclusive scan of counts
    int v0 = (i < NNODES) ? g_cnti[i] : 0;
    s[t] = v0;
    __syncthreads();
    for (int off = 1; off < SCAN_B; off <<= 1) {
        int u = (t >= off) ? s[t - off] : 0;
        __syncthreads();
        s[t] += u;
        __syncthreads();
    }
    if (i < NNODES) {
        int ex = bpre + s[t] - v0;
        g_rowptr[i] = ex;
        g_cursor[i] = ex;
    }
    if (blockIdx.x == 0 && t == 0) g_rowptr[NNODES] = NEDGES;
}

__global__ void csrfill_kernel(const int* __restrict__ src, const int* __restrict__ dst,
                               int E) {
    int e = blockIdx.x * blockDim.x + threadIdx.x;
    if (e >= E) return;
    int s = src[e], d = dst[e];
    int p = atomicAdd(&g_cursor[d], 1);
    g_epack[p] = make_int2(s, __float_as_int(g_dis[s] * g_dis[d]));
}

// ---------------------------------------------------------------------------
// mma helper
// ---------------------------------------------------------------------------
__device__ __forceinline__ void mma16816(float* c, const uint32_t* a, const uint32_t* b) {
    asm volatile(
        "mma.sync.aligned.m16n8k16.row.col.f32.bf16.bf16.f32 "
        "{%0,%1,%2,%3}, {%4,%5,%6,%7}, {%8,%9}, {%0,%1,%2,%3};"
        : "+f"(c[0]), "+f"(c[1]), "+f"(c[2]), "+f"(c[3])
        : "r"(a[0]), "r"(a[1]), "r"(a[2]), "r"(a[3]), "r"(b[0]), "r"(b[1]));
}

// ---------------------------------------------------------------------------
// 3xBF16 split GEMM, 128x128 tile, pipelined (R7/R8 proven)
// ---------------------------------------------------------------------------
template <int K, bool BRELU>
__global__ void __launch_bounds__(512)
mma_gemm_kernel(const float* __restrict__ A, const __nv_bfloat16* __restrict__ Whi,
                const __nv_bfloat16* __restrict__ Wlo, const float* __restrict__ bias,
                float* __restrict__ C, int N, int NOUT) {
    __shared__ __nv_bfloat16 AsH[128][40];
    __shared__ __nv_bfloat16 AsL[128][40];
    __shared__ __nv_bfloat16 BsH[128][40];
    __shared__ __nv_bfloat16 BsL[128][40];

    const int tid = threadIdx.x;
    const int wid = tid >> 5, lane = tid & 31;
    const int mw = (wid & 3) * 32;
    const int nw = (wid >> 2) * 32;
    const int m0 = blockIdx.y * 128;
    const int n0 = blockIdx.x * 128;

    float acc[2][4][4] = {};
    const int ar = lane >> 2;
    const int ac = (lane & 3) * 2;

    float2 va[4];
    uint4 vbh, vbl;
    const int br = tid >> 2;
    const int bc = (tid & 3) * 8;

    auto load_tile = [&](int kt) {
        #pragma unroll
        for (int it = 0; it < 4; ++it) {
            int idx = tid + it * 512;
            int r  = idx >> 4;
            int kp = (idx & 15) * 2;
            int rr = min(m0 + r, N - 1);
            va[it] = *(const float2*)(A + (size_t)rr * K + kt + kp);
        }
        vbh = *(const uint4*)(Whi + (size_t)(n0 + br) * K + kt + bc);
        vbl = *(const uint4*)(Wlo + (size_t)(n0 + br) * K + kt + bc);
    };
    auto store_tile = [&]() {
        #pragma unroll
        for (int it = 0; it < 4; ++it) {
            int idx = tid + it * 512;
            int r  = idx >> 4;
            int kp = (idx & 15) * 2;
            __nv_bfloat16 h0 = __float2bfloat16(va[it].x);
            __nv_bfloat16 h1 = __float2bfloat16(va[it].y);
            __nv_bfloat16 l0 = __float2bfloat16(va[it].x - __bfloat162float(h0));
            __nv_bfloat16 l1 = __float2bfloat16(va[it].y - __bfloat162float(h1));
            *(uint32_t*)&AsH[r][kp] = (uint32_t)__bfloat16_as_ushort(h0) |
                                      ((uint32_t)__bfloat16_as_ushort(h1) << 16);
            *(uint32_t*)&AsL[r][kp] = (uint32_t)__bfloat16_as_ushort(l0) |
                                      ((uint32_t)__bfloat16_as_ushort(l1) << 16);
        }
        *(uint4*)&BsH[br][bc] = vbh;
        *(uint4*)&BsL[br][bc] = vbl;
    };

    load_tile(0);
    store_tile();
    __syncthreads();

    for (int kt = 0; kt < K; kt += 32) {
        const bool more = (kt + 32) < K;
        if (more) load_tile(kt + 32);

        #pragma unroll
        for (int k16 = 0; k16 < 32; k16 += 16) {
            uint32_t ah[2][4], al[2][4];
            #pragma unroll
            for (int mt = 0; mt < 2; ++mt) {
                int r = mw + mt * 16 + ar;
                ah[mt][0] = *(uint32_t*)&AsH[r][k16 + ac];
                ah[mt][1] = *(uint32_t*)&AsH[r + 8][k16 + ac];
                ah[mt][2] = *(uint32_t*)&AsH[r][k16 + ac + 8];
                ah[mt][3] = *(uint32_t*)&AsH[r + 8][k16 + ac + 8];
                al[mt][0] = *(uint32_t*)&AsL[r][k16 + ac];
                al[mt][1] = *(uint32_t*)&AsL[r + 8][k16 + ac];
                al[mt][2] = *(uint32_t*)&AsL[r][k16 + ac + 8];
                al[mt][3] = *(uint32_t*)&AsL[r + 8][k16 + ac + 8];
            }
            uint32_t bh[4][2], bl[4][2];
            #pragma unroll
            for (int nt = 0; nt < 4; ++nt) {
                int r = nw + nt * 8 + ar;
                bh[nt][0] = *(uint32_t*)&BsH[r][k16 + ac];
                bh[nt][1] = *(uint32_t*)&BsH[r][k16 + ac + 8];
                bl[nt][0] = *(uint32_t*)&BsL[r][k16 + ac];
                bl[nt][1] = *(uint32_t*)&BsL[r][k16 + ac + 8];
            }
            #pragma unroll
            for (int mt = 0; mt < 2; ++mt)
                #pragma unroll
                for (int nt = 0; nt < 4; ++nt) {
                    mma16816(acc[mt][nt], ah[mt], bh[nt]);
                    mma16816(acc[mt][nt], ah[mt], bl[nt]);
                    mma16816(acc[mt][nt], al[mt], bh[nt]);
                }
        }
        if (more) {
            __syncthreads();
            store_tile();
            __syncthreads();
        }
    }

    #pragma unroll
    for (int mt = 0; mt < 2; ++mt) {
        int r0 = m0 + mw + mt * 16 + ar;
        #pragma unroll
        for (int nt = 0; nt < 4; ++nt) {
            int c = n0 + nw + nt * 8 + ac;
            float2 o0 = make_float2(acc[mt][nt][0], acc[mt][nt][1]);
            float2 o1 = make_float2(acc[mt][nt][2], acc[mt][nt][3]);
            if (BRELU) {
                float b0 = __ldg(&bias[c]), b1 = __ldg(&bias[c + 1]);
                o0.x = fmaxf(o0.x + b0, 0.f); o0.y = fmaxf(o0.y + b1, 0.f);
                o1.x = fmaxf(o1.x + b0, 0.f); o1.y = fmaxf(o1.y + b1, 0.f);
            }
            if (r0 < N)     *(float2*)(C + (size_t)r0 * NOUT + c) = o0;
            if (r0 + 8 < N) *(float2*)(C + (size_t)(r0 + 8) * NOUT + c) = o1;
        }
    }
}

// ---------------------------------------------------------------------------
// fused gather + self-loop (+bias) (+relu), packed edge records (R8 proven)
// ---------------------------------------------------------------------------
template <int H, bool RELU, bool BIAS>
__global__ void gather_kernel(const float* __restrict__ h, const float* __restrict__ bias,
                              float* __restrict__ out) {
    constexpr int HALVES = H / 128;
    int w = (blockIdx.x * blockDim.x + threadIdx.x) >> 5;
    int n = w / HALVES;
    if (n >= NNODES) return;
    int half = w - n * HALVES;
    int lane = threadIdx.x & 31;
    int col  = half * 128 + lane * 4;

    int p  = __ldg(&g_rowptr[n]);
    int p1 = __ldg(&g_rowptr[n + 1]);

    float4 acc = make_float4(0.f, 0.f, 0.f, 0.f);
    for (; p + 3 < p1; p += 4) {
        int2 e0 = __ldg(&g_epack[p]);
        int2 e1 = __ldg(&g_epack[p + 1]);
        int2 e2 = __ldg(&g_epack[p + 2]);
        int2 e3 = __ldg(&g_epack[p + 3]);
        float c0 = __int_as_float(e0.y), c1 = __int_as_float(e1.y);
        float c2 = __int_as_float(e2.y), c3 = __int_as_float(e3.y);
        float4 v0 = __ldg((const float4*)(h + (size_t)e0.x * H + col));
        float4 v1 = __ldg((const float4*)(h + (size_t)e1.x * H + col));
        float4 v2 = __ldg((const float4*)(h + (size_t)e2.x * H + col));
        float4 v3 = __ldg((const float4*)(h + (size_t)e3.x * H + col));
        acc.x += c0 * v0.x + c1 * v1.x + c2 * v2.x + c3 * v3.x;
        acc.y += c0 * v0.y + c1 * v1.y + c2 * v2.y + c3 * v3.y;
        acc.z += c0 * v0.z + c1 * v1.z + c2 * v2.z + c3 * v3.z;
        acc.w += c0 * v0.w + c1 * v1.w + c2 * v2.w + c3 * v3.w;
    }
    for (; p < p1; ++p) {
        int2 e = __ldg(&g_epack[p]);
        float c = __int_as_float(e.y);
        float4 v = __ldg((const float4*)(h + (size_t)e.x * H + col));
        acc.x += c * v.x; acc.y += c * v.y; acc.z += c * v.z; acc.w += c * v.w;
    }

    float dis = g_dis[n];
    float c2 = dis * dis;
    float4 hv = __ldg((const float4*)(h + (size_t)n * H + col));
    float4 r;
    r.x = acc.x + c2 * hv.x;
    r.y = acc.y + c2 * hv.y;
    r.z = acc.z + c2 * hv.z;
    r.w = acc.w + c2 * hv.w;
    if (BIAS) {
        float4 bv = __ldg((const float4*)(bias + col));
        r.x += bv.x; r.y += bv.y; r.z += bv.z; r.w += bv.w;
    }
    if (RELU) {
        r.x = fmaxf(r.x, 0.f); r.y = fmaxf(r.y, 0.f);
        r.z = fmaxf(r.z, 0.f); r.w = fmaxf(r.w, 0.f);
    }
    *(float4*)(out + (size_t)n * H + col) = r;
}

// ---------------------------------------------------------------------------
// pooling + fused finish
// ---------------------------------------------------------------------------
__global__ void pool_kernel(const float* __restrict__ ne, const int* __restrict__ batch,
                            float* __restrict__ gsum, int N) {
    int c  = threadIdx.x;
    int n0 = blockIdx.x * 256;
    int n1 = min(n0 + 256, N);
    float acc = 0.0f;
    int cur = -1;
    for (int n = n0; n < n1; ++n) {
        int g = __ldg(&batch[n]);
        if (g != cur) {
            if (cur >= 0) atomicAdd(&gsum[cur * DOUTC + c], acc);
            acc = 0.0f;
            cur = g;
        }
        acc += ne[(size_t)n * DOUTC + c];
    }
    if (cur >= 0) atomicAdd(&gsum[cur * DOUTC + c], acc);
}

__global__ void finish_kernel(const int* __restrict__ batch, float* __restrict__ gsum,
                              const float* __restrict__ Wc, const float* __restrict__ bc,
                              float* __restrict__ logit) {
    int g = blockIdx.x;
    __shared__ float cnt_s;
    __shared__ float row[DOUTC];
    if (threadIdx.x == 0) {
        int lo = 0, hi = NNODES;
        while (lo < hi) { int mid = (lo + hi) >> 1; if (__ldg(&batch[mid]) < g) lo = mid + 1; else hi = mid; }
        int lb = lo;
        lo = 0; hi = NNODES;
        while (lo < hi) { int mid = (lo + hi) >> 1; if (__ldg(&batch[mid]) <= g) lo = mid + 1; else hi = mid; }
        cnt_s = fmaxf((float)(lo - lb), 1.0f);
    }
    __syncthreads();
    int c = threadIdx.x;
    float v = gsum[g * DOUTC + c] / cnt_s;
    gsum[g * DOUTC + c] = v;
    row[c] = v;
    __syncthreads();
    if (c < 2) {
        float s = __ldg(&bc[c]);
        #pragma unroll 8
        for (int k = 0; k < DOUTC; ++k) s += row[k] * __ldg(&Wc[k * 2 + c]);
        logit[g * 2 + c] = s;
    }
}

// ---------------------------------------------------------------------------
// launch
// ---------------------------------------------------------------------------
extern "C" void kernel_launch(void* const* d_in, const int* in_sizes, int n_in,
                              void* d_out, int out_size) {
    const float* x     = (const float*)d_in[0];
    const int*   ei    = (const int*)d_in[1];
    const int*   batch = (const int*)d_in[2];
    const float* W_in  = (const float*)d_in[3];
    const float* b_in  = (const float*)d_in[4];
    const float* W_mid = (const float*)d_in[5];
    const float* b_mid = (const float*)d_in[6];
    const float* W_out = (const float*)d_in[7];
    const float* b_out = (const float*)d_in[8];
    const float* W_cls = (const float*)d_in[9];
    const float* b_cls = (const float*)d_in[10];

    const int* src = ei;
    const int* dst = ei + NEDGES;

    float *bufA, *bufB;
    __nv_bfloat16 *w1h, *w1l, *w2h, *w2l, *w3h, *w3l;
    cudaGetSymbolAddress((void**)&bufA, g_bufA);
    cudaGetSymbolAddress((void**)&bufB, g_bufB);
    cudaGetSymbolAddress((void**)&w1h, g_w1_hi);
    cudaGetSymbolAddress((void**)&w1l, g_w1_lo);
    cudaGetSymbolAddress((void**)&w2h, g_w2_hi);
    cudaGetSymbolAddress((void**)&w2l, g_w2_lo);
    cudaGetSymbolAddress((void**)&w3h, g_w3_hi);
    cudaGetSymbolAddress((void**)&w3l, g_w3_lo);

    float* node   = (float*)d_out;
    float* gsum   = node + (size_t)NNODES * DOUTC;
    float* logit  = gsum + NGRAPH * DOUTC;

    const int T = 256;

    // ----- prep (weights + zero counters) and CSR build -----
    prep_kernel<<<680, T>>>(W_in, W_mid, W_out);
    hist_kernel<<<(NEDGES + T - 1) / T, T>>>(dst, NEDGES);
    scan1_kernel<<<SCAN_NB, SCAN_B>>>((float4*)gsum);
    scan23_kernel<<<SCAN_NB, SCAN_B>>>();
    csrfill_kernel<<<(NEDGES + T - 1) / T, T>>>(src, dst, NEDGES);

    const int GB = (NNODES + 127) / 128;   // 313

    // ----- layer 1: propagate(x) [128-wide], then GEMM + bias + relu -----
    gather_kernel<DIN, false, false><<<(NNODES * 32 + T - 1) / T, T>>>(x, nullptr, bufA);
    mma_gemm_kernel<DIN, true><<<dim3(2, GB), 512>>>(bufA, w1h, w1l, b_in, bufB,
                                                     NNODES, DH);

    // ----- layer 2: GEMM, then propagate + bias + relu -----
    mma_gemm_kernel<DH, false><<<dim3(2, GB), 512>>>(bufB, w2h, w2l, nullptr, bufA,
                                                     NNODES, DH);
    gather_kernel<DH, true, true><<<(NNODES * 2 * 32 + T - 1) / T, T>>>(bufA, b_mid, bufB);

    // ----- layer 3: GEMM, then propagate + bias (no relu) -----
    mma_gemm_kernel<DH, false><<<dim3(1, GB), 512>>>(bufB, w3h, w3l, nullptr, bufA,
                                                     NNODES, DOUTC);
    gather_kernel<DOUTC, false, true><<<(NNODES * 32 + T - 1) / T, T>>>(bufA, b_out, node);

    // ----- mean pool + classifier -----
    pool_kernel<<<(NNODES + 255) / 256, 128>>>(node, batch, gsum, NNODES);
    finish_kernel<<<NGRAPH, DOUTC>>>(batch, gsum, W_cls, b_cls, logit);
}

// round 11
// speedup vs baseline: 1.2873x; 1.0370x over previous
#include <cuda_runtime.h>
#include <cuda_bf16.h>
#include <cuda_fp16.h>
#include <stdint.h>

#define NNODES 40000
#define NEDGES 640000
#define NGRAPH 64
#define DIN    128
#define DH     256
#define DOUTC  128

#define SCAN_B 256
#define SCAN_NB ((NNODES + SCAN_B - 1) / SCAN_B)   // 157

// ---- scratch (no allocations allowed) ----
__device__ float g_bufA[NNODES * DH];
__device__ float g_bufB[NNODES * DH];
__device__ float g_dis[NNODES];
// CSR scratch
__device__ int   g_cnti[NNODES];
__device__ int   g_rowptr[NNODES + 1];
__device__ int   g_cursor[NNODES];
__device__ int2  g_epack[NEDGES];          // {src, coef-as-int}
__device__ int   g_bsum[SCAN_NB];
// weights transposed to [NOUT, K] row-major, bf16 hi/lo split
__device__ __nv_bfloat16 g_w1_hi[DH * DIN];
__device__ __nv_bfloat16 g_w1_lo[DH * DIN];
__device__ __nv_bfloat16 g_w2_hi[DH * DH];
__device__ __nv_bfloat16 g_w2_lo[DH * DH];
__device__ __nv_bfloat16 g_w3_hi[DOUTC * DH];
__device__ __nv_bfloat16 g_w3_lo[DOUTC * DH];

// ---------------------------------------------------------------------------
// prep: weight transpose + bf16 split + zero degree counters
// ---------------------------------------------------------------------------
__device__ __forceinline__ void wsplit(const float* __restrict__ W,
                                       __nv_bfloat16* __restrict__ hi,
                                       __nv_bfloat16* __restrict__ lo,
                                       int K, int NOUT, int idx) {
    int k = idx / NOUT, n = idx - k * NOUT;
    float v = W[idx];
    __nv_bfloat16 h = __float2bfloat16(v);
    __nv_bfloat16 l = __float2bfloat16(v - __bfloat162float(h));
    hi[(size_t)n * K + k] = h;
    lo[(size_t)n * K + k] = l;
}

__global__ void prep_kernel(const float* __restrict__ W1, const float* __restrict__ W2,
                            const float* __restrict__ W3) {
    constexpr int E1 = DIN * DH;
    constexpr int E2 = E1 + DH * DH;
    constexpr int E3 = E2 + DH * DOUTC;
    constexpr int TOT = E3 + NNODES;
    int i = blockIdx.x * blockDim.x + threadIdx.x;
    for (; i < TOT; i += gridDim.x * blockDim.x) {
        if (i < E1)       wsplit(W1, g_w1_hi, g_w1_lo, DIN, DH, i);
        else if (i < E2)  wsplit(W2, g_w2_hi, g_w2_lo, DH, DH, i - E1);
        else if (i < E3)  wsplit(W3, g_w3_hi, g_w3_lo, DH, DOUTC, i - E2);
        else              g_cnti[i - E3] = 0;
    }
}

__global__ void hist_kernel(const int* __restrict__ dst, int E) {
    int e = blockIdx.x * blockDim.x + threadIdx.x;
    if (e < E) atomicAdd(&g_cnti[dst[e]], 1);
}

// ---------------------------------------------------------------------------
// scan phase 1: block sums (+ dis + gsum zeroing piggybacked)
// ---------------------------------------------------------------------------
__global__ void scan1_kernel(float4* __restrict__ gsum4) {
    __shared__ int s[SCAN_B];
    int i = blockIdx.x * SCAN_B + threadIdx.x;
    int v = (i < NNODES) ? g_cnti[i] : 0;
    if (i < NNODES) g_dis[i] = rsqrtf((float)v + 1.0f);
    if (i < NGRAPH * DOUTC / 4) gsum4[i] = make_float4(0.f, 0.f, 0.f, 0.f);
    s[threadIdx.x] = v;
    __syncthreads();
    for (int off = SCAN_B / 2; off > 0; off >>= 1) {
        if (threadIdx.x < off) s[threadIdx.x] += s[threadIdx.x + off];
        __syncthreads();
    }
    if (threadIdx.x == 0) g_bsum[blockIdx.x] = s[0];
}

// scan phase 2+3 fused
__global__ void scan23_kernel() {
    __shared__ int s[SCAN_B];
    __shared__ int bpre_s;
    int t = threadIdx.x;
    int i = blockIdx.x * SCAN_B + t;

    int v = (t < SCAN_NB && t < blockIdx.x) ? g_bsum[t] : 0;
    s[t] = v;
    __syncthreads();
    for (int off = SCAN_B / 2; off > 0; off >>= 1) {
        if (t < off) s[t] += s[t + off];
        __syncthreads();
    }
    if (t == 0) bpre_s = s[0];
    __syncthreads();
    int bpre = bpre_s;
    __syncthreads();

    int v0 = (i < NNODES) ? g_cnti[i] : 0;
    s[t] = v0;
    __syncthreads();
    for (int off = 1; off < SCAN_B; off <<= 1) {
        int u = (t >= off) ? s[t - off] : 0;
        __syncthreads();
        s[t] += u;
        __syncthreads();
    }
    if (i < NNODES) {
        int ex = bpre + s[t] - v0;
        g_rowptr[i] = ex;
        g_cursor[i] = ex;
    }
    if (blockIdx.x == 0 && t == 0) g_rowptr[NNODES] = NEDGES;
}

__global__ void csrfill_kernel(const int* __restrict__ src, const int* __restrict__ dst,
                               int E) {
    int e = blockIdx.x * blockDim.x + threadIdx.x;
    if (e >= E) return;
    int s = src[e], d = dst[e];
    int p = atomicAdd(&g_cursor[d], 1);
    g_epack[p] = make_int2(s, __float_as_int(g_dis[s] * g_dis[d]));
}

// ---------------------------------------------------------------------------
// mma helper
// ---------------------------------------------------------------------------
__device__ __forceinline__ void mma16816(float* c, const uint32_t* a, const uint32_t* b) {
    asm volatile(
        "mma.sync.aligned.m16n8k16.row.col.f32.bf16.bf16.f32 "
        "{%0,%1,%2,%3}, {%4,%5,%6,%7}, {%8,%9}, {%0,%1,%2,%3};"
        : "+f"(c[0]), "+f"(c[1]), "+f"(c[2]), "+f"(c[3])
        : "r"(a[0]), "r"(a[1]), "r"(a[2]), "r"(a[3]), "r"(b[0]), "r"(b[1]));
}

// ---------------------------------------------------------------------------
// 3xBF16 split GEMM, 128x128 tile, pipelined; optional fp16 output store
// ---------------------------------------------------------------------------
template <int K, bool BRELU, bool HALF_OUT>
__global__ void __launch_bounds__(512)
mma_gemm_kernel(const float* __restrict__ A, const __nv_bfloat16* __restrict__ Whi,
                const __nv_bfloat16* __restrict__ Wlo, const float* __restrict__ bias,
                float* __restrict__ C, int N, int NOUT) {
    __shared__ __nv_bfloat16 AsH[128][40];
    __shared__ __nv_bfloat16 AsL[128][40];
    __shared__ __nv_bfloat16 BsH[128][40];
    __shared__ __nv_bfloat16 BsL[128][40];

    const int tid = threadIdx.x;
    const int wid = tid >> 5, lane = tid & 31;
    const int mw = (wid & 3) * 32;
    const int nw = (wid >> 2) * 32;
    const int m0 = blockIdx.y * 128;
    const int n0 = blockIdx.x * 128;

    float acc[2][4][4] = {};
    const int ar = lane >> 2;
    const int ac = (lane & 3) * 2;

    float2 va[4];
    uint4 vbh, vbl;
    const int br = tid >> 2;
    const int bc = (tid & 3) * 8;

    auto load_tile = [&](int kt) {
        #pragma unroll
        for (int it = 0; it < 4; ++it) {
            int idx = tid + it * 512;
            int r  = idx >> 4;
            int kp = (idx & 15) * 2;
            int rr = min(m0 + r, N - 1);
            va[it] = *(const float2*)(A + (size_t)rr * K + kt + kp);
        }
        vbh = *(const uint4*)(Whi + (size_t)(n0 + br) * K + kt + bc);
        vbl = *(const uint4*)(Wlo + (size_t)(n0 + br) * K + kt + bc);
    };
    auto store_tile = [&]() {
        #pragma unroll
        for (int it = 0; it < 4; ++it) {
            int idx = tid + it * 512;
            int r  = idx >> 4;
            int kp = (idx & 15) * 2;
            __nv_bfloat16 h0 = __float2bfloat16(va[it].x);
            __nv_bfloat16 h1 = __float2bfloat16(va[it].y);
            __nv_bfloat16 l0 = __float2bfloat16(va[it].x - __bfloat162float(h0));
            __nv_bfloat16 l1 = __float2bfloat16(va[it].y - __bfloat162float(h1));
            *(uint32_t*)&AsH[r][kp] = (uint32_t)__bfloat16_as_ushort(h0) |
                                      ((uint32_t)__bfloat16_as_ushort(h1) << 16);
            *(uint32_t*)&AsL[r][kp] = (uint32_t)__bfloat16_as_ushort(l0) |
                                      ((uint32_t)__bfloat16_as_ushort(l1) << 16);
        }
        *(uint4*)&BsH[br][bc] = vbh;
        *(uint4*)&BsL[br][bc] = vbl;
    };

    load_tile(0);
    store_tile();
    __syncthreads();

    for (int kt = 0; kt < K; kt += 32) {
        const bool more = (kt + 32) < K;
        if (more) load_tile(kt + 32);

        #pragma unroll
        for (int k16 = 0; k16 < 32; k16 += 16) {
            uint32_t ah[2][4], al[2][4];
            #pragma unroll
            for (int mt = 0; mt < 2; ++mt) {
                int r = mw + mt * 16 + ar;
                ah[mt][0] = *(uint32_t*)&AsH[r][k16 + ac];
                ah[mt][1] = *(uint32_t*)&AsH[r + 8][k16 + ac];
                ah[mt][2] = *(uint32_t*)&AsH[r][k16 + ac + 8];
                ah[mt][3] = *(uint32_t*)&AsH[r + 8][k16 + ac + 8];
                al[mt][0] = *(uint32_t*)&AsL[r][k16 + ac];
                al[mt][1] = *(uint32_t*)&AsL[r + 8][k16 + ac];
                al[mt][2] = *(uint32_t*)&AsL[r][k16 + ac + 8];
                al[mt][3] = *(uint32_t*)&AsL[r + 8][k16 + ac + 8];
            }
            uint32_t bh[4][2], bl[4][2];
            #pragma unroll
            for (int nt = 0; nt < 4; ++nt) {
                int r = nw + nt * 8 + ar;
                bh[nt][0] = *(uint32_t*)&BsH[r][k16 + ac];
                bh[nt][1] = *(uint32_t*)&BsH[r][k16 + ac + 8];
                bl[nt][0] = *(uint32_t*)&BsL[r][k16 + ac];
                bl[nt][1] = *(uint32_t*)&BsL[r][k16 + ac + 8];
            }
            #pragma unroll
            for (int mt = 0; mt < 2; ++mt)
                #pragma unroll
                for (int nt = 0; nt < 4; ++nt) {
                    mma16816(acc[mt][nt], ah[mt], bh[nt]);
                    mma16816(acc[mt][nt], ah[mt], bl[nt]);
                    mma16816(acc[mt][nt], al[mt], bh[nt]);
                }
        }
        if (more) {
            __syncthreads();
            store_tile();
            __syncthreads();
        }
    }

    #pragma unroll
    for (int mt = 0; mt < 2; ++mt) {
        int r0 = m0 + mw + mt * 16 + ar;
        #pragma unroll
        for (int nt = 0; nt < 4; ++nt) {
            int c = n0 + nw + nt * 8 + ac;
            float2 o0 = make_float2(acc[mt][nt][0], acc[mt][nt][1]);
            float2 o1 = make_float2(acc[mt][nt][2], acc[mt][nt][3]);
            if (BRELU) {
                float b0 = __ldg(&bias[c]), b1 = __ldg(&bias[c + 1]);
                o0.x = fmaxf(o0.x + b0, 0.f); o0.y = fmaxf(o0.y + b1, 0.f);
                o1.x = fmaxf(o1.x + b0, 0.f); o1.y = fmaxf(o1.y + b1, 0.f);
            }
            if (HALF_OUT) {
                __half* Ch = (__half*)C;
                if (r0 < N)
                    *(__half2*)(Ch + (size_t)r0 * NOUT + c) = __floats2half2_rn(o0.x, o0.y);
                if (r0 + 8 < N)
                    *(__half2*)(Ch + (size_t)(r0 + 8) * NOUT + c) = __floats2half2_rn(o1.x, o1.y);
            } else {
                if (r0 < N)     *(float2*)(C + (size_t)r0 * NOUT + c) = o0;
                if (r0 + 8 < N) *(float2*)(C + (size_t)(r0 + 8) * NOUT + c) = o1;
            }
        }
    }
}

// ---------------------------------------------------------------------------
// fused gather + self-loop (+bias) (+relu); optional fp16 input
// ---------------------------------------------------------------------------
template <int H, bool RELU, bool BIAS, bool HALF_IN>
__global__ void gather_kernel(const void* __restrict__ hv_in, const float* __restrict__ bias,
                              float* __restrict__ out) {
    constexpr int HALVES = H / 128;
    int w = (blockIdx.x * blockDim.x + threadIdx.x) >> 5;
    int n = w / HALVES;
    if (n >= NNODES) return;
    int half = w - n * HALVES;
    int lane = threadIdx.x & 31;
    int col  = half * 128 + lane * 4;

    auto loadrow = [&](int s) -> float4 {
        if (HALF_IN) {
            const __half* hp = (const __half*)hv_in + (size_t)s * H + col;
            uint2 raw = __ldg((const uint2*)hp);
            __half2 p0 = *reinterpret_cast<__half2*>(&raw.x);
            __half2 p1 = *reinterpret_cast<__half2*>(&raw.y);
            float2 f0 = __half22float2(p0), f1 = __half22float2(p1);
            return make_float4(f0.x, f0.y, f1.x, f1.y);
        } else {
            return __ldg((const float4*)((const float*)hv_in + (size_t)s * H + col));
        }
    };

    int p  = __ldg(&g_rowptr[n]);
    int p1 = __ldg(&g_rowptr[n + 1]);

    float4 acc = make_float4(0.f, 0.f, 0.f, 0.f);
    for (; p + 3 < p1; p += 4) {
        int2 e0 = __ldg(&g_epack[p]);
        int2 e1 = __ldg(&g_epack[p + 1]);
        int2 e2 = __ldg(&g_epack[p + 2]);
        int2 e3 = __ldg(&g_epack[p + 3]);
        float c0 = __int_as_float(e0.y), c1 = __int_as_float(e1.y);
        float c2 = __int_as_float(e2.y), c3 = __int_as_float(e3.y);
        float4 v0 = loadrow(e0.x);
        float4 v1 = loadrow(e1.x);
        float4 v2 = loadrow(e2.x);
        float4 v3 = loadrow(e3.x);
        acc.x += c0 * v0.x + c1 * v1.x + c2 * v2.x + c3 * v3.x;
        acc.y += c0 * v0.y + c1 * v1.y + c2 * v2.y + c3 * v3.y;
        acc.z += c0 * v0.z + c1 * v1.z + c2 * v2.z + c3 * v3.z;
        acc.w += c0 * v0.w + c1 * v1.w + c2 * v2.w + c3 * v3.w;
    }
    for (; p < p1; ++p) {
        int2 e = __ldg(&g_epack[p]);
        float c = __int_as_float(e.y);
        float4 v = loadrow(e.x);
        acc.x += c * v.x; acc.y += c * v.y; acc.z += c * v.z; acc.w += c * v.w;
    }

    float dis = g_dis[n];
    float c2 = dis * dis;
    float4 hv = loadrow(n);
    float4 r;
    r.x = acc.x + c2 * hv.x;
    r.y = acc.y + c2 * hv.y;
    r.z = acc.z + c2 * hv.z;
    r.w = acc.w + c2 * hv.w;
    if (BIAS) {
        float4 bv = __ldg((const float4*)(bias + col));
        r.x += bv.x; r.y += bv.y; r.z += bv.z; r.w += bv.w;
    }
    if (RELU) {
        r.x = fmaxf(r.x, 0.f); r.y = fmaxf(r.y, 0.f);
        r.z = fmaxf(r.z, 0.f); r.w = fmaxf(r.w, 0.f);
    }
    *(float4*)(out + (size_t)n * H + col) = r;
}

// ---------------------------------------------------------------------------
// pooling + fused finish
// ---------------------------------------------------------------------------
__global__ void pool_kernel(const float* __restrict__ ne, const int* __restrict__ batch,
                            float* __restrict__ gsum, int N) {
    int c  = threadIdx.x;
    int n0 = blockIdx.x * 256;
    int n1 = min(n0 + 256, N);
    float acc = 0.0f;
    int cur = -1;
    for (int n = n0; n < n1; ++n) {
        int g = __ldg(&batch[n]);
        if (g != cur) {
            if (cur >= 0) atomicAdd(&gsum[cur * DOUTC + c], acc);
            acc = 0.0f;
            cur = g;
        }
        acc += ne[(size_t)n * DOUTC + c];
    }
    if (cur >= 0) atomicAdd(&gsum[cur * DOUTC + c], acc);
}

__global__ void finish_kernel(const int* __restrict__ batch, float* __restrict__ gsum,
                              const float* __restrict__ Wc, const float* __restrict__ bc,
                              float* __restrict__ logit) {
    int g = blockIdx.x;
    __shared__ float cnt_s;
    __shared__ float row[DOUTC];
    if (threadIdx.x == 0) {
        int lo = 0, hi = NNODES;
        while (lo < hi) { int mid = (lo + hi) >> 1; if (__ldg(&batch[mid]) < g) lo = mid + 1; else hi = mid; }
        int lb = lo;
        lo = 0; hi = NNODES;
        while (lo < hi) { int mid = (lo + hi) >> 1; if (__ldg(&batch[mid]) <= g) lo = mid + 1; else hi = mid; }
        cnt_s = fmaxf((float)(lo - lb), 1.0f);
    }
    __syncthreads();
    int c = threadIdx.x;
    float v = gsum[g * DOUTC + c] / cnt_s;
    gsum[g * DOUTC + c] = v;
    row[c] = v;
    __syncthreads();
    if (c < 2) {
        float s = __ldg(&bc[c]);
        #pragma unroll 8
        for (int k = 0; k < DOUTC; ++k) s += row[k] * __ldg(&Wc[k * 2 + c]);
        logit[g * 2 + c] = s;
    }
}

// ---------------------------------------------------------------------------
// launch
// ---------------------------------------------------------------------------
extern "C" void kernel_launch(void* const* d_in, const int* in_sizes, int n_in,
                              void* d_out, int out_size) {
    const float* x     = (const float*)d_in[0];
    const int*   ei    = (const int*)d_in[1];
    const int*   batch = (const int*)d_in[2];
    const float* W_in  = (const float*)d_in[3];
    const float* b_in  = (const float*)d_in[4];
    const float* W_mid = (const float*)d_in[5];
    const float* b_mid = (const float*)d_in[6];
    const float* W_out = (const float*)d_in[7];
    const float* b_out = (const float*)d_in[8];
    const float* W_cls = (const float*)d_in[9];
    const float* b_cls = (const float*)d_in[10];

    const int* src = ei;
    const int* dst = ei + NEDGES;

    float *bufA, *bufB;
    __nv_bfloat16 *w1h, *w1l, *w2h, *w2l, *w3h, *w3l;
    cudaGetSymbolAddress((void**)&bufA, g_bufA);
    cudaGetSymbolAddress((void**)&bufB, g_bufB);
    cudaGetSymbolAddress((void**)&w1h, g_w1_hi);
    cudaGetSymbolAddress((void**)&w1l, g_w1_lo);
    cudaGetSymbolAddress((void**)&w2h, g_w2_hi);
    cudaGetSymbolAddress((void**)&w2l, g_w2_lo);
    cudaGetSymbolAddress((void**)&w3h, g_w3_hi);
    cudaGetSymbolAddress((void**)&w3l, g_w3_lo);

    float* node   = (float*)d_out;
    float* gsum   = node + (size_t)NNODES * DOUTC;
    float* logit  = gsum + NGRAPH * DOUTC;

    const int T = 256;

    // ----- prep (weights + zero counters) and CSR build -----
    prep_kernel<<<680, T>>>(W_in, W_mid, W_out);
    hist_kernel<<<(NEDGES + T - 1) / T, T>>>(dst, NEDGES);
    scan1_kernel<<<SCAN_NB, SCAN_B>>>((float4*)gsum);
    scan23_kernel<<<SCAN_NB, SCAN_B>>>();
    csrfill_kernel<<<(NEDGES + T - 1) / T, T>>>(src, dst, NEDGES);

    const int GB = (NNODES + 127) / 128;   // 313

    // ----- layer 1: propagate(x) [128-wide], then GEMM + bias + relu -----
    gather_kernel<DIN, false, false, false><<<(NNODES * 32 + T - 1) / T, T>>>(x, nullptr, bufA);
    mma_gemm_kernel<DIN, true, false><<<dim3(2, GB), 512>>>(bufA, w1h, w1l, b_in, bufB,
                                                            NNODES, DH);

    // ----- layer 2: GEMM (fp16 out), then propagate(fp16 in) + bias + relu -----
    mma_gemm_kernel<DH, false, true><<<dim3(2, GB), 512>>>(bufB, w2h, w2l, nullptr, bufA,
                                                           NNODES, DH);
    gather_kernel<DH, true, true, true><<<(NNODES * 2 * 32 + T - 1) / T, T>>>(bufA, b_mid, bufB);

    // ----- layer 3: GEMM, then propagate + bias (no relu) -----
    mma_gemm_kernel<DH, false, false><<<dim3(1, GB), 512>>>(bufB, w3h, w3l, nullptr, bufA,
                                                            NNODES, DOUTC);
    gather_kernel<DOUTC, false, true, false><<<(NNODES * 32 + T - 1) / T, T>>>(bufA, b_out, node);

    // ----- mean pool + classifier -----
    pool_kernel<<<(NNODES + 255) / 256, 128>>>(node, batch, gsum, NNODES);
    finish_kernel<<<NGRAPH, DOUTC>>>(batch, gsum, W_cls, b_cls, logit);
}

// round 12
// speedup vs baseline: 1.3301x; 1.0332x over previous
#include <cuda_runtime.h>
#include <cuda_bf16.h>
#include <cuda_fp16.h>
#include <stdint.h>

#define NNODES 40000
#define NEDGES 640000
#define NGRAPH 64
#define DIN    128
#define DH     256
#define DOUTC  128

#define SCAN_B 256
#define SCAN_NB ((NNODES + SCAN_B - 1) / SCAN_B)   // 157

// ---- scratch (no allocations allowed) ----
__device__ float g_bufA[NNODES * DH];
__device__ float g_bufB[NNODES * DH];
__device__ float g_dis[NNODES];
// CSR scratch
__device__ int   g_cnti[NNODES];
__device__ int   g_rowptr[NNODES + 1];
__device__ int   g_cursor[NNODES];
__device__ int2  g_epack[NEDGES];          // {src, coef-as-int}
__device__ int   g_bsum[SCAN_NB];
// weights transposed to [NOUT, K] row-major, bf16 hi/lo split
__device__ __nv_bfloat16 g_w1_hi[DH * DIN];
__device__ __nv_bfloat16 g_w1_lo[DH * DIN];
__device__ __nv_bfloat16 g_w2_hi[DH * DH];
__device__ __nv_bfloat16 g_w2_lo[DH * DH];
__device__ __nv_bfloat16 g_w3_hi[DOUTC * DH];
__device__ __nv_bfloat16 g_w3_lo[DOUTC * DH];

// ---------------------------------------------------------------------------
// prep: weight transpose + bf16 split + zero degree counters
// ---------------------------------------------------------------------------
__device__ __forceinline__ void wsplit(const float* __restrict__ W,
                                       __nv_bfloat16* __restrict__ hi,
                                       __nv_bfloat16* __restrict__ lo,
                                       int K, int NOUT, int idx) {
    int k = idx / NOUT, n = idx - k * NOUT;
    float v = W[idx];
    __nv_bfloat16 h = __float2bfloat16(v);
    __nv_bfloat16 l = __float2bfloat16(v - __bfloat162float(h));
    hi[(size_t)n * K + k] = h;
    lo[(size_t)n * K + k] = l;
}

__global__ void prep_kernel(const float* __restrict__ W1, const float* __restrict__ W2,
                            const float* __restrict__ W3) {
    constexpr int E1 = DIN * DH;
    constexpr int E2 = E1 + DH * DH;
    constexpr int E3 = E2 + DH * DOUTC;
    constexpr int TOT = E3 + NNODES;
    int i = blockIdx.x * blockDim.x + threadIdx.x;
    for (; i < TOT; i += gridDim.x * blockDim.x) {
        if (i < E1)       wsplit(W1, g_w1_hi, g_w1_lo, DIN, DH, i);
        else if (i < E2)  wsplit(W2, g_w2_hi, g_w2_lo, DH, DH, i - E1);
        else if (i < E3)  wsplit(W3, g_w3_hi, g_w3_lo, DH, DOUTC, i - E2);
        else              g_cnti[i - E3] = 0;
    }
}

// convert fp32 -> fp16, vectorized (float4 -> 2x half2)
__global__ void tohalf_kernel(const float4* __restrict__ in, uint2* __restrict__ out, int n4) {
    int i = blockIdx.x * blockDim.x + threadIdx.x;
    for (; i < n4; i += gridDim.x * blockDim.x) {
        float4 v = in[i];
        __half2 p0 = __floats2half2_rn(v.x, v.y);
        __half2 p1 = __floats2half2_rn(v.z, v.w);
        uint2 o;
        o.x = *reinterpret_cast<uint32_t*>(&p0);
        o.y = *reinterpret_cast<uint32_t*>(&p1);
        out[i] = o;
    }
}

__global__ void hist_kernel(const int* __restrict__ dst, int E) {
    int e = blockIdx.x * blockDim.x + threadIdx.x;
    if (e < E) atomicAdd(&g_cnti[dst[e]], 1);
}

// ---------------------------------------------------------------------------
// scan phase 1: block sums (+ dis + gsum zeroing piggybacked)
// ---------------------------------------------------------------------------
__global__ void scan1_kernel(float4* __restrict__ gsum4) {
    __shared__ int s[SCAN_B];
    int i = blockIdx.x * SCAN_B + threadIdx.x;
    int v = (i < NNODES) ? g_cnti[i] : 0;
    if (i < NNODES) g_dis[i] = rsqrtf((float)v + 1.0f);
    if (i < NGRAPH * DOUTC / 4) gsum4[i] = make_float4(0.f, 0.f, 0.f, 0.f);
    s[threadIdx.x] = v;
    __syncthreads();
    for (int off = SCAN_B / 2; off > 0; off >>= 1) {
        if (threadIdx.x < off) s[threadIdx.x] += s[threadIdx.x + off];
        __syncthreads();
    }
    if (threadIdx.x == 0) g_bsum[blockIdx.x] = s[0];
}

// scan phase 2+3 fused
__global__ void scan23_kernel() {
    __shared__ int s[SCAN_B];
    __shared__ int bpre_s;
    int t = threadIdx.x;
    int i = blockIdx.x * SCAN_B + t;

    int v = (t < SCAN_NB && t < blockIdx.x) ? g_bsum[t] : 0;
    s[t] = v;
    __syncthreads();
    for (int off = SCAN_B / 2; off > 0; off >>= 1) {
        if (t < off) s[t] += s[t + off];
        __syncthreads();
    }
    if (t == 0) bpre_s = s[0];
    __syncthreads();
    int bpre = bpre_s;
    __syncthreads();

    int v0 = (i < NNODES) ? g_cnti[i] : 0;
    s[t] = v0;
    __syncthreads();
    for (int off = 1; off < SCAN_B; off <<= 1) {
        int u = (t >= off) ? s[t - off] : 0;
        __syncthreads();
        s[t] += u;
        __syncthreads();
    }
    if (i < NNODES) {
        int ex = bpre + s[t] - v0;
        g_rowptr[i] = ex;
        g_cursor[i] = ex;
    }
    if (blockIdx.x == 0 && t == 0) g_rowptr[NNODES] = NEDGES;
}

__global__ void csrfill_kernel(const int* __restrict__ src, const int* __restrict__ dst,
                               int E) {
    int e = blockIdx.x * blockDim.x + threadIdx.x;
    if (e >= E) return;
    int s = src[e], d = dst[e];
    int p = atomicAdd(&g_cursor[d], 1);
    g_epack[p] = make_int2(s, __float_as_int(g_dis[s] * g_dis[d]));
}

// ---------------------------------------------------------------------------
// mma helper
// ---------------------------------------------------------------------------
__device__ __forceinline__ void mma16816(float* c, const uint32_t* a, const uint32_t* b) {
    asm volatile(
        "mma.sync.aligned.m16n8k16.row.col.f32.bf16.bf16.f32 "
        "{%0,%1,%2,%3}, {%4,%5,%6,%7}, {%8,%9}, {%0,%1,%2,%3};"
        : "+f"(c[0]), "+f"(c[1]), "+f"(c[2]), "+f"(c[3])
        : "r"(a[0]), "r"(a[1]), "r"(a[2]), "r"(a[3]), "r"(b[0]), "r"(b[1]));
}

// ---------------------------------------------------------------------------
// 3xBF16 split GEMM, 128x128 tile, pipelined; optional fp16 output store
// ---------------------------------------------------------------------------
template <int K, bool BRELU, bool HALF_OUT>
__global__ void __launch_bounds__(512)
mma_gemm_kernel(const float* __restrict__ A, const __nv_bfloat16* __restrict__ Whi,
                const __nv_bfloat16* __restrict__ Wlo, const float* __restrict__ bias,
                float* __restrict__ C, int N, int NOUT) {
    __shared__ __nv_bfloat16 AsH[128][40];
    __shared__ __nv_bfloat16 AsL[128][40];
    __shared__ __nv_bfloat16 BsH[128][40];
    __shared__ __nv_bfloat16 BsL[128][40];

    const int tid = threadIdx.x;
    const int wid = tid >> 5, lane = tid & 31;
    const int mw = (wid & 3) * 32;
    const int nw = (wid >> 2) * 32;
    const int m0 = blockIdx.y * 128;
    const int n0 = blockIdx.x * 128;

    float acc[2][4][4] = {};
    const int ar = lane >> 2;
    const int ac = (lane & 3) * 2;

    float2 va[4];
    uint4 vbh, vbl;
    const int br = tid >> 2;
    const int bc = (tid & 3) * 8;

    auto load_tile = [&](int kt) {
        #pragma unroll
        for (int it = 0; it < 4; ++it) {
            int idx = tid + it * 512;
            int r  = idx >> 4;
            int kp = (idx & 15) * 2;
            int rr = min(m0 + r, N - 1);
            va[it] = *(const float2*)(A + (size_t)rr * K + kt + kp);
        }
        vbh = *(const uint4*)(Whi + (size_t)(n0 + br) * K + kt + bc);
        vbl = *(const uint4*)(Wlo + (size_t)(n0 + br) * K + kt + bc);
    };
    auto store_tile = [&]() {
        #pragma unroll
        for (int it = 0; it < 4; ++it) {
            int idx = tid + it * 512;
            int r  = idx >> 4;
            int kp = (idx & 15) * 2;
            __nv_bfloat16 h0 = __float2bfloat16(va[it].x);
            __nv_bfloat16 h1 = __float2bfloat16(va[it].y);
            __nv_bfloat16 l0 = __float2bfloat16(va[it].x - __bfloat162float(h0));
            __nv_bfloat16 l1 = __float2bfloat16(va[it].y - __bfloat162float(h1));
            *(uint32_t*)&AsH[r][kp] = (uint32_t)__bfloat16_as_ushort(h0) |
                                      ((uint32_t)__bfloat16_as_ushort(h1) << 16);
            *(uint32_t*)&AsL[r][kp] = (uint32_t)__bfloat16_as_ushort(l0) |
                                      ((uint32_t)__bfloat16_as_ushort(l1) << 16);
        }
        *(uint4*)&BsH[br][bc] = vbh;
        *(uint4*)&BsL[br][bc] = vbl;
    };

    load_tile(0);
    store_tile();
    __syncthreads();

    for (int kt = 0; kt < K; kt += 32) {
        const bool more = (kt + 32) < K;
        if (more) load_tile(kt + 32);

        #pragma unroll
        for (int k16 = 0; k16 < 32; k16 += 16) {
            uint32_t ah[2][4], al[2][4];
            #pragma unroll
            for (int mt = 0; mt < 2; ++mt) {
                int r = mw + mt * 16 + ar;
                ah[mt][0] = *(uint32_t*)&AsH[r][k16 + ac];
                ah[mt][1] = *(uint32_t*)&AsH[r + 8][k16 + ac];
                ah[mt][2] = *(uint32_t*)&AsH[r][k16 + ac + 8];
                ah[mt][3] = *(uint32_t*)&AsH[r + 8][k16 + ac + 8];
                al[mt][0] = *(uint32_t*)&AsL[r][k16 + ac];
                al[mt][1] = *(uint32_t*)&AsL[r + 8][k16 + ac];
                al[mt][2] = *(uint32_t*)&AsL[r][k16 + ac + 8];
                al[mt][3] = *(uint32_t*)&AsL[r + 8][k16 + ac + 8];
            }
            uint32_t bh[4][2], bl[4][2];
            #pragma unroll
            for (int nt = 0; nt < 4; ++nt) {
                int r = nw + nt * 8 + ar;
                bh[nt][0] = *(uint32_t*)&BsH[r][k16 + ac];
                bh[nt][1] = *(uint32_t*)&BsH[r][k16 + ac + 8];
                bl[nt][0] = *(uint32_t*)&BsL[r][k16 + ac];
                bl[nt][1] = *(uint32_t*)&BsL[r][k16 + ac + 8];
            }
            #pragma unroll
            for (int mt = 0; mt < 2; ++mt)
                #pragma unroll
                for (int nt = 0; nt < 4; ++nt) {
                    mma16816(acc[mt][nt], ah[mt], bh[nt]);
                    mma16816(acc[mt][nt], ah[mt], bl[nt]);
                    mma16816(acc[mt][nt], al[mt], bh[nt]);
                }
        }
        if (more) {
            __syncthreads();
            store_tile();
            __syncthreads();
        }
    }

    #pragma unroll
    for (int mt = 0; mt < 2; ++mt) {
        int r0 = m0 + mw + mt * 16 + ar;
        #pragma unroll
        for (int nt = 0; nt < 4; ++nt) {
            int c = n0 + nw + nt * 8 + ac;
            float2 o0 = make_float2(acc[mt][nt][0], acc[mt][nt][1]);
            float2 o1 = make_float2(acc[mt][nt][2], acc[mt][nt][3]);
            if (BRELU) {
                float b0 = __ldg(&bias[c]), b1 = __ldg(&bias[c + 1]);
                o0.x = fmaxf(o0.x + b0, 0.f); o0.y = fmaxf(o0.y + b1, 0.f);
                o1.x = fmaxf(o1.x + b0, 0.f); o1.y = fmaxf(o1.y + b1, 0.f);
            }
            if (HALF_OUT) {
                __half* Ch = (__half*)C;
                if (r0 < N)
                    *(__half2*)(Ch + (size_t)r0 * NOUT + c) = __floats2half2_rn(o0.x, o0.y);
                if (r0 + 8 < N)
                    *(__half2*)(Ch + (size_t)(r0 + 8) * NOUT + c) = __floats2half2_rn(o1.x, o1.y);
            } else {
                if (r0 < N)     *(float2*)(C + (size_t)r0 * NOUT + c) = o0;
                if (r0 + 8 < N) *(float2*)(C + (size_t)(r0 + 8) * NOUT + c) = o1;
            }
        }
    }
}

// ---------------------------------------------------------------------------
// fused gather + self-loop (+bias) (+relu); optional fp16 input
// ---------------------------------------------------------------------------
template <int H, bool RELU, bool BIAS, bool HALF_IN>
__global__ void gather_kernel(const void* __restrict__ hv_in, const float* __restrict__ bias,
                              float* __restrict__ out) {
    constexpr int HALVES = H / 128;
    int w = (blockIdx.x * blockDim.x + threadIdx.x) >> 5;
    int n = w / HALVES;
    if (n >= NNODES) return;
    int half = w - n * HALVES;
    int lane = threadIdx.x & 31;
    int col  = half * 128 + lane * 4;

    auto loadrow = [&](int s) -> float4 {
        if (HALF_IN) {
            const __half* hp = (const __half*)hv_in + (size_t)s * H + col;
            uint2 raw = __ldg((const uint2*)hp);
            __half2 p0 = *reinterpret_cast<__half2*>(&raw.x);
            __half2 p1 = *reinterpret_cast<__half2*>(&raw.y);
            float2 f0 = __half22float2(p0), f1 = __half22float2(p1);
            return make_float4(f0.x, f0.y, f1.x, f1.y);
        } else {
            return __ldg((const float4*)((const float*)hv_in + (size_t)s * H + col));
        }
    };

    int p  = __ldg(&g_rowptr[n]);
    int p1 = __ldg(&g_rowptr[n + 1]);

    float4 acc = make_float4(0.f, 0.f, 0.f, 0.f);
    for (; p + 3 < p1; p += 4) {
        int2 e0 = __ldg(&g_epack[p]);
        int2 e1 = __ldg(&g_epack[p + 1]);
        int2 e2 = __ldg(&g_epack[p + 2]);
        int2 e3 = __ldg(&g_epack[p + 3]);
        float c0 = __int_as_float(e0.y), c1 = __int_as_float(e1.y);
        float c2 = __int_as_float(e2.y), c3 = __int_as_float(e3.y);
        float4 v0 = loadrow(e0.x);
        float4 v1 = loadrow(e1.x);
        float4 v2 = loadrow(e2.x);
        float4 v3 = loadrow(e3.x);
        acc.x += c0 * v0.x + c1 * v1.x + c2 * v2.x + c3 * v3.x;
        acc.y += c0 * v0.y + c1 * v1.y + c2 * v2.y + c3 * v3.y;
        acc.z += c0 * v0.z + c1 * v1.z + c2 * v2.z + c3 * v3.z;
        acc.w += c0 * v0.w + c1 * v1.w + c2 * v2.w + c3 * v3.w;
    }
    for (; p < p1; ++p) {
        int2 e = __ldg(&g_epack[p]);
        float c = __int_as_float(e.y);
        float4 v = loadrow(e.x);
        acc.x += c * v.x; acc.y += c * v.y; acc.z += c * v.z; acc.w += c * v.w;
    }

    float dis = g_dis[n];
    float c2 = dis * dis;
    float4 hv = loadrow(n);
    float4 r;
    r.x = acc.x + c2 * hv.x;
    r.y = acc.y + c2 * hv.y;
    r.z = acc.z + c2 * hv.z;
    r.w = acc.w + c2 * hv.w;
    if (BIAS) {
        float4 bv = __ldg((const float4*)(bias + col));
        r.x += bv.x; r.y += bv.y; r.z += bv.z; r.w += bv.w;
    }
    if (RELU) {
        r.x = fmaxf(r.x, 0.f); r.y = fmaxf(r.y, 0.f);
        r.z = fmaxf(r.z, 0.f); r.w = fmaxf(r.w, 0.f);
    }
    *(float4*)(out + (size_t)n * H + col) = r;
}

// ---------------------------------------------------------------------------
// pooling + fused finish
// ---------------------------------------------------------------------------
__global__ void pool_kernel(const float* __restrict__ ne, const int* __restrict__ batch,
                            float* __restrict__ gsum, int N) {
    int c  = threadIdx.x;
    int n0 = blockIdx.x * 256;
    int n1 = min(n0 + 256, N);
    float acc = 0.0f;
    int cur = -1;
    for (int n = n0; n < n1; ++n) {
        int g = __ldg(&batch[n]);
        if (g != cur) {
            if (cur >= 0) atomicAdd(&gsum[cur * DOUTC + c], acc);
            acc = 0.0f;
            cur = g;
        }
        acc += ne[(size_t)n * DOUTC + c];
    }
    if (cur >= 0) atomicAdd(&gsum[cur * DOUTC + c], acc);
}

__global__ void finish_kernel(const int* __restrict__ batch, float* __restrict__ gsum,
                              const float* __restrict__ Wc, const float* __restrict__ bc,
                              float* __restrict__ logit) {
    int g = blockIdx.x;
    __shared__ float cnt_s;
    __shared__ float row[DOUTC];
    if (threadIdx.x == 0) {
        int lo = 0, hi = NNODES;
        while (lo < hi) { int mid = (lo + hi) >> 1; if (__ldg(&batch[mid]) < g) lo = mid + 1; else hi = mid; }
        int lb = lo;
        lo = 0; hi = NNODES;
        while (lo < hi) { int mid = (lo + hi) >> 1; if (__ldg(&batch[mid]) <= g) lo = mid + 1; else hi = mid; }
        cnt_s = fmaxf((float)(lo - lb), 1.0f);
    }
    __syncthreads();
    int c = threadIdx.x;
    float v = gsum[g * DOUTC + c] / cnt_s;
    gsum[g * DOUTC + c] = v;
    row[c] = v;
    __syncthreads();
    if (c < 2) {
        float s = __ldg(&bc[c]);
        #pragma unroll 8
        for (int k = 0; k < DOUTC; ++k) s += row[k] * __ldg(&Wc[k * 2 + c]);
        logit[g * 2 + c] = s;
    }
}

// ---------------------------------------------------------------------------
// launch
// ---------------------------------------------------------------------------
extern "C" void kernel_launch(void* const* d_in, const int* in_sizes, int n_in,
                              void* d_out, int out_size) {
    const float* x     = (const float*)d_in[0];
    const int*   ei    = (const int*)d_in[1];
    const int*   batch = (const int*)d_in[2];
    const float* W_in  = (const float*)d_in[3];
    const float* b_in  = (const float*)d_in[4];
    const float* W_mid = (const float*)d_in[5];
    const float* b_mid = (const float*)d_in[6];
    const float* W_out = (const float*)d_in[7];
    const float* b_out = (const float*)d_in[8];
    const float* W_cls = (const float*)d_in[9];
    const float* b_cls = (const float*)d_in[10];

    const int* src = ei;
    const int* dst = ei + NEDGES;

    float *bufA, *bufB;
    __nv_bfloat16 *w1h, *w1l, *w2h, *w2l, *w3h, *w3l;
    cudaGetSymbolAddress((void**)&bufA, g_bufA);
    cudaGetSymbolAddress((void**)&bufB, g_bufB);
    cudaGetSymbolAddress((void**)&w1h, g_w1_hi);
    cudaGetSymbolAddress((void**)&w1l, g_w1_lo);
    cudaGetSymbolAddress((void**)&w2h, g_w2_hi);
    cudaGetSymbolAddress((void**)&w2l, g_w2_lo);
    cudaGetSymbolAddress((void**)&w3h, g_w3_hi);
    cudaGetSymbolAddress((void**)&w3l, g_w3_lo);

    float* node   = (float*)d_out;
    float* gsum   = node + (size_t)NNODES * DOUTC;
    float* logit  = gsum + NGRAPH * DOUTC;

    const int T = 256;

    // ----- prep (weights + zero counters), x->fp16, CSR build -----
    prep_kernel<<<680, T>>>(W_in, W_mid, W_out);
    tohalf_kernel<<<640, T>>>((const float4*)x, (uint2*)bufB, NNODES * DIN / 4);
    hist_kernel<<<(NEDGES + T - 1) / T, T>>>(dst, NEDGES);
    scan1_kernel<<<SCAN_NB, SCAN_B>>>((float4*)gsum);
    scan23_kernel<<<SCAN_NB, SCAN_B>>>();
    csrfill_kernel<<<(NEDGES + T - 1) / T, T>>>(src, dst, NEDGES);

    const int GB = (NNODES + 127) / 128;   // 313

    // ----- layer 1: propagate(x fp16) -> fp32, then GEMM + bias + relu -----
    gather_kernel<DIN, false, false, true><<<(NNODES * 32 + T - 1) / T, T>>>(bufB, nullptr, bufA);
    mma_gemm_kernel<DIN, true, false><<<dim3(2, GB), 512>>>(bufA, w1h, w1l, b_in, bufB,
                                                            NNODES, DH);

    // ----- layer 2: GEMM (fp16 out), then propagate(fp16 in) + bias + relu -----
    mma_gemm_kernel<DH, false, true><<<dim3(2, GB), 512>>>(bufB, w2h, w2l, nullptr, bufA,
                                                           NNODES, DH);
    gather_kernel<DH, true, true, true><<<(NNODES * 2 * 32 + T - 1) / T, T>>>(bufA, b_mid, bufB);

    // ----- layer 3: GEMM (fp16 out), then propagate(fp16 in) + bias -----
    mma_gemm_kernel<DH, false, true><<<dim3(1, GB), 512>>>(bufB, w3h, w3l, nullptr, bufA,
                                                           NNODES, DOUTC);
    gather_kernel<DOUTC, false, true, true><<<(NNODES * 32 + T - 1) / T, T>>>(bufA, b_out, node);

    // ----- mean pool + classifier -----
    pool_kernel<<<(NNODES + 255) / 256, 128>>>(node, batch, gsum, NNODES);
    finish_kernel<<<NGRAPH, DOUTC>>>(batch, gsum, W_cls, b_cls, logit);
}

// round 13
// speedup vs baseline: 1.3676x; 1.0282x over previous
#include <cuda_runtime.h>
#include <cuda_bf16.h>
#include <cuda_fp16.h>
#include <stdint.h>

#define NNODES 40000
#define NEDGES 640000
#define NGRAPH 64
#define DIN    128
#define DH     256
#define DOUTC  128

#define SCAN_B 256
#define SCAN_NB ((NNODES + SCAN_B - 1) / SCAN_B)   // 157

// ---- scratch (no allocations allowed) ----
__device__ float g_bufA[NNODES * DH];
__device__ float g_bufB[NNODES * DH];
__device__ float g_dis[NNODES];
// CSR scratch
__device__ int   g_cnti[NNODES];
__device__ int   g_rowptr[NNODES + 1];
__device__ int   g_cursor[NNODES];
__device__ int2  g_epack[NEDGES];          // {src, coef-as-int}
__device__ int   g_bsum[SCAN_NB];
// weights transposed to [NOUT, K] row-major, bf16 hi/lo split
__device__ __nv_bfloat16 g_w1_hi[DH * DIN];
__device__ __nv_bfloat16 g_w1_lo[DH * DIN];
__device__ __nv_bfloat16 g_w2_hi[DH * DH];
__device__ __nv_bfloat16 g_w2_lo[DH * DH];
__device__ __nv_bfloat16 g_w3_hi[DOUTC * DH];
__device__ __nv_bfloat16 g_w3_lo[DOUTC * DH];

// ---------------------------------------------------------------------------
// prep: weight transpose + bf16 split + zero degree counters
// ---------------------------------------------------------------------------
__device__ __forceinline__ void wsplit(const float* __restrict__ W,
                                       __nv_bfloat16* __restrict__ hi,
                                       __nv_bfloat16* __restrict__ lo,
                                       int K, int NOUT, int idx) {
    int k = idx / NOUT, n = idx - k * NOUT;
    float v = W[idx];
    __nv_bfloat16 h = __float2bfloat16(v);
    __nv_bfloat16 l = __float2bfloat16(v - __bfloat162float(h));
    hi[(size_t)n * K + k] = h;
    lo[(size_t)n * K + k] = l;
}

__global__ void prep_kernel(const float* __restrict__ W1, const float* __restrict__ W2,
                            const float* __restrict__ W3) {
    constexpr int E1 = DIN * DH;
    constexpr int E2 = E1 + DH * DH;
    constexpr int E3 = E2 + DH * DOUTC;
    constexpr int TOT = E3 + NNODES;
    int i = blockIdx.x * blockDim.x + threadIdx.x;
    for (; i < TOT; i += gridDim.x * blockDim.x) {
        if (i < E1)       wsplit(W1, g_w1_hi, g_w1_lo, DIN, DH, i);
        else if (i < E2)  wsplit(W2, g_w2_hi, g_w2_lo, DH, DH, i - E1);
        else if (i < E3)  wsplit(W3, g_w3_hi, g_w3_lo, DH, DOUTC, i - E2);
        else              g_cnti[i - E3] = 0;
    }
}

// convert fp32 -> fp16, vectorized
__global__ void tohalf_kernel(const float4* __restrict__ in, uint2* __restrict__ out, int n4) {
    int i = blockIdx.x * blockDim.x + threadIdx.x;
    for (; i < n4; i += gridDim.x * blockDim.x) {
        float4 v = in[i];
        __half2 p0 = __floats2half2_rn(v.x, v.y);
        __half2 p1 = __floats2half2_rn(v.z, v.w);
        uint2 o;
        o.x = *reinterpret_cast<uint32_t*>(&p0);
        o.y = *reinterpret_cast<uint32_t*>(&p1);
        out[i] = o;
    }
}

__global__ void hist_kernel(const int* __restrict__ dst, int E) {
    int e = blockIdx.x * blockDim.x + threadIdx.x;
    if (e < E) atomicAdd(&g_cnti[dst[e]], 1);
}

// ---------------------------------------------------------------------------
// scan phase 1: block sums (+ dis + gsum zeroing piggybacked)
// ---------------------------------------------------------------------------
__global__ void scan1_kernel(float4* __restrict__ gsum4) {
    __shared__ int s[SCAN_B];
    int i = blockIdx.x * SCAN_B + threadIdx.x;
    int v = (i < NNODES) ? g_cnti[i] : 0;
    if (i < NNODES) g_dis[i] = rsqrtf((float)v + 1.0f);
    if (i < NGRAPH * DOUTC / 4) gsum4[i] = make_float4(0.f, 0.f, 0.f, 0.f);
    s[threadIdx.x] = v;
    __syncthreads();
    for (int off = SCAN_B / 2; off > 0; off >>= 1) {
        if (threadIdx.x < off) s[threadIdx.x] += s[threadIdx.x + off];
        __syncthreads();
    }
    if (threadIdx.x == 0) g_bsum[blockIdx.x] = s[0];
}

// scan phase 2+3 fused
__global__ void scan23_kernel() {
    __shared__ int s[SCAN_B];
    __shared__ int bpre_s;
    int t = threadIdx.x;
    int i = blockIdx.x * SCAN_B + t;

    int v = (t < SCAN_NB && t < blockIdx.x) ? g_bsum[t] : 0;
    s[t] = v;
    __syncthreads();
    for (int off = SCAN_B / 2; off > 0; off >>= 1) {
        if (t < off) s[t] += s[t + off];
        __syncthreads();
    }
    if (t == 0) bpre_s = s[0];
    __syncthreads();
    int bpre = bpre_s;
    __syncthreads();

    int v0 = (i < NNODES) ? g_cnti[i] : 0;
    s[t] = v0;
    __syncthreads();
    for (int off = 1; off < SCAN_B; off <<= 1) {
        int u = (t >= off) ? s[t - off] : 0;
        __syncthreads();
        s[t] += u;
        __syncthreads();
    }
    if (i < NNODES) {
        int ex = bpre + s[t] - v0;
        g_rowptr[i] = ex;
        g_cursor[i] = ex;
    }
    if (blockIdx.x == 0 && t == 0) g_rowptr[NNODES] = NEDGES;
}

__global__ void csrfill_kernel(const int* __restrict__ src, const int* __restrict__ dst,
                               int E) {
    int e = blockIdx.x * blockDim.x + threadIdx.x;
    if (e >= E) return;
    int s = src[e], d = dst[e];
    int p = atomicAdd(&g_cursor[d], 1);
    g_epack[p] = make_int2(s, __float_as_int(g_dis[s] * g_dis[d]));
}

// ---------------------------------------------------------------------------
// mma helper
// ---------------------------------------------------------------------------
__device__ __forceinline__ void mma16816(float* c, const uint32_t* a, const uint32_t* b) {
    asm volatile(
        "mma.sync.aligned.m16n8k16.row.col.f32.bf16.bf16.f32 "
        "{%0,%1,%2,%3}, {%4,%5,%6,%7}, {%8,%9}, {%0,%1,%2,%3};"
        : "+f"(c[0]), "+f"(c[1]), "+f"(c[2]), "+f"(c[3])
        : "r"(a[0]), "r"(a[1]), "r"(a[2]), "r"(a[3]), "r"(b[0]), "r"(b[1]));
}

// ---------------------------------------------------------------------------
// 3xBF16 split GEMM, 128x128 tile, pipelined.
// HALF_A: A operand is fp16 (lossless into bf16 hi/lo). HALF_OUT: fp16 C store.
// ---------------------------------------------------------------------------
template <int K, bool BRELU, bool HALF_OUT, bool HALF_A>
__global__ void __launch_bounds__(512)
mma_gemm_kernel(const void* __restrict__ Av, const __nv_bfloat16* __restrict__ Whi,
                const __nv_bfloat16* __restrict__ Wlo, const float* __restrict__ bias,
                void* __restrict__ Cv, int N, int NOUT) {
    __shared__ __nv_bfloat16 AsH[128][40];
    __shared__ __nv_bfloat16 AsL[128][40];
    __shared__ __nv_bfloat16 BsH[128][40];
    __shared__ __nv_bfloat16 BsL[128][40];

    const int tid = threadIdx.x;
    const int wid = tid >> 5, lane = tid & 31;
    const int mw = (wid & 3) * 32;
    const int nw = (wid >> 2) * 32;
    const int m0 = blockIdx.y * 128;
    const int n0 = blockIdx.x * 128;

    float acc[2][4][4] = {};
    const int ar = lane >> 2;
    const int ac = (lane & 3) * 2;

    float2 va[4];             // fp32 pair, or raw fp16x2 bits in .x when HALF_A
    uint4 vbh, vbl;
    const int br = tid >> 2;
    const int bc = (tid & 3) * 8;

    auto load_tile = [&](int kt) {
        #pragma unroll
        for (int it = 0; it < 4; ++it) {
            int idx = tid + it * 512;
            int r  = idx >> 4;
            int kp = (idx & 15) * 2;
            int rr = min(m0 + r, N - 1);
            if (HALF_A) {
                uint32_t raw = __ldg((const uint32_t*)((const __half*)Av +
                                     (size_t)rr * K + kt + kp));
                va[it].x = __uint_as_float(raw);
            } else {
                va[it] = *(const float2*)((const float*)Av + (size_t)rr * K + kt + kp);
            }
        }
        vbh = *(const uint4*)(Whi + (size_t)(n0 + br) * K + kt + bc);
        vbl = *(const uint4*)(Wlo + (size_t)(n0 + br) * K + kt + bc);
    };
    auto store_tile = [&]() {
        #pragma unroll
        for (int it = 0; it < 4; ++it) {
            int idx = tid + it * 512;
            int r  = idx >> 4;
            int kp = (idx & 15) * 2;
            float fx, fy;
            if (HALF_A) {
                uint32_t raw = __float_as_uint(va[it].x);
                __half2 h2 = *reinterpret_cast<__half2*>(&raw);
                float2 f = __half22float2(h2);
                fx = f.x; fy = f.y;
            } else {
                fx = va[it].x; fy = va[it].y;
            }
            __nv_bfloat16 h0 = __float2bfloat16(fx);
            __nv_bfloat16 h1 = __float2bfloat16(fy);
            __nv_bfloat16 l0 = __float2bfloat16(fx - __bfloat162float(h0));
            __nv_bfloat16 l1 = __float2bfloat16(fy - __bfloat162float(h1));
            *(uint32_t*)&AsH[r][kp] = (uint32_t)__bfloat16_as_ushort(h0) |
                                      ((uint32_t)__bfloat16_as_ushort(h1) << 16);
            *(uint32_t*)&AsL[r][kp] = (uint32_t)__bfloat16_as_ushort(l0) |
                                      ((uint32_t)__bfloat16_as_ushort(l1) << 16);
        }
        *(uint4*)&BsH[br][bc] = vbh;
        *(uint4*)&BsL[br][bc] = vbl;
    };

    load_tile(0);
    store_tile();
    __syncthreads();

    for (int kt = 0; kt < K; kt += 32) {
        const bool more = (kt + 32) < K;
        if (more) load_tile(kt + 32);

        #pragma unroll
        for (int k16 = 0; k16 < 32; k16 += 16) {
            uint32_t ah[2][4], al[2][4];
            #pragma unroll
            for (int mt = 0; mt < 2; ++mt) {
                int r = mw + mt * 16 + ar;
                ah[mt][0] = *(uint32_t*)&AsH[r][k16 + ac];
                ah[mt][1] = *(uint32_t*)&AsH[r + 8][k16 + ac];
                ah[mt][2] = *(uint32_t*)&AsH[r][k16 + ac + 8];
                ah[mt][3] = *(uint32_t*)&AsH[r + 8][k16 + ac + 8];
                al[mt][0] = *(uint32_t*)&AsL[r][k16 + ac];
                al[mt][1] = *(uint32_t*)&AsL[r + 8][k16 + ac];
                al[mt][2] = *(uint32_t*)&AsL[r][k16 + ac + 8];
                al[mt][3] = *(uint32_t*)&AsL[r + 8][k16 + ac + 8];
            }
            uint32_t bh[4][2], bl[4][2];
            #pragma unroll
            for (int nt = 0; nt < 4; ++nt) {
                int r = nw + nt * 8 + ar;
                bh[nt][0] = *(uint32_t*)&BsH[r][k16 + ac];
                bh[nt][1] = *(uint32_t*)&BsH[r][k16 + ac + 8];
                bl[nt][0] = *(uint32_t*)&BsL[r][k16 + ac];
                bl[nt][1] = *(uint32_t*)&BsL[r][k16 + ac + 8];
            }
            #pragma unroll
            for (int mt = 0; mt < 2; ++mt)
                #pragma unroll
                for (int nt = 0; nt < 4; ++nt) {
                    mma16816(acc[mt][nt], ah[mt], bh[nt]);
                    mma16816(acc[mt][nt], ah[mt], bl[nt]);
                    mma16816(acc[mt][nt], al[mt], bh[nt]);
                }
        }
        if (more) {
            __syncthreads();
            store_tile();
            __syncthreads();
        }
    }

    #pragma unroll
    for (int mt = 0; mt < 2; ++mt) {
        int r0 = m0 + mw + mt * 16 + ar;
        #pragma unroll
        for (int nt = 0; nt < 4; ++nt) {
            int c = n0 + nw + nt * 8 + ac;
            float2 o0 = make_float2(acc[mt][nt][0], acc[mt][nt][1]);
            float2 o1 = make_float2(acc[mt][nt][2], acc[mt][nt][3]);
            if (BRELU) {
                float b0 = __ldg(&bias[c]), b1 = __ldg(&bias[c + 1]);
                o0.x = fmaxf(o0.x + b0, 0.f); o0.y = fmaxf(o0.y + b1, 0.f);
                o1.x = fmaxf(o1.x + b0, 0.f); o1.y = fmaxf(o1.y + b1, 0.f);
            }
            if (HALF_OUT) {
                __half* Ch = (__half*)Cv;
                if (r0 < N)
                    *(__half2*)(Ch + (size_t)r0 * NOUT + c) = __floats2half2_rn(o0.x, o0.y);
                if (r0 + 8 < N)
                    *(__half2*)(Ch + (size_t)(r0 + 8) * NOUT + c) = __floats2half2_rn(o1.x, o1.y);
            } else {
                float* Cf = (float*)Cv;
                if (r0 < N)     *(float2*)(Cf + (size_t)r0 * NOUT + c) = o0;
                if (r0 + 8 < N) *(float2*)(Cf + (size_t)(r0 + 8) * NOUT + c) = o1;
            }
        }
    }
}

// ---------------------------------------------------------------------------
// fused gather + self-loop (+bias) (+relu): ONE warp per node, all H columns.
// HALF_IN / HALF_OUT select fp16 data paths.
// ---------------------------------------------------------------------------
template <int H, bool RELU, bool BIAS, bool HALF_IN, bool HALF_OUT>
__global__ void gather_kernel(const void* __restrict__ hv_in, const float* __restrict__ bias,
                              void* __restrict__ out_v) {
    constexpr int NCH = H / 128;              // float4 chunks per lane
    int n = (blockIdx.x * blockDim.x + threadIdx.x) >> 5;
    if (n >= NNODES) return;
    int lane = threadIdx.x & 31;
    int col0 = lane * 4;

    auto loadrow = [&](int s, int c) -> float4 {
        if (HALF_IN) {
            const __half* hp = (const __half*)hv_in + (size_t)s * H + col0 + c * 128;
            uint2 raw = __ldg((const uint2*)hp);
            __half2 p0 = *reinterpret_cast<__half2*>(&raw.x);
            __half2 p1 = *reinterpret_cast<__half2*>(&raw.y);
            float2 f0 = __half22float2(p0), f1 = __half22float2(p1);
            return make_float4(f0.x, f0.y, f1.x, f1.y);
        } else {
            return __ldg((const float4*)((const float*)hv_in + (size_t)s * H + col0 + c * 128));
        }
    };

    int p  = __ldg(&g_rowptr[n]);
    int p1 = __ldg(&g_rowptr[n + 1]);

    float4 acc[NCH];
    #pragma unroll
    for (int c = 0; c < NCH; ++c) acc[c] = make_float4(0.f, 0.f, 0.f, 0.f);

    for (; p + 3 < p1; p += 4) {
        int2 e[4];
        e[0] = __ldg(&g_epack[p]);
        e[1] = __ldg(&g_epack[p + 1]);
        e[2] = __ldg(&g_epack[p + 2]);
        e[3] = __ldg(&g_epack[p + 3]);
        float4 v[4][NCH];
        #pragma unroll
        for (int j = 0; j < 4; ++j)
            #pragma unroll
            for (int c = 0; c < NCH; ++c) v[j][c] = loadrow(e[j].x, c);
        #pragma unroll
        for (int j = 0; j < 4; ++j) {
            float cf = __int_as_float(e[j].y);
            #pragma unroll
            for (int c = 0; c < NCH; ++c) {
                acc[c].x += cf * v[j][c].x;
                acc[c].y += cf * v[j][c].y;
                acc[c].z += cf * v[j][c].z;
                acc[c].w += cf * v[j][c].w;
            }
        }
    }
    for (; p < p1; ++p) {
        int2 e = __ldg(&g_epack[p]);
        float cf = __int_as_float(e.y);
        #pragma unroll
        for (int c = 0; c < NCH; ++c) {
            float4 v = loadrow(e.x, c);
            acc[c].x += cf * v.x; acc[c].y += cf * v.y;
            acc[c].z += cf * v.z; acc[c].w += cf * v.w;
        }
    }

    float dis = g_dis[n];
    float sc = dis * dis;
    #pragma unroll
    for (int c = 0; c < NCH; ++c) {
        float4 hv = loadrow(n, c);
        float4 r;
        r.x = acc[c].x + sc * hv.x;
        r.y = acc[c].y + sc * hv.y;
        r.z = acc[c].z + sc * hv.z;
        r.w = acc[c].w + sc * hv.w;
        if (BIAS) {
            float4 bv = __ldg((const float4*)(bias + col0 + c * 128));
            r.x += bv.x; r.y += bv.y; r.z += bv.z; r.w += bv.w;
        }
        if (RELU) {
            r.x = fmaxf(r.x, 0.f); r.y = fmaxf(r.y, 0.f);
            r.z = fmaxf(r.z, 0.f); r.w = fmaxf(r.w, 0.f);
        }
        if (HALF_OUT) {
            __half* op = (__half*)out_v + (size_t)n * H + col0 + c * 128;
            __half2 p0 = __floats2half2_rn(r.x, r.y);
            __half2 p1 = __floats2half2_rn(r.z, r.w);
            uint2 o;
            o.x = *reinterpret_cast<uint32_t*>(&p0);
            o.y = *reinterpret_cast<uint32_t*>(&p1);
            *(uint2*)op = o;
        } else {
            *(float4*)((float*)out_v + (size_t)n * H + col0 + c * 128) = r;
        }
    }
}

// ---------------------------------------------------------------------------
// pooling + fused finish
// ---------------------------------------------------------------------------
__global__ void pool_kernel(const float* __restrict__ ne, const int* __restrict__ batch,
                            float* __restrict__ gsum, int N) {
    int c  = threadIdx.x;
    int n0 = blockIdx.x * 256;
    int n1 = min(n0 + 256, N);
    float acc = 0.0f;
    int cur = -1;
    for (int n = n0; n < n1; ++n) {
        int g = __ldg(&batch[n]);
        if (g != cur) {
            if (cur >= 0) atomicAdd(&gsum[cur * DOUTC + c], acc);
            acc = 0.0f;
            cur = g;
        }
        acc += ne[(size_t)n * DOUTC + c];
    }
    if (cur >= 0) atomicAdd(&gsum[cur * DOUTC + c], acc);
}

__global__ void finish_kernel(const int* __restrict__ batch, float* __restrict__ gsum,
                              const float* __restrict__ Wc, const float* __restrict__ bc,
                              float* __restrict__ logit) {
    int g = blockIdx.x;
    __shared__ float cnt_s;
    __shared__ float row[DOUTC];
    if (threadIdx.x == 0) {
        int lo = 0, hi = NNODES;
        while (lo < hi) { int mid = (lo + hi) >> 1; if (__ldg(&batch[mid]) < g) lo = mid + 1; else hi = mid; }
        int lb = lo;
        lo = 0; hi = NNODES;
        while (lo < hi) { int mid = (lo + hi) >> 1; if (__ldg(&batch[mid]) <= g) lo = mid + 1; else hi = mid; }
        cnt_s = fmaxf((float)(lo - lb), 1.0f);
    }
    __syncthreads();
    int c = threadIdx.x;
    float v = gsum[g * DOUTC + c] / cnt_s;
    gsum[g * DOUTC + c] = v;
    row[c] = v;
    __syncthreads();
    if (c < 2) {
        float s = __ldg(&bc[c]);
        #pragma unroll 8
        for (int k = 0; k < DOUTC; ++k) s += row[k] * __ldg(&Wc[k * 2 + c]);
        logit[g * 2 + c] = s;
    }
}

// ---------------------------------------------------------------------------
// launch
// ---------------------------------------------------------------------------
extern "C" void kernel_launch(void* const* d_in, const int* in_sizes, int n_in,
                              void* d_out, int out_size) {
    const float* x     = (const float*)d_in[0];
    const int*   ei    = (const int*)d_in[1];
    const int*   batch = (const int*)d_in[2];
    const float* W_in  = (const float*)d_in[3];
    const float* b_in  = (const float*)d_in[4];
    const float* W_mid = (const float*)d_in[5];
    const float* b_mid = (const float*)d_in[6];
    const float* W_out = (const float*)d_in[7];
    const float* b_out = (const float*)d_in[8];
    const float* W_cls = (const float*)d_in[9];
    const float* b_cls = (const float*)d_in[10];

    const int* src = ei;
    const int* dst = ei + NEDGES;

    float *bufA, *bufB;
    __nv_bfloat16 *w1h, *w1l, *w2h, *w2l, *w3h, *w3l;
    cudaGetSymbolAddress((void**)&bufA, g_bufA);
    cudaGetSymbolAddress((void**)&bufB, g_bufB);
    cudaGetSymbolAddress((void**)&w1h, g_w1_hi);
    cudaGetSymbolAddress((void**)&w1l, g_w1_lo);
    cudaGetSymbolAddress((void**)&w2h, g_w2_hi);
    cudaGetSymbolAddress((void**)&w2l, g_w2_lo);
    cudaGetSymbolAddress((void**)&w3h, g_w3_hi);
    cudaGetSymbolAddress((void**)&w3l, g_w3_lo);

    float* node   = (float*)d_out;
    float* gsum   = node + (size_t)NNODES * DOUTC;
    float* logit  = gsum + NGRAPH * DOUTC;

    const int T = 256;
    const int GW = (NNODES * 32 + T - 1) / T;   // 1 warp per node

    // ----- prep (weights + zero counters), x->fp16, CSR build -----
    prep_kernel<<<680, T>>>(W_in, W_mid, W_out);
    tohalf_kernel<<<640, T>>>((const float4*)x, (uint2*)bufB, NNODES * DIN / 4);
    hist_kernel<<<(NEDGES + T - 1) / T, T>>>(dst, NEDGES);
    scan1_kernel<<<SCAN_NB, SCAN_B>>>((float4*)gsum);
    scan23_kernel<<<SCAN_NB, SCAN_B>>>();
    csrfill_kernel<<<(NEDGES + T - 1) / T, T>>>(src, dst, NEDGES);

    const int GB = (NNODES + 127) / 128;   // 313

    // ----- layer 1: propagate(x fp16)->fp16, GEMM(fp16 A) + bias + relu -> fp16 -----
    gather_kernel<DIN, false, false, true, true><<<GW, T>>>(bufB, nullptr, bufA);
    mma_gemm_kernel<DIN, true, true, true><<<dim3(2, GB), 512>>>(bufA, w1h, w1l, b_in,
                                                                 bufB, NNODES, DH);

    // ----- layer 2: GEMM(fp16 A) -> fp16, propagate + bias + relu -> fp16 -----
    mma_gemm_kernel<DH, false, true, true><<<dim3(2, GB), 512>>>(bufB, w2h, w2l, nullptr,
                                                                 bufA, NNODES, DH);
    gather_kernel<DH, true, true, true, true><<<GW, T>>>(bufA, b_mid, bufB);

    // ----- layer 3: GEMM(fp16 A) -> fp16, propagate + bias -> fp32 node -----
    mma_gemm_kernel<DH, false, true, true><<<dim3(1, GB), 512>>>(bufB, w3h, w3l, nullptr,
                                                                 bufA, NNODES, DOUTC);
    gather_kernel<DOUTC, false, true, true, false><<<GW, T>>>(bufA, b_out, node);

    // ----- mean pool + classifier -----
    pool_kernel<<<(NNODES + 255) / 256, 128>>>(node, batch, gsum, NNODES);
    finish_kernel<<<NGRAPH, DOUTC>>>(batch, gsum, W_cls, b_cls, logit);
}

// round 14
// speedup vs baseline: 1.5363x; 1.1233x over previous
#include <cuda_runtime.h>
#include <cuda_bf16.h>
#include <cuda_fp16.h>
#include <stdint.h>

#define NNODES 40000
#define NEDGES 640000
#define NGRAPH 64
#define DIN    128
#define DH     256
#define DOUTC  128

#define SCAN_B 256
#define SCAN_NB ((NNODES + SCAN_B - 1) / SCAN_B)   // 157

// ---- scratch (no allocations allowed) ----
__device__ float g_bufA[NNODES * DH];
__device__ float g_bufB[NNODES * DH];
__device__ float g_dis[NNODES];
// CSR scratch
__device__ int   g_cnti[NNODES];
__device__ int   g_rowptr[NNODES + 1];
__device__ int   g_cursor[NNODES];
__device__ int2  g_epack[NEDGES];          // {src, coef-as-int}
__device__ int   g_bsum[SCAN_NB];
// weights transposed to [NOUT, K] row-major, fp16 hi/lo split (11+11 bits ~ exact)
__device__ __half g_w1_hi[DH * DIN];
__device__ __half g_w1_lo[DH * DIN];
__device__ __half g_w2_hi[DH * DH];
__device__ __half g_w2_lo[DH * DH];
__device__ __half g_w3_hi[DOUTC * DH];
__device__ __half g_w3_lo[DOUTC * DH];

// ---------------------------------------------------------------------------
// prep: weight transpose + fp16 split + zero degree counters
// ---------------------------------------------------------------------------
__device__ __forceinline__ void wsplit(const float* __restrict__ W,
                                       __half* __restrict__ hi,
                                       __half* __restrict__ lo,
                                       int K, int NOUT, int idx) {
    int k = idx / NOUT, n = idx - k * NOUT;
    float v = W[idx];
    __half h = __float2half_rn(v);
    __half l = __float2half_rn(v - __half2float(h));
    hi[(size_t)n * K + k] = h;
    lo[(size_t)n * K + k] = l;
}

__global__ void prep_kernel(const float* __restrict__ W1, const float* __restrict__ W2,
                            const float* __restrict__ W3) {
    constexpr int E1 = DIN * DH;
    constexpr int E2 = E1 + DH * DH;
    constexpr int E3 = E2 + DH * DOUTC;
    constexpr int TOT = E3 + NNODES;
    int i = blockIdx.x * blockDim.x + threadIdx.x;
    for (; i < TOT; i += gridDim.x * blockDim.x) {
        if (i < E1)       wsplit(W1, g_w1_hi, g_w1_lo, DIN, DH, i);
        else if (i < E2)  wsplit(W2, g_w2_hi, g_w2_lo, DH, DH, i - E1);
        else if (i < E3)  wsplit(W3, g_w3_hi, g_w3_lo, DH, DOUTC, i - E2);
        else              g_cnti[i - E3] = 0;
    }
}

// convert fp32 -> fp16, vectorized
__global__ void tohalf_kernel(const float4* __restrict__ in, uint2* __restrict__ out, int n4) {
    int i = blockIdx.x * blockDim.x + threadIdx.x;
    for (; i < n4; i += gridDim.x * blockDim.x) {
        float4 v = in[i];
        __half2 p0 = __floats2half2_rn(v.x, v.y);
        __half2 p1 = __floats2half2_rn(v.z, v.w);
        uint2 o;
        o.x = *reinterpret_cast<uint32_t*>(&p0);
        o.y = *reinterpret_cast<uint32_t*>(&p1);
        out[i] = o;
    }
}

__global__ void hist_kernel(const int* __restrict__ dst, int E) {
    int e = blockIdx.x * blockDim.x + threadIdx.x;
    if (e < E) atomicAdd(&g_cnti[dst[e]], 1);
}

// ---------------------------------------------------------------------------
// scan phase 1: block sums (+ dis + gsum zeroing piggybacked)
// ---------------------------------------------------------------------------
__global__ void scan1_kernel(float4* __restrict__ gsum4) {
    __shared__ int s[SCAN_B];
    int i = blockIdx.x * SCAN_B + threadIdx.x;
    int v = (i < NNODES) ? g_cnti[i] : 0;
    if (i < NNODES) g_dis[i] = rsqrtf((float)v + 1.0f);
    if (i < NGRAPH * DOUTC / 4) gsum4[i] = make_float4(0.f, 0.f, 0.f, 0.f);
    s[threadIdx.x] = v;
    __syncthreads();
    for (int off = SCAN_B / 2; off > 0; off >>= 1) {
        if (threadIdx.x < off) s[threadIdx.x] += s[threadIdx.x + off];
        __syncthreads();
    }
    if (threadIdx.x == 0) g_bsum[blockIdx.x] = s[0];
}

// scan phase 2+3 fused
__global__ void scan23_kernel() {
    __shared__ int s[SCAN_B];
    __shared__ int bpre_s;
    int t = threadIdx.x;
    int i = blockIdx.x * SCAN_B + t;

    int v = (t < SCAN_NB && t < blockIdx.x) ? g_bsum[t] : 0;
    s[t] = v;
    __syncthreads();
    for (int off = SCAN_B / 2; off > 0; off >>= 1) {
        if (t < off) s[t] += s[t + off];
        __syncthreads();
    }
    if (t == 0) bpre_s = s[0];
    __syncthreads();
    int bpre = bpre_s;
    __syncthreads();

    int v0 = (i < NNODES) ? g_cnti[i] : 0;
    s[t] = v0;
    __syncthreads();
    for (int off = 1; off < SCAN_B; off <<= 1) {
        int u = (t >= off) ? s[t - off] : 0;
        __syncthreads();
        s[t] += u;
        __syncthreads();
    }
    if (i < NNODES) {
        int ex = bpre + s[t] - v0;
        g_rowptr[i] = ex;
        g_cursor[i] = ex;
    }
    if (blockIdx.x == 0 && t == 0) g_rowptr[NNODES] = NEDGES;
}

__global__ void csrfill_kernel(const int* __restrict__ src, const int* __restrict__ dst,
                               int E) {
    int e = blockIdx.x * blockDim.x + threadIdx.x;
    if (e >= E) return;
    int s = src[e], d = dst[e];
    int p = atomicAdd(&g_cursor[d], 1);
    g_epack[p] = make_int2(s, __float_as_int(g_dis[s] * g_dis[d]));
}

// ---------------------------------------------------------------------------
// mma helper: fp16 inputs, fp32 accum
// ---------------------------------------------------------------------------
__device__ __forceinline__ void mma16816h(float* c, const uint32_t* a, const uint32_t* b) {
    asm volatile(
        "mma.sync.aligned.m16n8k16.row.col.f32.f16.f16.f32 "
        "{%0,%1,%2,%3}, {%4,%5,%6,%7}, {%8,%9}, {%0,%1,%2,%3};"
        : "+f"(c[0]), "+f"(c[1]), "+f"(c[2]), "+f"(c[3])
        : "r"(a[0]), "r"(a[1]), "r"(a[2]), "r"(a[3]), "r"(b[0]), "r"(b[1]));
}

// ---------------------------------------------------------------------------
// fp16 GEMM with fp16-split W (2 MMAs): C = A(fp16) @ (Whi + Wlo)
// 128x128 tile, pipelined. HALF_OUT: fp16 C store, else fp32.
// ---------------------------------------------------------------------------
template <int K, bool BRELU, bool HALF_OUT>
__global__ void __launch_bounds__(512)
mma_gemm_kernel(const __half* __restrict__ A, const __half* __restrict__ Whi,
                const __half* __restrict__ Wlo, const float* __restrict__ bias,
                void* __restrict__ Cv, int N, int NOUT) {
    __shared__ __half As[128][40];
    __shared__ __half BsH[128][40];
    __shared__ __half BsL[128][40];

    const int tid = threadIdx.x;
    const int wid = tid >> 5, lane = tid & 31;
    const int mw = (wid & 3) * 32;
    const int nw = (wid >> 2) * 32;
    const int m0 = blockIdx.y * 128;
    const int n0 = blockIdx.x * 128;

    float acc[2][4][4] = {};
    const int ar = lane >> 2;
    const int ac = (lane & 3) * 2;

    uint32_t va[4];           // raw fp16x2
    uint4 vbh, vbl;
    const int br = tid >> 2;
    const int bc = (tid & 3) * 8;

    auto load_tile = [&](int kt) {
        #pragma unroll
        for (int it = 0; it < 4; ++it) {
            int idx = tid + it * 512;
            int r  = idx >> 4;
            int kp = (idx & 15) * 2;
            int rr = min(m0 + r, N - 1);
            va[it] = __ldg((const uint32_t*)(A + (size_t)rr * K + kt + kp));
        }
        vbh = *(const uint4*)(Whi + (size_t)(n0 + br) * K + kt + bc);
        vbl = *(const uint4*)(Wlo + (size_t)(n0 + br) * K + kt + bc);
    };
    auto store_tile = [&]() {
        #pragma unroll
        for (int it = 0; it < 4; ++it) {
            int idx = tid + it * 512;
            int r  = idx >> 4;
            int kp = (idx & 15) * 2;
            *(uint32_t*)&As[r][kp] = va[it];
        }
        *(uint4*)&BsH[br][bc] = vbh;
        *(uint4*)&BsL[br][bc] = vbl;
    };

    load_tile(0);
    store_tile();
    __syncthreads();

    for (int kt = 0; kt < K; kt += 32) {
        const bool more = (kt + 32) < K;
        if (more) load_tile(kt + 32);

        #pragma unroll
        for (int k16 = 0; k16 < 32; k16 += 16) {
            uint32_t ah[2][4];
            #pragma unroll
            for (int mt = 0; mt < 2; ++mt) {
                int r = mw + mt * 16 + ar;
                ah[mt][0] = *(uint32_t*)&As[r][k16 + ac];
                ah[mt][1] = *(uint32_t*)&As[r + 8][k16 + ac];
                ah[mt][2] = *(uint32_t*)&As[r][k16 + ac + 8];
                ah[mt][3] = *(uint32_t*)&As[r + 8][k16 + ac + 8];
            }
            uint32_t bh[4][2], bl[4][2];
            #pragma unroll
            for (int nt = 0; nt < 4; ++nt) {
                int r = nw + nt * 8 + ar;
                bh[nt][0] = *(uint32_t*)&BsH[r][k16 + ac];
                bh[nt][1] = *(uint32_t*)&BsH[r][k16 + ac + 8];
                bl[nt][0] = *(uint32_t*)&BsL[r][k16 + ac];
                bl[nt][1] = *(uint32_t*)&BsL[r][k16 + ac + 8];
            }
            #pragma unroll
            for (int mt = 0; mt < 2; ++mt)
                #pragma unroll
                for (int nt = 0; nt < 4; ++nt) {
                    mma16816h(acc[mt][nt], ah[mt], bh[nt]);
                    mma16816h(acc[mt][nt], ah[mt], bl[nt]);
                }
        }
        if (more) {
            __syncthreads();
            store_tile();
            __syncthreads();
        }
    }

    #pragma unroll
    for (int mt = 0; mt < 2; ++mt) {
        int r0 = m0 + mw + mt * 16 + ar;
        #pragma unroll
        for (int nt = 0; nt < 4; ++nt) {
            int c = n0 + nw + nt * 8 + ac;
            float2 o0 = make_float2(acc[mt][nt][0], acc[mt][nt][1]);
            float2 o1 = make_float2(acc[mt][nt][2], acc[mt][nt][3]);
            if (BRELU) {
                float b0 = __ldg(&bias[c]), b1 = __ldg(&bias[c + 1]);
                o0.x = fmaxf(o0.x + b0, 0.f); o0.y = fmaxf(o0.y + b1, 0.f);
                o1.x = fmaxf(o1.x + b0, 0.f); o1.y = fmaxf(o1.y + b1, 0.f);
            }
            if (HALF_OUT) {
                __half* Ch = (__half*)Cv;
                if (r0 < N)
                    *(__half2*)(Ch + (size_t)r0 * NOUT + c) = __floats2half2_rn(o0.x, o0.y);
                if (r0 + 8 < N)
                    *(__half2*)(Ch + (size_t)(r0 + 8) * NOUT + c) = __floats2half2_rn(o1.x, o1.y);
            } else {
                float* Cf = (float*)Cv;
                if (r0 < N)     *(float2*)(Cf + (size_t)r0 * NOUT + c) = o0;
                if (r0 + 8 < N) *(float2*)(Cf + (size_t)(r0 + 8) * NOUT + c) = o1;
            }
        }
    }
}

// ---------------------------------------------------------------------------
// fused gather + self-loop (+bias) (+relu): ONE warp per node, all H columns.
// ---------------------------------------------------------------------------
template <int H, bool RELU, bool BIAS, bool HALF_IN, bool HALF_OUT>
__global__ void gather_kernel(const void* __restrict__ hv_in, const float* __restrict__ bias,
                              void* __restrict__ out_v) {
    constexpr int NCH = H / 128;
    int n = (blockIdx.x * blockDim.x + threadIdx.x) >> 5;
    if (n >= NNODES) return;
    int lane = threadIdx.x & 31;
    int col0 = lane * 4;

    auto loadrow = [&](int s, int c) -> float4 {
        if (HALF_IN) {
            const __half* hp = (const __half*)hv_in + (size_t)s * H + col0 + c * 128;
            uint2 raw = __ldg((const uint2*)hp);
            __half2 p0 = *reinterpret_cast<__half2*>(&raw.x);
            __half2 p1 = *reinterpret_cast<__half2*>(&raw.y);
            float2 f0 = __half22float2(p0), f1 = __half22float2(p1);
            return make_float4(f0.x, f0.y, f1.x, f1.y);
        } else {
            return __ldg((const float4*)((const float*)hv_in + (size_t)s * H + col0 + c * 128));
        }
    };

    int p  = __ldg(&g_rowptr[n]);
    int p1 = __ldg(&g_rowptr[n + 1]);

    float4 acc[NCH];
    #pragma unroll
    for (int c = 0; c < NCH; ++c) acc[c] = make_float4(0.f, 0.f, 0.f, 0.f);

    for (; p + 3 < p1; p += 4) {
        int2 e[4];
        e[0] = __ldg(&g_epack[p]);
        e[1] = __ldg(&g_epack[p + 1]);
        e[2] = __ldg(&g_epack[p + 2]);
        e[3] = __ldg(&g_epack[p + 3]);
        float4 v[4][NCH];
        #pragma unroll
        for (int j = 0; j < 4; ++j)
            #pragma unroll
            for (int c = 0; c < NCH; ++c) v[j][c] = loadrow(e[j].x, c);
        #pragma unroll
        for (int j = 0; j < 4; ++j) {
            float cf = __int_as_float(e[j].y);
            #pragma unroll
            for (int c = 0; c < NCH; ++c) {
                acc[c].x += cf * v[j][c].x;
                acc[c].y += cf * v[j][c].y;
                acc[c].z += cf * v[j][c].z;
                acc[c].w += cf * v[j][c].w;
            }
        }
    }
    for (; p < p1; ++p) {
        int2 e = __ldg(&g_epack[p]);
        float cf = __int_as_float(e.y);
        #pragma unroll
        for (int c = 0; c < NCH; ++c) {
            float4 v = loadrow(e.x, c);
            acc[c].x += cf * v.x; acc[c].y += cf * v.y;
            acc[c].z += cf * v.z; acc[c].w += cf * v.w;
        }
    }

    float dis = g_dis[n];
    float sc = dis * dis;
    #pragma unroll
    for (int c = 0; c < NCH; ++c) {
        float4 hv = loadrow(n, c);
        float4 r;
        r.x = acc[c].x + sc * hv.x;
        r.y = acc[c].y + sc * hv.y;
        r.z = acc[c].z + sc * hv.z;
        r.w = acc[c].w + sc * hv.w;
        if (BIAS) {
            float4 bv = __ldg((const float4*)(bias + col0 + c * 128));
            r.x += bv.x; r.y += bv.y; r.z += bv.z; r.w += bv.w;
        }
        if (RELU) {
            r.x = fmaxf(r.x, 0.f); r.y = fmaxf(r.y, 0.f);
            r.z = fmaxf(r.z, 0.f); r.w = fmaxf(r.w, 0.f);
        }
        if (HALF_OUT) {
            __half* op = (__half*)out_v + (size_t)n * H + col0 + c * 128;
            __half2 p0 = __floats2half2_rn(r.x, r.y);
            __half2 p1 = __floats2half2_rn(r.z, r.w);
            uint2 o;
            o.x = *reinterpret_cast<uint32_t*>(&p0);
            o.y = *reinterpret_cast<uint32_t*>(&p1);
            *(uint2*)op = o;
        } else {
            *(float4*)((float*)out_v + (size_t)n * H + col0 + c * 128) = r;
        }
    }
}

// ---------------------------------------------------------------------------
// pooling + fused finish
// ---------------------------------------------------------------------------
__global__ void pool_kernel(const float* __restrict__ ne, const int* __restrict__ batch,
                            float* __restrict__ gsum, int N) {
    int c  = threadIdx.x;
    int n0 = blockIdx.x * 256;
    int n1 = min(n0 + 256, N);
    float acc = 0.0f;
    int cur = -1;
    for (int n = n0; n < n1; ++n) {
        int g = __ldg(&batch[n]);
        if (g != cur) {
            if (cur >= 0) atomicAdd(&gsum[cur * DOUTC + c], acc);
            acc = 0.0f;
            cur = g;
        }
        acc += ne[(size_t)n * DOUTC + c];
    }
    if (cur >= 0) atomicAdd(&gsum[cur * DOUTC + c], acc);
}

__global__ void finish_kernel(const int* __restrict__ batch, float* __restrict__ gsum,
                              const float* __restrict__ Wc, const float* __restrict__ bc,
                              float* __restrict__ logit) {
    int g = blockIdx.x;
    __shared__ float cnt_s;
    __shared__ float row[DOUTC];
    if (threadIdx.x == 0) {
        int lo = 0, hi = NNODES;
        while (lo < hi) { int mid = (lo + hi) >> 1; if (__ldg(&batch[mid]) < g) lo = mid + 1; else hi = mid; }
        int lb = lo;
        lo = 0; hi = NNODES;
        while (lo < hi) { int mid = (lo + hi) >> 1; if (__ldg(&batch[mid]) <= g) lo = mid + 1; else hi = mid; }
        cnt_s = fmaxf((float)(lo - lb), 1.0f);
    }
    __syncthreads();
    int c = threadIdx.x;
    float v = gsum[g * DOUTC + c] / cnt_s;
    gsum[g * DOUTC + c] = v;
    row[c] = v;
    __syncthreads();
    if (c < 2) {
        float s = __ldg(&bc[c]);
        #pragma unroll 8
        for (int k = 0; k < DOUTC; ++k) s += row[k] * __ldg(&Wc[k * 2 + c]);
        logit[g * 2 + c] = s;
    }
}

// ---------------------------------------------------------------------------
// launch
// ---------------------------------------------------------------------------
extern "C" void kernel_launch(void* const* d_in, const int* in_sizes, int n_in,
                              void* d_out, int out_size) {
    const float* x     = (const float*)d_in[0];
    const int*   ei    = (const int*)d_in[1];
    const int*   batch = (const int*)d_in[2];
    const float* W_in  = (const float*)d_in[3];
    const float* b_in  = (const float*)d_in[4];
    const float* W_mid = (const float*)d_in[5];
    const float* b_mid = (const float*)d_in[6];
    const float* W_out = (const float*)d_in[7];
    const float* b_out = (const float*)d_in[8];
    const float* W_cls = (const float*)d_in[9];
    const float* b_cls = (const float*)d_in[10];

    const int* src = ei;
    const int* dst = ei + NEDGES;

    float *bufA, *bufB;
    __half *w1h, *w1l, *w2h, *w2l, *w3h, *w3l;
    cudaGetSymbolAddress((void**)&bufA, g_bufA);
    cudaGetSymbolAddress((void**)&bufB, g_bufB);
    cudaGetSymbolAddress((void**)&w1h, g_w1_hi);
    cudaGetSymbolAddress((void**)&w1l, g_w1_lo);
    cudaGetSymbolAddress((void**)&w2h, g_w2_hi);
    cudaGetSymbolAddress((void**)&w2l, g_w2_lo);
    cudaGetSymbolAddress((void**)&w3h, g_w3_hi);
    cudaGetSymbolAddress((void**)&w3l, g_w3_lo);

    float* node   = (float*)d_out;
    float* gsum   = node + (size_t)NNODES * DOUTC;
    float* logit  = gsum + NGRAPH * DOUTC;

    const int T = 256;
    const int GW = (NNODES * 32 + T - 1) / T;   // 1 warp per node

    // ----- prep (weights + zero counters), x->fp16, CSR build -----
    prep_kernel<<<680, T>>>(W_in, W_mid, W_out);
    tohalf_kernel<<<640, T>>>((const float4*)x, (uint2*)bufB, NNODES * DIN / 4);
    hist_kernel<<<(NEDGES + T - 1) / T, T>>>(dst, NEDGES);
    scan1_kernel<<<SCAN_NB, SCAN_B>>>((float4*)gsum);
    scan23_kernel<<<SCAN_NB, SCAN_B>>>();
    csrfill_kernel<<<(NEDGES + T - 1) / T, T>>>(src, dst, NEDGES);

    const int GB = (NNODES + 127) / 128;   // 313

    // ----- layer 1: propagate(x fp16)->fp16, fp16 GEMM + bias + relu -> fp16 -----
    gather_kernel<DIN, false, false, true, true><<<GW, T>>>(bufB, nullptr, bufA);
    mma_gemm_kernel<DIN, true, true><<<dim3(2, GB), 512>>>((const __half*)bufA, w1h, w1l,
                                                           b_in, bufB, NNODES, DH);

    // ----- layer 2: fp16 GEMM -> fp16, propagate + bias + relu -> fp16 -----
    mma_gemm_kernel<DH, false, true><<<dim3(2, GB), 512>>>((const __half*)bufB, w2h, w2l,
                                                           nullptr, bufA, NNODES, DH);
    gather_kernel<DH, true, true, true, true><<<GW, T>>>(bufA, b_mid, bufB);

    // ----- layer 3: fp16 GEMM -> fp16, propagate + bias -> fp32 node -----
    mma_gemm_kernel<DH, false, true><<<dim3(1, GB), 512>>>((const __half*)bufB, w3h, w3l,
                                                           nullptr, bufA, NNODES, DOUTC);
    gather_kernel<DOUTC, false, true, true, false><<<GW, T>>>(bufA, b_out, node);

    // ----- mean pool + classifier -----
    pool_kernel<<<(NNODES + 255) / 256, 128>>>(node, batch, gsum, NNODES);
    finish_kernel<<<NGRAPH, DOUTC>>>(batch, gsum, W_cls, b_cls, logit);
}

// round 15
// speedup vs baseline: 1.7355x; 1.1297x over previous
#include <cuda_runtime.h>
#include <cuda_bf16.h>
#include <cuda_fp16.h>
#include <stdint.h>

#define NNODES 40000
#define NEDGES 640000
#define NGRAPH 64
#define DIN    128
#define DH     256
#define DOUTC  128

#define SCAN_B 256
#define SCAN_NB ((NNODES + SCAN_B - 1) / SCAN_B)   // 157

// ---- scratch (no allocations allowed) ----
__device__ float g_bufA[NNODES * DH];
__device__ float g_bufB[NNODES * DH];
__device__ float g_dis[NNODES];
// CSR scratch
__device__ int   g_cnti[NNODES];
__device__ int   g_rowptr[NNODES + 1];
__device__ int   g_cursor[NNODES];
__device__ int2  g_epack[NEDGES];          // {src, coef-as-int}
__device__ int   g_bsum[SCAN_NB];
// weights transposed to [NOUT, K] row-major, fp16
__device__ __half g_w1[DH * DIN];
__device__ __half g_w2[DH * DH];
__device__ __half g_w3[DOUTC * DH];

// ---------------------------------------------------------------------------
// prep: weight transpose + fp16 + zero degree counters
// ---------------------------------------------------------------------------
__device__ __forceinline__ void wprep(const float* __restrict__ W,
                                      __half* __restrict__ wh,
                                      int K, int NOUT, int idx) {
    int k = idx / NOUT, n = idx - k * NOUT;
    wh[(size_t)n * K + k] = __float2half_rn(W[idx]);
}

__global__ void prep_kernel(const float* __restrict__ W1, const float* __restrict__ W2,
                            const float* __restrict__ W3) {
    constexpr int E1 = DIN * DH;
    constexpr int E2 = E1 + DH * DH;
    constexpr int E3 = E2 + DH * DOUTC;
    constexpr int TOT = E3 + NNODES;
    int i = blockIdx.x * blockDim.x + threadIdx.x;
    for (; i < TOT; i += gridDim.x * blockDim.x) {
        if (i < E1)       wprep(W1, g_w1, DIN, DH, i);
        else if (i < E2)  wprep(W2, g_w2, DH, DH, i - E1);
        else if (i < E3)  wprep(W3, g_w3, DH, DOUTC, i - E2);
        else              g_cnti[i - E3] = 0;
    }
}

// convert fp32 -> fp16, vectorized
__global__ void tohalf_kernel(const float4* __restrict__ in, uint2* __restrict__ out, int n4) {
    int i = blockIdx.x * blockDim.x + threadIdx.x;
    for (; i < n4; i += gridDim.x * blockDim.x) {
        float4 v = in[i];
        __half2 p0 = __floats2half2_rn(v.x, v.y);
        __half2 p1 = __floats2half2_rn(v.z, v.w);
        uint2 o;
        o.x = *reinterpret_cast<uint32_t*>(&p0);
        o.y = *reinterpret_cast<uint32_t*>(&p1);
        out[i] = o;
    }
}

__global__ void hist_kernel(const int* __restrict__ dst, int E) {
    int e = blockIdx.x * blockDim.x + threadIdx.x;
    if (e < E) atomicAdd(&g_cnti[dst[e]], 1);
}

// ---------------------------------------------------------------------------
// scan phase 1: block sums (+ dis + gsum zeroing piggybacked)
// ---------------------------------------------------------------------------
__global__ void scan1_kernel(float4* __restrict__ gsum4) {
    __shared__ int s[SCAN_B];
    int i = blockIdx.x * SCAN_B + threadIdx.x;
    int v = (i < NNODES) ? g_cnti[i] : 0;
    if (i < NNODES) g_dis[i] = rsqrtf((float)v + 1.0f);
    if (i < NGRAPH * DOUTC / 4) gsum4[i] = make_float4(0.f, 0.f, 0.f, 0.f);
    s[threadIdx.x] = v;
    __syncthreads();
    for (int off = SCAN_B / 2; off > 0; off >>= 1) {
        if (threadIdx.x < off) s[threadIdx.x] += s[threadIdx.x + off];
        __syncthreads();
    }
    if (threadIdx.x == 0) g_bsum[blockIdx.x] = s[0];
}

// scan phase 2+3 fused
__global__ void scan23_kernel() {
    __shared__ int s[SCAN_B];
    __shared__ int bpre_s;
    int t = threadIdx.x;
    int i = blockIdx.x * SCAN_B + t;

    int v = (t < SCAN_NB && t < blockIdx.x) ? g_bsum[t] : 0;
    s[t] = v;
    __syncthreads();
    for (int off = SCAN_B / 2; off > 0; off >>= 1) {
        if (t < off) s[t] += s[t + off];
        __syncthreads();
    }
    if (t == 0) bpre_s = s[0];
    __syncthreads();
    int bpre = bpre_s;
    __syncthreads();

    int v0 = (i < NNODES) ? g_cnti[i] : 0;
    s[t] = v0;
    __syncthreads();
    for (int off = 1; off < SCAN_B; off <<= 1) {
        int u = (t >= off) ? s[t - off] : 0;
        __syncthreads();
        s[t] += u;
        __syncthreads();
    }
    if (i < NNODES) {
        int ex = bpre + s[t] - v0;
        g_rowptr[i] = ex;
        g_cursor[i] = ex;
    }
    if (blockIdx.x == 0 && t == 0) g_rowptr[NNODES] = NEDGES;
}

__global__ void csrfill_kernel(const int* __restrict__ src, const int* __restrict__ dst,
                               int E) {
    int e = blockIdx.x * blockDim.x + threadIdx.x;
    if (e >= E) return;
    int s = src[e], d = dst[e];
    int p = atomicAdd(&g_cursor[d], 1);
    g_epack[p] = make_int2(s, __float_as_int(g_dis[s] * g_dis[d]));
}

// ---------------------------------------------------------------------------
// mma helper: fp16 inputs, fp32 accum
// ---------------------------------------------------------------------------
__device__ __forceinline__ void mma16816h(float* c, const uint32_t* a, const uint32_t* b) {
    asm volatile(
        "mma.sync.aligned.m16n8k16.row.col.f32.f16.f16.f32 "
        "{%0,%1,%2,%3}, {%4,%5,%6,%7}, {%8,%9}, {%0,%1,%2,%3};"
        : "+f"(c[0]), "+f"(c[1]), "+f"(c[2]), "+f"(c[3])
        : "r"(a[0]), "r"(a[1]), "r"(a[2]), "r"(a[3]), "r"(b[0]), "r"(b[1]));
}

// ---------------------------------------------------------------------------
// fp16 GEMM (single MMA per tile): C = A(fp16) @ W(fp16)
// 128x128 tile, pipelined. HALF_OUT: fp16 C store, else fp32.
// ---------------------------------------------------------------------------
template <int K, bool BRELU, bool HALF_OUT>
__global__ void __launch_bounds__(512)
mma_gemm_kernel(const __half* __restrict__ A, const __half* __restrict__ W,
                const float* __restrict__ bias, void* __restrict__ Cv, int N, int NOUT) {
    __shared__ __half As[128][40];
    __shared__ __half Bs[128][40];

    const int tid = threadIdx.x;
    const int wid = tid >> 5, lane = tid & 31;
    const int mw = (wid & 3) * 32;
    const int nw = (wid >> 2) * 32;
    const int m0 = blockIdx.y * 128;
    const int n0 = blockIdx.x * 128;

    float acc[2][4][4] = {};
    const int ar = lane >> 2;
    const int ac = (lane & 3) * 2;

    uint32_t va[4];           // raw fp16x2
    uint4 vb;
    const int br = tid >> 2;
    const int bc = (tid & 3) * 8;

    auto load_tile = [&](int kt) {
        #pragma unroll
        for (int it = 0; it < 4; ++it) {
            int idx = tid + it * 512;
            int r  = idx >> 4;
            int kp = (idx & 15) * 2;
            int rr = min(m0 + r, N - 1);
            va[it] = __ldg((const uint32_t*)(A + (size_t)rr * K + kt + kp));
        }
        vb = *(const uint4*)(W + (size_t)(n0 + br) * K + kt + bc);
    };
    auto store_tile = [&]() {
        #pragma unroll
        for (int it = 0; it < 4; ++it) {
            int idx = tid + it * 512;
            int r  = idx >> 4;
            int kp = (idx & 15) * 2;
            *(uint32_t*)&As[r][kp] = va[it];
        }
        *(uint4*)&Bs[br][bc] = vb;
    };

    load_tile(0);
    store_tile();
    __syncthreads();

    for (int kt = 0; kt < K; kt += 32) {
        const bool more = (kt + 32) < K;
        if (more) load_tile(kt + 32);

        #pragma unroll
        for (int k16 = 0; k16 < 32; k16 += 16) {
            uint32_t ah[2][4];
            #pragma unroll
            for (int mt = 0; mt < 2; ++mt) {
                int r = mw + mt * 16 + ar;
                ah[mt][0] = *(uint32_t*)&As[r][k16 + ac];
                ah[mt][1] = *(uint32_t*)&As[r + 8][k16 + ac];
                ah[mt][2] = *(uint32_t*)&As[r][k16 + ac + 8];
                ah[mt][3] = *(uint32_t*)&As[r + 8][k16 + ac + 8];
            }
            uint32_t bb[4][2];
            #pragma unroll
            for (int nt = 0; nt < 4; ++nt) {
                int r = nw + nt * 8 + ar;
                bb[nt][0] = *(uint32_t*)&Bs[r][k16 + ac];
                bb[nt][1] = *(uint32_t*)&Bs[r][k16 + ac + 8];
            }
            #pragma unroll
            for (int mt = 0; mt < 2; ++mt)
                #pragma unroll
                for (int nt = 0; nt < 4; ++nt)
                    mma16816h(acc[mt][nt], ah[mt], bb[nt]);
        }
        if (more) {
            __syncthreads();
            store_tile();
            __syncthreads();
        }
    }

    #pragma unroll
    for (int mt = 0; mt < 2; ++mt) {
        int r0 = m0 + mw + mt * 16 + ar;
        #pragma unroll
        for (int nt = 0; nt < 4; ++nt) {
            int c = n0 + nw + nt * 8 + ac;
            float2 o0 = make_float2(acc[mt][nt][0], acc[mt][nt][1]);
            float2 o1 = make_float2(acc[mt][nt][2], acc[mt][nt][3]);
            if (BRELU) {
                float b0 = __ldg(&bias[c]), b1 = __ldg(&bias[c + 1]);
                o0.x = fmaxf(o0.x + b0, 0.f); o0.y = fmaxf(o0.y + b1, 0.f);
                o1.x = fmaxf(o1.x + b0, 0.f); o1.y = fmaxf(o1.y + b1, 0.f);
            }
            if (HALF_OUT) {
                __half* Ch = (__half*)Cv;
                if (r0 < N)
                    *(__half2*)(Ch + (size_t)r0 * NOUT + c) = __floats2half2_rn(o0.x, o0.y);
                if (r0 + 8 < N)
                    *(__half2*)(Ch + (size_t)(r0 + 8) * NOUT + c) = __floats2half2_rn(o1.x, o1.y);
            } else {
                float* Cf = (float*)Cv;
                if (r0 < N)     *(float2*)(Cf + (size_t)r0 * NOUT + c) = o0;
                if (r0 + 8 < N) *(float2*)(Cf + (size_t)(r0 + 8) * NOUT + c) = o1;
            }
        }
    }
}

// ---------------------------------------------------------------------------
// fused gather + self-loop (+bias) (+relu): ONE warp per node, all H columns.
// ---------------------------------------------------------------------------
template <int H, bool RELU, bool BIAS, bool HALF_IN, bool HALF_OUT>
__global__ void gather_kernel(const void* __restrict__ hv_in, const float* __restrict__ bias,
                              void* __restrict__ out_v) {
    constexpr int NCH = H / 128;
    int n = (blockIdx.x * blockDim.x + threadIdx.x) >> 5;
    if (n >= NNODES) return;
    int lane = threadIdx.x & 31;
    int col0 = lane * 4;

    auto loadrow = [&](int s, int c) -> float4 {
        if (HALF_IN) {
            const __half* hp = (const __half*)hv_in + (size_t)s * H + col0 + c * 128;
            uint2 raw = __ldg((const uint2*)hp);
            __half2 p0 = *reinterpret_cast<__half2*>(&raw.x);
            __half2 p1 = *reinterpret_cast<__half2*>(&raw.y);
            float2 f0 = __half22float2(p0), f1 = __half22float2(p1);
            return make_float4(f0.x, f0.y, f1.x, f1.y);
        } else {
            return __ldg((const float4*)((const float*)hv_in + (size_t)s * H + col0 + c * 128));
        }
    };

    int p  = __ldg(&g_rowptr[n]);
    int p1 = __ldg(&g_rowptr[n + 1]);

    float4 acc[NCH];
    #pragma unroll
    for (int c = 0; c < NCH; ++c) acc[c] = make_float4(0.f, 0.f, 0.f, 0.f);

    for (; p + 3 < p1; p += 4) {
        int2 e[4];
        e[0] = __ldg(&g_epack[p]);
        e[1] = __ldg(&g_epack[p + 1]);
        e[2] = __ldg(&g_epack[p + 2]);
        e[3] = __ldg(&g_epack[p + 3]);
        float4 v[4][NCH];
        #pragma unroll
        for (int j = 0; j < 4; ++j)
            #pragma unroll
            for (int c = 0; c < NCH; ++c) v[j][c] = loadrow(e[j].x, c);
        #pragma unroll
        for (int j = 0; j < 4; ++j) {
            float cf = __int_as_float(e[j].y);
            #pragma unroll
            for (int c = 0; c < NCH; ++c) {
                acc[c].x += cf * v[j][c].x;
                acc[c].y += cf * v[j][c].y;
                acc[c].z += cf * v[j][c].z;
                acc[c].w += cf * v[j][c].w;
            }
        }
    }
    for (; p < p1; ++p) {
        int2 e = __ldg(&g_epack[p]);
        float cf = __int_as_float(e.y);
        #pragma unroll
        for (int c = 0; c < NCH; ++c) {
            float4 v = loadrow(e.x, c);
            acc[c].x += cf * v.x; acc[c].y += cf * v.y;
            acc[c].z += cf * v.z; acc[c].w += cf * v.w;
        }
    }

    float dis = g_dis[n];
    float sc = dis * dis;
    #pragma unroll
    for (int c = 0; c < NCH; ++c) {
        float4 hv = loadrow(n, c);
        float4 r;
        r.x = acc[c].x + sc * hv.x;
        r.y = acc[c].y + sc * hv.y;
        r.z = acc[c].z + sc * hv.z;
        r.w = acc[c].w + sc * hv.w;
        if (BIAS) {
            float4 bv = __ldg((const float4*)(bias + col0 + c * 128));
            r.x += bv.x; r.y += bv.y; r.z += bv.z; r.w += bv.w;
        }
        if (RELU) {
            r.x = fmaxf(r.x, 0.f); r.y = fmaxf(r.y, 0.f);
            r.z = fmaxf(r.z, 0.f); r.w = fmaxf(r.w, 0.f);
        }
        if (HALF_OUT) {
            __half* op = (__half*)out_v + (size_t)n * H + col0 + c * 128;
            __half2 p0 = __floats2half2_rn(r.x, r.y);
            __half2 p1 = __floats2half2_rn(r.z, r.w);
            uint2 o;
            o.x = *reinterpret_cast<uint32_t*>(&p0);
            o.y = *reinterpret_cast<uint32_t*>(&p1);
            *(uint2*)op = o;
        } else {
            *(float4*)((float*)out_v + (size_t)n * H + col0 + c * 128) = r;
        }
    }
}

// ---------------------------------------------------------------------------
// pooling + fused finish
// ---------------------------------------------------------------------------
__global__ void pool_kernel(const float* __restrict__ ne, const int* __restrict__ batch,
                            float* __restrict__ gsum, int N) {
    int c  = threadIdx.x;
    int n0 = blockIdx.x * 256;
    int n1 = min(n0 + 256, N);
    float acc = 0.0f;
    int cur = -1;
    for (int n = n0; n < n1; ++n) {
        int g = __ldg(&batch[n]);
        if (g != cur) {
            if (cur >= 0) atomicAdd(&gsum[cur * DOUTC + c], acc);
            acc = 0.0f;
            cur = g;
        }
        acc += ne[(size_t)n * DOUTC + c];
    }
    if (cur >= 0) atomicAdd(&gsum[cur * DOUTC + c], acc);
}

__global__ void finish_kernel(const int* __restrict__ batch, float* __restrict__ gsum,
                              const float* __restrict__ Wc, const float* __restrict__ bc,
                              float* __restrict__ logit) {
    int g = blockIdx.x;
    __shared__ float cnt_s;
    __shared__ float row[DOUTC];
    if (threadIdx.x == 0) {
        int lo = 0, hi = NNODES;
        while (lo < hi) { int mid = (lo + hi) >> 1; if (__ldg(&batch[mid]) < g) lo = mid + 1; else hi = mid; }
        int lb = lo;
        lo = 0; hi = NNODES;
        while (lo < hi) { int mid = (lo + hi) >> 1; if (__ldg(&batch[mid]) <= g) lo = mid + 1; else hi = mid; }
        cnt_s = fmaxf((float)(lo - lb), 1.0f);
    }
    __syncthreads();
    int c = threadIdx.x;
    float v = gsum[g * DOUTC + c] / cnt_s;
    gsum[g * DOUTC + c] = v;
    row[c] = v;
    __syncthreads();
    if (c < 2) {
        float s = __ldg(&bc[c]);
        #pragma unroll 8
        for (int k = 0; k < DOUTC; ++k) s += row[k] * __ldg(&Wc[k * 2 + c]);
        logit[g * 2 + c] = s;
    }
}

// ---------------------------------------------------------------------------
// launch
// ---------------------------------------------------------------------------
extern "C" void kernel_launch(void* const* d_in, const int* in_sizes, int n_in,
                              void* d_out, int out_size) {
    const float* x     = (const float*)d_in[0];
    const int*   ei    = (const int*)d_in[1];
    const int*   batch = (const int*)d_in[2];
    const float* W_in  = (const float*)d_in[3];
    const float* b_in  = (const float*)d_in[4];
    const float* W_mid = (const float*)d_in[5];
    const float* b_mid = (const float*)d_in[6];
    const float* W_out = (const float*)d_in[7];
    const float* b_out = (const float*)d_in[8];
    const float* W_cls = (const float*)d_in[9];
    const float* b_cls = (const float*)d_in[10];

    const int* src = ei;
    const int* dst = ei + NEDGES;

    float *bufA, *bufB;
    __half *w1, *w2, *w3;
    cudaGetSymbolAddress((void**)&bufA, g_bufA);
    cudaGetSymbolAddress((void**)&bufB, g_bufB);
    cudaGetSymbolAddress((void**)&w1, g_w1);
    cudaGetSymbolAddress((void**)&w2, g_w2);
    cudaGetSymbolAddress((void**)&w3, g_w3);

    float* node   = (float*)d_out;
    float* gsum   = node + (size_t)NNODES * DOUTC;
    float* logit  = gsum + NGRAPH * DOUTC;

    const int T = 256;
    const int GW = (NNODES * 32 + T - 1) / T;   // 1 warp per node

    // ----- prep (weights + zero counters), x->fp16, CSR build -----
    prep_kernel<<<680, T>>>(W_in, W_mid, W_out);
    tohalf_kernel<<<640, T>>>((const float4*)x, (uint2*)bufB, NNODES * DIN / 4);
    hist_kernel<<<(NEDGES + T - 1) / T, T>>>(dst, NEDGES);
    scan1_kernel<<<SCAN_NB, SCAN_B>>>((float4*)gsum);
    scan23_kernel<<<SCAN_NB, SCAN_B>>>();
    csrfill_kernel<<<(NEDGES + T - 1) / T, T>>>(src, dst, NEDGES);

    const int GB = (NNODES + 127) / 128;   // 313

    // ----- layer 1: propagate(x fp16)->fp16, fp16 GEMM + bias + relu -> fp16 -----
    gather_kernel<DIN, false, false, true, true><<<GW, T>>>(bufB, nullptr, bufA);
    mma_gemm_kernel<DIN, true, true><<<dim3(2, GB), 512>>>((const __half*)bufA, w1,
                                                           b_in, bufB, NNODES, DH);

    // ----- layer 2: fp16 GEMM -> fp16, propagate + bias + relu -> fp16 -----
    mma_gemm_kernel<DH, false, true><<<dim3(2, GB), 512>>>((const __half*)bufB, w2,
                                                           nullptr, bufA, NNODES, DH);
    gather_kernel<DH, true, true, true, true><<<GW, T>>>(bufA, b_mid, bufB);

    // ----- layer 3: fp16 GEMM -> fp16, propagate + bias -> fp32 node -----
    mma_gemm_kernel<DH, false, true><<<dim3(1, GB), 512>>>((const __half*)bufB, w3,
                                                           nullptr, bufA, NNODES, DOUTC);
    gather_kernel<DOUTC, false, true, true, false><<<GW, T>>>(bufA, b_out, node);

    // ----- mean pool + classifier -----
    pool_kernel<<<(NNODES + 255) / 256, 128>>>(node, batch, gsum, NNODES);
    finish_kernel<<<NGRAPH, DOUTC>>>(batch, gsum, W_cls, b_cls, logit);
}

// round 16
// speedup vs baseline: 1.7524x; 1.0097x over previous
#include <cuda_runtime.h>
#include <cuda_bf16.h>
#include <cuda_fp16.h>
#include <stdint.h>

#define NNODES 40000
#define NEDGES 640000
#define NGRAPH 64
#define DIN    128
#define DH     256
#define DOUTC  128

#define SCAN_B 256
#define SCAN_NB ((NNODES + SCAN_B - 1) / SCAN_B)   // 157

// ---- scratch (no allocations allowed) ----
__device__ float g_bufA[NNODES * DH];
__device__ float g_bufB[NNODES * DH];
__device__ float g_dis[NNODES];
// CSR scratch
__device__ int   g_cnti[NNODES];
__device__ int   g_rowptr[NNODES + 1];
__device__ int   g_cursor[NNODES];
__device__ int2  g_epack[NEDGES];          // {src, coef-as-int}
__device__ int   g_bsum[SCAN_NB];
// weights transposed to [NOUT, K] row-major, fp16
__device__ __half g_w1[DH * DIN];
__device__ __half g_w2[DH * DH];
__device__ __half g_w3[DOUTC * DH];

// ---------------------------------------------------------------------------
// prep: weight transpose + fp16 + zero degree counters
// ---------------------------------------------------------------------------
__device__ __forceinline__ void wprep(const float* __restrict__ W,
                                      __half* __restrict__ wh,
                                      int K, int NOUT, int idx) {
    int k = idx / NOUT, n = idx - k * NOUT;
    wh[(size_t)n * K + k] = __float2half_rn(W[idx]);
}

__global__ void prep_kernel(const float* __restrict__ W1, const float* __restrict__ W2,
                            const float* __restrict__ W3) {
    constexpr int E1 = DIN * DH;
    constexpr int E2 = E1 + DH * DH;
    constexpr int E3 = E2 + DH * DOUTC;
    constexpr int TOT = E3 + NNODES;
    int i = blockIdx.x * blockDim.x + threadIdx.x;
    for (; i < TOT; i += gridDim.x * blockDim.x) {
        if (i < E1)       wprep(W1, g_w1, DIN, DH, i);
        else if (i < E2)  wprep(W2, g_w2, DH, DH, i - E1);
        else if (i < E3)  wprep(W3, g_w3, DH, DOUTC, i - E2);
        else              g_cnti[i - E3] = 0;
    }
}

// convert fp32 -> fp16, vectorized
__global__ void tohalf_kernel(const float4* __restrict__ in, uint2* __restrict__ out, int n4) {
    int i = blockIdx.x * blockDim.x + threadIdx.x;
    for (; i < n4; i += gridDim.x * blockDim.x) {
        float4 v = in[i];
        __half2 p0 = __floats2half2_rn(v.x, v.y);
        __half2 p1 = __floats2half2_rn(v.z, v.w);
        uint2 o;
        o.x = *reinterpret_cast<uint32_t*>(&p0);
        o.y = *reinterpret_cast<uint32_t*>(&p1);
        out[i] = o;
    }
}

__global__ void hist_kernel(const int* __restrict__ dst, int E) {
    int e = blockIdx.x * blockDim.x + threadIdx.x;
    if (e < E) atomicAdd(&g_cnti[dst[e]], 1);
}

// ---------------------------------------------------------------------------
// scan phase 1: block sums (+ dis + gsum zeroing piggybacked)
// ---------------------------------------------------------------------------
__global__ void scan1_kernel(float4* __restrict__ gsum4) {
    __shared__ int s[SCAN_B];
    int i = blockIdx.x * SCAN_B + threadIdx.x;
    int v = (i < NNODES) ? g_cnti[i] : 0;
    if (i < NNODES) g_dis[i] = rsqrtf((float)v + 1.0f);
    if (i < NGRAPH * DOUTC / 4) gsum4[i] = make_float4(0.f, 0.f, 0.f, 0.f);
    s[threadIdx.x] = v;
    __syncthreads();
    for (int off = SCAN_B / 2; off > 0; off >>= 1) {
        if (threadIdx.x < off) s[threadIdx.x] += s[threadIdx.x + off];
        __syncthreads();
    }
    if (threadIdx.x == 0) g_bsum[blockIdx.x] = s[0];
}

// scan phase 2+3 fused
__global__ void scan23_kernel() {
    __shared__ int s[SCAN_B];
    __shared__ int bpre_s;
    int t = threadIdx.x;
    int i = blockIdx.x * SCAN_B + t;

    int v = (t < SCAN_NB && t < blockIdx.x) ? g_bsum[t] : 0;
    s[t] = v;
    __syncthreads();
    for (int off = SCAN_B / 2; off > 0; off >>= 1) {
        if (t < off) s[t] += s[t + off];
        __syncthreads();
    }
    if (t == 0) bpre_s = s[0];
    __syncthreads();
    int bpre = bpre_s;
    __syncthreads();

    int v0 = (i < NNODES) ? g_cnti[i] : 0;
    s[t] = v0;
    __syncthreads();
    for (int off = 1; off < SCAN_B; off <<= 1) {
        int u = (t >= off) ? s[t - off] : 0;
        __syncthreads();
        s[t] += u;
        __syncthreads();
    }
    if (i < NNODES) {
        int ex = bpre + s[t] - v0;
        g_rowptr[i] = ex;
        g_cursor[i] = ex;
    }
    if (blockIdx.x == 0 && t == 0) g_rowptr[NNODES] = NEDGES;
}

__global__ void csrfill_kernel(const int* __restrict__ src, const int* __restrict__ dst,
                               int E) {
    int e = blockIdx.x * blockDim.x + threadIdx.x;
    if (e >= E) return;
    int s = src[e], d = dst[e];
    int p = atomicAdd(&g_cursor[d], 1);
    g_epack[p] = make_int2(s, __float_as_int(g_dis[s] * g_dis[d]));
}

// ---------------------------------------------------------------------------
// mma helper: fp16 inputs, fp32 accum
// ---------------------------------------------------------------------------
__device__ __forceinline__ void mma16816h(float* c, const uint32_t* a, const uint32_t* b) {
    asm volatile(
        "mma.sync.aligned.m16n8k16.row.col.f32.f16.f16.f32 "
        "{%0,%1,%2,%3}, {%4,%5,%6,%7}, {%8,%9}, {%0,%1,%2,%3};"
        : "+f"(c[0]), "+f"(c[1]), "+f"(c[2]), "+f"(c[3])
        : "r"(a[0]), "r"(a[1]), "r"(a[2]), "r"(a[3]), "r"(b[0]), "r"(b[1]));
}

// ---------------------------------------------------------------------------
// fp16 GEMM (single MMA per tile), double-buffered SMEM (1 sync/iter)
// 128x128 tile. HALF_OUT: fp16 C store, else fp32.
// ---------------------------------------------------------------------------
template <int K, bool BRELU, bool HALF_OUT>
__global__ void __launch_bounds__(512)
mma_gemm_kernel(const __half* __restrict__ A, const __half* __restrict__ W,
                const float* __restrict__ bias, void* __restrict__ Cv, int N, int NOUT) {
    __shared__ __half As[2][128][40];
    __shared__ __half Bs[2][128][40];

    const int tid = threadIdx.x;
    const int wid = tid >> 5, lane = tid & 31;
    const int mw = (wid & 3) * 32;
    const int nw = (wid >> 2) * 32;
    const int m0 = blockIdx.y * 128;
    const int n0 = blockIdx.x * 128;

    float acc[2][4][4] = {};
    const int ar = lane >> 2;
    const int ac = (lane & 3) * 2;

    uint32_t va[4];           // raw fp16x2
    uint4 vb;
    const int br = tid >> 2;
    const int bc = (tid & 3) * 8;

    auto load_tile = [&](int kt) {
        #pragma unroll
        for (int it = 0; it < 4; ++it) {
            int idx = tid + it * 512;
            int r  = idx >> 4;
            int kp = (idx & 15) * 2;
            int rr = min(m0 + r, N - 1);
            va[it] = __ldg((const uint32_t*)(A + (size_t)rr * K + kt + kp));
        }
        vb = *(const uint4*)(W + (size_t)(n0 + br) * K + kt + bc);
    };
    auto store_tile = [&](int st) {
        #pragma unroll
        for (int it = 0; it < 4; ++it) {
            int idx = tid + it * 512;
            int r  = idx >> 4;
            int kp = (idx & 15) * 2;
            *(uint32_t*)&As[st][r][kp] = va[it];
        }
        *(uint4*)&Bs[st][br][bc] = vb;
    };

    load_tile(0);
    store_tile(0);
    __syncthreads();

    int st = 0;
    for (int kt = 0; kt < K; kt += 32) {
        const bool more = (kt + 32) < K;
        if (more) load_tile(kt + 32);

        #pragma unroll
        for (int k16 = 0; k16 < 32; k16 += 16) {
            uint32_t ah[2][4];
            #pragma unroll
            for (int mt = 0; mt < 2; ++mt) {
                int r = mw + mt * 16 + ar;
                ah[mt][0] = *(uint32_t*)&As[st][r][k16 + ac];
                ah[mt][1] = *(uint32_t*)&As[st][r + 8][k16 + ac];
                ah[mt][2] = *(uint32_t*)&As[st][r][k16 + ac + 8];
                ah[mt][3] = *(uint32_t*)&As[st][r + 8][k16 + ac + 8];
            }
            uint32_t bb[4][2];
            #pragma unroll
            for (int nt = 0; nt < 4; ++nt) {
                int r = nw + nt * 8 + ar;
                bb[nt][0] = *(uint32_t*)&Bs[st][r][k16 + ac];
                bb[nt][1] = *(uint32_t*)&Bs[st][r][k16 + ac + 8];
            }
            #pragma unroll
            for (int mt = 0; mt < 2; ++mt)
                #pragma unroll
                for (int nt = 0; nt < 4; ++nt)
                    mma16816h(acc[mt][nt], ah[mt], bb[nt]);
        }
        if (more) {
            store_tile(st ^ 1);   // write other buffer: no barrier needed before
            __syncthreads();      // visibility for next compute
            st ^= 1;
        }
    }

    #pragma unroll
    for (int mt = 0; mt < 2; ++mt) {
        int r0 = m0 + mw + mt * 16 + ar;
        #pragma unroll
        for (int nt = 0; nt < 4; ++nt) {
            int c = n0 + nw + nt * 8 + ac;
            float2 o0 = make_float2(acc[mt][nt][0], acc[mt][nt][1]);
            float2 o1 = make_float2(acc[mt][nt][2], acc[mt][nt][3]);
            if (BRELU) {
                float b0 = __ldg(&bias[c]), b1 = __ldg(&bias[c + 1]);
                o0.x = fmaxf(o0.x + b0, 0.f); o0.y = fmaxf(o0.y + b1, 0.f);
                o1.x = fmaxf(o1.x + b0, 0.f); o1.y = fmaxf(o1.y + b1, 0.f);
            }
            if (HALF_OUT) {
                __half* Ch = (__half*)Cv;
                if (r0 < N)
                    *(__half2*)(Ch + (size_t)r0 * NOUT + c) = __floats2half2_rn(o0.x, o0.y);
                if (r0 + 8 < N)
                    *(__half2*)(Ch + (size_t)(r0 + 8) * NOUT + c) = __floats2half2_rn(o1.x, o1.y);
            } else {
                float* Cf = (float*)Cv;
                if (r0 < N)     *(float2*)(Cf + (size_t)r0 * NOUT + c) = o0;
                if (r0 + 8 < N) *(float2*)(Cf + (size_t)(r0 + 8) * NOUT + c) = o1;
            }
        }
    }
}

// ---------------------------------------------------------------------------
// fused gather + self-loop (+bias) (+relu): ONE warp per node.
// Lane covers H/32 contiguous halves -> a single LDG (uint4 for H=256,
// uint2 for H=128) per edge per lane. fp16 input always; fp16 or fp32 output.
// ---------------------------------------------------------------------------
template <int H, bool RELU, bool BIAS, bool HALF_OUT>
__global__ void gather_kernel(const __half* __restrict__ hv_in,
                              const float* __restrict__ bias,
                              void* __restrict__ out_v) {
    constexpr int LE = H / 32;                // halves per lane: 4 or 8
    int n = (blockIdx.x * blockDim.x + threadIdx.x) >> 5;
    if (n >= NNODES) return;
    int lane = threadIdx.x & 31;
    int col0 = lane * LE;

    auto loadrow = [&](int s, float* f) {
        const __half* hp = hv_in + (size_t)s * H + col0;
        if (LE == 8) {
            uint4 raw = __ldg((const uint4*)hp);
            uint32_t w[4] = {raw.x, raw.y, raw.z, raw.w};
            #pragma unroll
            for (int q = 0; q < 4; ++q) {
                __half2 h = *reinterpret_cast<__half2*>(&w[q]);
                float2 t = __half22float2(h);
                f[q * 2] = t.x; f[q * 2 + 1] = t.y;
            }
        } else {
            uint2 raw = __ldg((const uint2*)hp);
            uint32_t w[2] = {raw.x, raw.y};
            #pragma unroll
            for (int q = 0; q < 2; ++q) {
                __half2 h = *reinterpret_cast<__half2*>(&w[q]);
                float2 t = __half22float2(h);
                f[q * 2] = t.x; f[q * 2 + 1] = t.y;
            }
        }
    };

    int p  = __ldg(&g_rowptr[n]);
    int p1 = __ldg(&g_rowptr[n + 1]);

    float acc[LE];
    #pragma unroll
    for (int q = 0; q < LE; ++q) acc[q] = 0.f;

    for (; p + 3 < p1; p += 4) {
        int2 e[4];
        e[0] = __ldg(&g_epack[p]);
        e[1] = __ldg(&g_epack[p + 1]);
        e[2] = __ldg(&g_epack[p + 2]);
        e[3] = __ldg(&g_epack[p + 3]);
        float v[4][LE];
        #pragma unroll
        for (int j = 0; j < 4; ++j) loadrow(e[j].x, v[j]);
        #pragma unroll
        for (int j = 0; j < 4; ++j) {
            float cf = __int_as_float(e[j].y);
            #pragma unroll
            for (int q = 0; q < LE; ++q) acc[q] += cf * v[j][q];
        }
    }
    for (; p < p1; ++p) {
        int2 e = __ldg(&g_epack[p]);
        float cf = __int_as_float(e.y);
        float v[LE];
        loadrow(e.x, v);
        #pragma unroll
        for (int q = 0; q < LE; ++q) acc[q] += cf * v[q];
    }

    float dis = g_dis[n];
    float sc = dis * dis;
    {
        float v[LE];
        loadrow(n, v);
        #pragma unroll
        for (int q = 0; q < LE; ++q) acc[q] += sc * v[q];
    }
    if (BIAS) {
        #pragma unroll
        for (int q4 = 0; q4 < LE; q4 += 4) {
            float4 bv = __ldg((const float4*)(bias + col0 + q4));
            acc[q4 + 0] += bv.x; acc[q4 + 1] += bv.y;
            acc[q4 + 2] += bv.z; acc[q4 + 3] += bv.w;
        }
    }
    if (RELU) {
        #pragma unroll
        for (int q = 0; q < LE; ++q) acc[q] = fmaxf(acc[q], 0.f);
    }
    if (HALF_OUT) {
        __half* op = (__half*)out_v + (size_t)n * H + col0;
        uint32_t w[LE / 2];
        #pragma unroll
        for (int q = 0; q < LE / 2; ++q) {
            __half2 h = __floats2half2_rn(acc[q * 2], acc[q * 2 + 1]);
            w[q] = *reinterpret_cast<uint32_t*>(&h);
        }
        if (LE == 8) *(uint4*)op = make_uint4(w[0], w[1], w[2], w[3]);
        else         *(uint2*)op = make_uint2(w[0], w[1]);
    } else {
        float* op = (float*)out_v + (size_t)n * H + col0;
        #pragma unroll
        for (int q4 = 0; q4 < LE; q4 += 4)
            *(float4*)(op + q4) = make_float4(acc[q4], acc[q4 + 1],
                                              acc[q4 + 2], acc[q4 + 3]);
    }
}

// ---------------------------------------------------------------------------
// pooling + fused finish
// ---------------------------------------------------------------------------
__global__ void pool_kernel(const float* __restrict__ ne, const int* __restrict__ batch,
                            float* __restrict__ gsum, int N) {
    int c  = threadIdx.x;
    int n0 = blockIdx.x * 256;
    int n1 = min(n0 + 256, N);
    float acc = 0.0f;
    int cur = -1;
    for (int n = n0; n < n1; ++n) {
        int g = __ldg(&batch[n]);
        if (g != cur) {
            if (cur >= 0) atomicAdd(&gsum[cur * DOUTC + c], acc);
            acc = 0.0f;
            cur = g;
        }
        acc += ne[(size_t)n * DOUTC + c];
    }
    if (cur >= 0) atomicAdd(&gsum[cur * DOUTC + c], acc);
}

__global__ void finish_kernel(const int* __restrict__ batch, float* __restrict__ gsum,
                              const float* __restrict__ Wc, const float* __restrict__ bc,
                              float* __restrict__ logit) {
    int g = blockIdx.x;
    __shared__ float cnt_s;
    __shared__ float row[DOUTC];
    if (threadIdx.x == 0) {
        int lo = 0, hi = NNODES;
        while (lo < hi) { int mid = (lo + hi) >> 1; if (__ldg(&batch[mid]) < g) lo = mid + 1; else hi = mid; }
        int lb = lo;
        lo = 0; hi = NNODES;
        while (lo < hi) { int mid = (lo + hi) >> 1; if (__ldg(&batch[mid]) <= g) lo = mid + 1; else hi = mid; }
        cnt_s = fmaxf((float)(lo - lb), 1.0f);
    }
    __syncthreads();
    int c = threadIdx.x;
    float v = gsum[g * DOUTC + c] / cnt_s;
    gsum[g * DOUTC + c] = v;
    row[c] = v;
    __syncthreads();
    if (c < 2) {
        float s = __ldg(&bc[c]);
        #pragma unroll 8
        for (int k = 0; k < DOUTC; ++k) s += row[k] * __ldg(&Wc[k * 2 + c]);
        logit[g * 2 + c] = s;
    }
}

// ---------------------------------------------------------------------------
// launch
// ---------------------------------------------------------------------------
extern "C" void kernel_launch(void* const* d_in, const int* in_sizes, int n_in,
                              void* d_out, int out_size) {
    const float* x     = (const float*)d_in[0];
    const int*   ei    = (const int*)d_in[1];
    const int*   batch = (const int*)d_in[2];
    const float* W_in  = (const float*)d_in[3];
    const float* b_in  = (const float*)d_in[4];
    const float* W_mid = (const float*)d_in[5];
    const float* b_mid = (const float*)d_in[6];
    const float* W_out = (const float*)d_in[7];
    const float* b_out = (const float*)d_in[8];
    const float* W_cls = (const float*)d_in[9];
    const float* b_cls = (const float*)d_in[10];

    const int* src = ei;
    const int* dst = ei + NEDGES;

    float *bufA, *bufB;
    __half *w1, *w2, *w3;
    cudaGetSymbolAddress((void**)&bufA, g_bufA);
    cudaGetSymbolAddress((void**)&bufB, g_bufB);
    cudaGetSymbolAddress((void**)&w1, g_w1);
    cudaGetSymbolAddress((void**)&w2, g_w2);
    cudaGetSymbolAddress((void**)&w3, g_w3);

    float* node   = (float*)d_out;
    float* gsum   = node + (size_t)NNODES * DOUTC;
    float* logit  = gsum + NGRAPH * DOUTC;

    const int T = 256;
    const int GW = (NNODES * 32 + T - 1) / T;   // 1 warp per node

    // ----- prep (weights + zero counters), x->fp16, CSR build -----
    prep_kernel<<<680, T>>>(W_in, W_mid, W_out);
    tohalf_kernel<<<640, T>>>((const float4*)x, (uint2*)bufB, NNODES * DIN / 4);
    hist_kernel<<<(NEDGES + T - 1) / T, T>>>(dst, NEDGES);
    scan1_kernel<<<SCAN_NB, SCAN_B>>>((float4*)gsum);
    scan23_kernel<<<SCAN_NB, SCAN_B>>>();
    csrfill_kernel<<<(NEDGES + T - 1) / T, T>>>(src, dst, NEDGES);

    const int GB = (NNODES + 127) / 128;   // 313

    // ----- layer 1: propagate(x fp16)->fp16, fp16 GEMM + bias + relu -> fp16 -----
    gather_kernel<DIN, false, false, true><<<GW, T>>>((const __half*)bufB, nullptr, bufA);
    mma_gemm_kernel<DIN, true, true><<<dim3(2, GB), 512>>>((const __half*)bufA, w1,
                                                           b_in, bufB, NNODES, DH);

    // ----- layer 2: fp16 GEMM -> fp16, propagate + bias + relu -> fp16 -----
    mma_gemm_kernel<DH, false, true><<<dim3(2, GB), 512>>>((const __half*)bufB, w2,
                                                           nullptr, bufA, NNODES, DH);
    gather_kernel<DH, true, true, true><<<GW, T>>>((const __half*)bufA, b_mid, bufB);

    // ----- layer 3: fp16 GEMM -> fp16, propagate + bias -> fp32 node -----
    mma_gemm_kernel<DH, false, true><<<dim3(1, GB), 512>>>((const __half*)bufB, w3,
                                                           nullptr, bufA, NNODES, DOUTC);
    gather_kernel<DOUTC, false, true, false><<<GW, T>>>((const __half*)bufA, b_out, node);

    // ----- mean pool + classifier -----
    pool_kernel<<<(NNODES + 255) / 256, 128>>>(node, batch, gsum, NNODES);
    finish_kernel<<<NGRAPH, DOUTC>>>(batch, gsum, W_cls, b_cls, logit);
}

// round 17
// speedup vs baseline: 1.9648x; 1.1212x over previous
#include <cuda_runtime.h>
#include <cuda_bf16.h>
#include <cuda_fp16.h>
#include <stdint.h>

#define NNODES 40000
#define NEDGES 640000
#define NGRAPH 64
#define DIN    128
#define DH     256
#define DOUTC  128

#define SCAN_B 256
#define SCAN_NB ((NNODES + SCAN_B - 1) / SCAN_B)   // 157

// ---- scratch (no allocations allowed) ----
__device__ float g_bufA[NNODES * DH];
__device__ float g_bufB[NNODES * DH];
__device__ float g_dis[NNODES];
// CSR scratch
__device__ int   g_cnti[NNODES];
__device__ int   g_rowptr[NNODES + 1];
__device__ int   g_cursor[NNODES];
__device__ int2  g_epack[NEDGES];          // {src, coef-as-int}
__device__ int   g_bsum[SCAN_NB];
// weights transposed to [NOUT, K] row-major, fp16
__device__ __half g_w1[DH * DIN];
__device__ __half g_w2[DH * DH];
__device__ __half g_w3[DOUTC * DH];

// ---------------------------------------------------------------------------
// prep: weight transpose+fp16, zero degree counters, x -> fp16 (all fused)
// ---------------------------------------------------------------------------
__device__ __forceinline__ void wprep(const float* __restrict__ W,
                                      __half* __restrict__ wh,
                                      int K, int NOUT, int idx) {
    int k = idx / NOUT, n = idx - k * NOUT;
    wh[(size_t)n * K + k] = __float2half_rn(W[idx]);
}

__global__ void prep_kernel(const float* __restrict__ W1, const float* __restrict__ W2,
                            const float* __restrict__ W3, const float4* __restrict__ x4,
                            uint2* __restrict__ xh) {
    constexpr int E1 = DIN * DH;
    constexpr int E2 = E1 + DH * DH;
    constexpr int E3 = E2 + DH * DOUTC;
    constexpr int E4 = E3 + NNODES;
    constexpr int TOT = E4 + NNODES * DIN / 4;
    int i = blockIdx.x * blockDim.x + threadIdx.x;
    for (; i < TOT; i += gridDim.x * blockDim.x) {
        if (i < E1)       wprep(W1, g_w1, DIN, DH, i);
        else if (i < E2)  wprep(W2, g_w2, DH, DH, i - E1);
        else if (i < E3)  wprep(W3, g_w3, DH, DOUTC, i - E2);
        else if (i < E4)  g_cnti[i - E3] = 0;
        else {
            int j = i - E4;
            float4 v = x4[j];
            __half2 p0 = __floats2half2_rn(v.x, v.y);
            __half2 p1 = __floats2half2_rn(v.z, v.w);
            uint2 o;
            o.x = *reinterpret_cast<uint32_t*>(&p0);
            o.y = *reinterpret_cast<uint32_t*>(&p1);
            xh[j] = o;
        }
    }
}

__global__ void hist_kernel(const int* __restrict__ dst, int E) {
    int e = blockIdx.x * blockDim.x + threadIdx.x;
    if (e < E) atomicAdd(&g_cnti[dst[e]], 1);
}

// ---------------------------------------------------------------------------
// scan phase 1: block sums (+ dis piggybacked)
// ---------------------------------------------------------------------------
__global__ void scan1_kernel() {
    __shared__ int s[SCAN_B];
    int i = blockIdx.x * SCAN_B + threadIdx.x;
    int v = (i < NNODES) ? g_cnti[i] : 0;
    if (i < NNODES) g_dis[i] = rsqrtf((float)v + 1.0f);
    s[threadIdx.x] = v;
    __syncthreads();
    for (int off = SCAN_B / 2; off > 0; off >>= 1) {
        if (threadIdx.x < off) s[threadIdx.x] += s[threadIdx.x + off];
        __syncthreads();
    }
    if (threadIdx.x == 0) g_bsum[blockIdx.x] = s[0];
}

// scan phase 2+3 fused
__global__ void scan23_kernel() {
    __shared__ int s[SCAN_B];
    __shared__ int bpre_s;
    int t = threadIdx.x;
    int i = blockIdx.x * SCAN_B + t;

    int v = (t < SCAN_NB && t < blockIdx.x) ? g_bsum[t] : 0;
    s[t] = v;
    __syncthreads();
    for (int off = SCAN_B / 2; off > 0; off >>= 1) {
        if (t < off) s[t] += s[t + off];
        __syncthreads();
    }
    if (t == 0) bpre_s = s[0];
    __syncthreads();
    int bpre = bpre_s;
    __syncthreads();

    int v0 = (i < NNODES) ? g_cnti[i] : 0;
    s[t] = v0;
    __syncthreads();
    for (int off = 1; off < SCAN_B; off <<= 1) {
        int u = (t >= off) ? s[t - off] : 0;
        __syncthreads();
        s[t] += u;
        __syncthreads();
    }
    if (i < NNODES) {
        int ex = bpre + s[t] - v0;
        g_rowptr[i] = ex;
        g_cursor[i] = ex;
    }
    if (blockIdx.x == 0 && t == 0) g_rowptr[NNODES] = NEDGES;
}

__global__ void csrfill_kernel(const int* __restrict__ src, const int* __restrict__ dst,
                               int E) {
    int e = blockIdx.x * blockDim.x + threadIdx.x;
    if (e >= E) return;
    int s = src[e], d = dst[e];
    int p = atomicAdd(&g_cursor[d], 1);
    g_epack[p] = make_int2(s, __float_as_int(g_dis[s] * g_dis[d]));
}

// ---------------------------------------------------------------------------
// mma helper: fp16 inputs, fp32 accum
// ---------------------------------------------------------------------------
__device__ __forceinline__ void mma16816h(float* c, const uint32_t* a, const uint32_t* b) {
    asm volatile(
        "mma.sync.aligned.m16n8k16.row.col.f32.f16.f16.f32 "
        "{%0,%1,%2,%3}, {%4,%5,%6,%7}, {%8,%9}, {%0,%1,%2,%3};"
        : "+f"(c[0]), "+f"(c[1]), "+f"(c[2]), "+f"(c[3])
        : "r"(a[0]), "r"(a[1]), "r"(a[2]), "r"(a[3]), "r"(b[0]), "r"(b[1]));
}

// ---------------------------------------------------------------------------
// fp16 GEMM (single MMA per tile), double-buffered SMEM (1 sync/iter)
// 128x128 tile. HALF_OUT: fp16 C store, else fp32.
// ---------------------------------------------------------------------------
template <int K, bool BRELU, bool HALF_OUT>
__global__ void __launch_bounds__(512)
mma_gemm_kernel(const __half* __restrict__ A, const __half* __restrict__ W,
                const float* __restrict__ bias, void* __restrict__ Cv, int N, int NOUT) {
    __shared__ __half As[2][128][40];
    __shared__ __half Bs[2][128][40];

    const int tid = threadIdx.x;
    const int wid = tid >> 5, lane = tid & 31;
    const int mw = (wid & 3) * 32;
    const int nw = (wid >> 2) * 32;
    const int m0 = blockIdx.y * 128;
    const int n0 = blockIdx.x * 128;

    float acc[2][4][4] = {};
    const int ar = lane >> 2;
    const int ac = (lane & 3) * 2;

    uint32_t va[4];           // raw fp16x2
    uint4 vb;
    const int br = tid >> 2;
    const int bc = (tid & 3) * 8;

    auto load_tile = [&](int kt) {
        #pragma unroll
        for (int it = 0; it < 4; ++it) {
            int idx = tid + it * 512;
            int r  = idx >> 4;
            int kp = (idx & 15) * 2;
            int rr = min(m0 + r, N - 1);
            va[it] = __ldg((const uint32_t*)(A + (size_t)rr * K + kt + kp));
        }
        vb = *(const uint4*)(W + (size_t)(n0 + br) * K + kt + bc);
    };
    auto store_tile = [&](int st) {
        #pragma unroll
        for (int it = 0; it < 4; ++it) {
            int idx = tid + it * 512;
            int r  = idx >> 4;
            int kp = (idx & 15) * 2;
            *(uint32_t*)&As[st][r][kp] = va[it];
        }
        *(uint4*)&Bs[st][br][bc] = vb;
    };

    load_tile(0);
    store_tile(0);
    __syncthreads();

    int st = 0;
    for (int kt = 0; kt < K; kt += 32) {
        const bool more = (kt + 32) < K;
        if (more) load_tile(kt + 32);

        #pragma unroll
        for (int k16 = 0; k16 < 32; k16 += 16) {
            uint32_t ah[2][4];
            #pragma unroll
            for (int mt = 0; mt < 2; ++mt) {
                int r = mw + mt * 16 + ar;
                ah[mt][0] = *(uint32_t*)&As[st][r][k16 + ac];
                ah[mt][1] = *(uint32_t*)&As[st][r + 8][k16 + ac];
                ah[mt][2] = *(uint32_t*)&As[st][r][k16 + ac + 8];
                ah[mt][3] = *(uint32_t*)&As[st][r + 8][k16 + ac + 8];
            }
            uint32_t bb[4][2];
            #pragma unroll
            for (int nt = 0; nt < 4; ++nt) {
                int r = nw + nt * 8 + ar;
                bb[nt][0] = *(uint32_t*)&Bs[st][r][k16 + ac];
                bb[nt][1] = *(uint32_t*)&Bs[st][r][k16 + ac + 8];
            }
            #pragma unroll
            for (int mt = 0; mt < 2; ++mt)
                #pragma unroll
                for (int nt = 0; nt < 4; ++nt)
                    mma16816h(acc[mt][nt], ah[mt], bb[nt]);
        }
        if (more) {
            store_tile(st ^ 1);
            __syncthreads();
            st ^= 1;
        }
    }

    #pragma unroll
    for (int mt = 0; mt < 2; ++mt) {
        int r0 = m0 + mw + mt * 16 + ar;
        #pragma unroll
        for (int nt = 0; nt < 4; ++nt) {
            int c = n0 + nw + nt * 8 + ac;
            float2 o0 = make_float2(acc[mt][nt][0], acc[mt][nt][1]);
            float2 o1 = make_float2(acc[mt][nt][2], acc[mt][nt][3]);
            if (BRELU) {
                float b0 = __ldg(&bias[c]), b1 = __ldg(&bias[c + 1]);
                o0.x = fmaxf(o0.x + b0, 0.f); o0.y = fmaxf(o0.y + b1, 0.f);
                o1.x = fmaxf(o1.x + b0, 0.f); o1.y = fmaxf(o1.y + b1, 0.f);
            }
            if (HALF_OUT) {
                __half* Ch = (__half*)Cv;
                if (r0 < N)
                    *(__half2*)(Ch + (size_t)r0 * NOUT + c) = __floats2half2_rn(o0.x, o0.y);
                if (r0 + 8 < N)
                    *(__half2*)(Ch + (size_t)(r0 + 8) * NOUT + c) = __floats2half2_rn(o1.x, o1.y);
            } else {
                float* Cf = (float*)Cv;
                if (r0 < N)     *(float2*)(Cf + (size_t)r0 * NOUT + c) = o0;
                if (r0 + 8 < N) *(float2*)(Cf + (size_t)(r0 + 8) * NOUT + c) = o1;
            }
        }
    }
}

// ---------------------------------------------------------------------------
// fused gather + self-loop (+bias) (+relu): ONE warp per node, single LDG/edge
// ---------------------------------------------------------------------------
template <int H, bool RELU, bool BIAS, bool HALF_OUT>
__global__ void gather_kernel(const __half* __restrict__ hv_in,
                              const float* __restrict__ bias,
                              void* __restrict__ out_v) {
    constexpr int LE = H / 32;                // halves per lane: 4 or 8
    int n = (blockIdx.x * blockDim.x + threadIdx.x) >> 5;
    if (n >= NNODES) return;
    int lane = threadIdx.x & 31;
    int col0 = lane * LE;

    auto loadrow = [&](int s, float* f) {
        const __half* hp = hv_in + (size_t)s * H + col0;
        if (LE == 8) {
            uint4 raw = __ldg((const uint4*)hp);
            uint32_t w[4] = {raw.x, raw.y, raw.z, raw.w};
            #pragma unroll
            for (int q = 0; q < 4; ++q) {
                __half2 h = *reinterpret_cast<__half2*>(&w[q]);
                float2 t = __half22float2(h);
                f[q * 2] = t.x; f[q * 2 + 1] = t.y;
            }
        } else {
            uint2 raw = __ldg((const uint2*)hp);
            uint32_t w[2] = {raw.x, raw.y};
            #pragma unroll
            for (int q = 0; q < 2; ++q) {
                __half2 h = *reinterpret_cast<__half2*>(&w[q]);
                float2 t = __half22float2(h);
                f[q * 2] = t.x; f[q * 2 + 1] = t.y;
            }
        }
    };

    int p  = __ldg(&g_rowptr[n]);
    int p1 = __ldg(&g_rowptr[n + 1]);

    float acc[LE];
    #pragma unroll
    for (int q = 0; q < LE; ++q) acc[q] = 0.f;

    for (; p + 3 < p1; p += 4) {
        int2 e[4];
        e[0] = __ldg(&g_epack[p]);
        e[1] = __ldg(&g_epack[p + 1]);
        e[2] = __ldg(&g_epack[p + 2]);
        e[3] = __ldg(&g_epack[p + 3]);
        float v[4][LE];
        #pragma unroll
        for (int j = 0; j < 4; ++j) loadrow(e[j].x, v[j]);
        #pragma unroll
        for (int j = 0; j < 4; ++j) {
            float cf = __int_as_float(e[j].y);
            #pragma unroll
            for (int q = 0; q < LE; ++q) acc[q] += cf * v[j][q];
        }
    }
    for (; p < p1; ++p) {
        int2 e = __ldg(&g_epack[p]);
        float cf = __int_as_float(e.y);
        float v[LE];
        loadrow(e.x, v);
        #pragma unroll
        for (int q = 0; q < LE; ++q) acc[q] += cf * v[q];
    }

    float dis = g_dis[n];
    float sc = dis * dis;
    {
        float v[LE];
        loadrow(n, v);
        #pragma unroll
        for (int q = 0; q < LE; ++q) acc[q] += sc * v[q];
    }
    if (BIAS) {
        #pragma unroll
        for (int q4 = 0; q4 < LE; q4 += 4) {
            float4 bv = __ldg((const float4*)(bias + col0 + q4));
            acc[q4 + 0] += bv.x; acc[q4 + 1] += bv.y;
            acc[q4 + 2] += bv.z; acc[q4 + 3] += bv.w;
        }
    }
    if (RELU) {
        #pragma unroll
        for (int q = 0; q < LE; ++q) acc[q] = fmaxf(acc[q], 0.f);
    }
    if (HALF_OUT) {
        __half* op = (__half*)out_v + (size_t)n * H + col0;
        uint32_t w[LE / 2];
        #pragma unroll
        for (int q = 0; q < LE / 2; ++q) {
            __half2 h = __floats2half2_rn(acc[q * 2], acc[q * 2 + 1]);
            w[q] = *reinterpret_cast<uint32_t*>(&h);
        }
        if (LE == 8) *(uint4*)op = make_uint4(w[0], w[1], w[2], w[3]);
        else         *(uint2*)op = make_uint2(w[0], w[1]);
    } else {
        float* op = (float*)out_v + (size_t)n * H + col0;
        #pragma unroll
        for (int q4 = 0; q4 < LE; q4 += 4)
            *(float4*)(op + q4) = make_float4(acc[q4], acc[q4 + 1],
                                              acc[q4 + 2], acc[q4 + 3]);
    }
}

// ---------------------------------------------------------------------------
// fused mean-pool + classifier: one block per graph (batch is sorted)
// ---------------------------------------------------------------------------
__global__ void poolfinish_kernel(const float* __restrict__ node,
                                  const int* __restrict__ batch,
                                  float* __restrict__ gsum,
                                  const float* __restrict__ Wc,
                                  const float* __restrict__ bc,
                                  float* __restrict__ logit) {
    int g = blockIdx.x;          // 0..63
    int c = threadIdx.x;         // 0..127
    __shared__ int lb_s, ub_s;
    __shared__ float row[DOUTC];

    if (c < 2) {
        int key = g + c;         // c==0: lower bound of g; c==1: lower bound of g+1
        int lo = 0, hi = NNODES;
        while (lo < hi) {
            int mid = (lo + hi) >> 1;
            if (__ldg(&batch[mid]) < key) lo = mid + 1; else hi = mid;
        }
        if (c == 0) lb_s = lo; else ub_s = lo;
    }
    __syncthreads();
    int lb = lb_s, ub = ub_s;

    float acc = 0.0f;
    int n = lb;
    for (; n + 3 < ub; n += 4) {
        float a0 = __ldg(&node[(size_t)n * DOUTC + c]);
        float a1 = __ldg(&node[(size_t)(n + 1) * DOUTC + c]);
        float a2 = __ldg(&node[(size_t)(n + 2) * DOUTC + c]);
        float a3 = __ldg(&node[(size_t)(n + 3) * DOUTC + c]);
        acc += (a0 + a1) + (a2 + a3);
    }
    for (; n < ub; ++n) acc += __ldg(&node[(size_t)n * DOUTC + c]);

    float cnt = fmaxf((float)(ub - lb), 1.0f);
    float v = acc / cnt;
    gsum[g * DOUTC + c] = v;
    row[c] = v;
    __syncthreads();
    if (c < 2) {
        float s = __ldg(&bc[c]);
        #pragma unroll 8
        for (int k = 0; k < DOUTC; ++k) s += row[k] * __ldg(&Wc[k * 2 + c]);
        logit[g * 2 + c] = s;
    }
}

// ---------------------------------------------------------------------------
// launch
// ---------------------------------------------------------------------------
extern "C" void kernel_launch(void* const* d_in, const int* in_sizes, int n_in,
                              void* d_out, int out_size) {
    const float* x     = (const float*)d_in[0];
    const int*   ei    = (const int*)d_in[1];
    const int*   batch = (const int*)d_in[2];
    const float* W_in  = (const float*)d_in[3];
    const float* b_in  = (const float*)d_in[4];
    const float* W_mid = (const float*)d_in[5];
    const float* b_mid = (const float*)d_in[6];
    const float* W_out = (const float*)d_in[7];
    const float* b_out = (const float*)d_in[8];
    const float* W_cls = (const float*)d_in[9];
    const float* b_cls = (const float*)d_in[10];

    const int* src = ei;
    const int* dst = ei + NEDGES;

    float *bufA, *bufB;
    __half *w1, *w2, *w3;
    cudaGetSymbolAddress((void**)&bufA, g_bufA);
    cudaGetSymbolAddress((void**)&bufB, g_bufB);
    cudaGetSymbolAddress((void**)&w1, g_w1);
    cudaGetSymbolAddress((void**)&w2, g_w2);
    cudaGetSymbolAddress((void**)&w3, g_w3);

    float* node   = (float*)d_out;
    float* gsum   = node + (size_t)NNODES * DOUTC;
    float* logit  = gsum + NGRAPH * DOUTC;

    const int T = 256;
    const int GW = (NNODES * 32 + T - 1) / T;   // 1 warp per node

    // ----- prep (weights + zero counters + x->fp16), CSR build -----
    prep_kernel<<<1184, T>>>(W_in, W_mid, W_out, (const float4*)x, (uint2*)bufB);
    hist_kernel<<<(NEDGES + T - 1) / T, T>>>(dst, NEDGES);
    scan1_kernel<<<SCAN_NB, SCAN_B>>>();
    scan23_kernel<<<SCAN_NB, SCAN_B>>>();
    csrfill_kernel<<<(NEDGES + T - 1) / T, T>>>(src, dst, NEDGES);

    const int GB = (NNODES + 127) / 128;   // 313

    // ----- layer 1: propagate(x fp16)->fp16, fp16 GEMM + bias + relu -> fp16 -----
    gather_kernel<DIN, false, false, true><<<GW, T>>>((const __half*)bufB, nullptr, bufA);
    mma_gemm_kernel<DIN, true, true><<<dim3(2, GB), 512>>>((const __half*)bufA, w1,
                                                           b_in, bufB, NNODES, DH);

    // ----- layer 2: fp16 GEMM -> fp16, propagate + bias + relu -> fp16 -----
    mma_gemm_kernel<DH, false, true><<<dim3(2, GB), 512>>>((const __half*)bufB, w2,
                                                           nullptr, bufA, NNODES, DH);
    gather_kernel<DH, true, true, true><<<GW, T>>>((const __half*)bufA, b_mid, bufB);

    // ----- layer 3: fp16 GEMM -> fp16, propagate + bias -> fp32 node -----
    mma_gemm_kernel<DH, false, true><<<dim3(1, GB), 512>>>((const __half*)bufB, w3,
                                                           nullptr, bufA, NNODES, DOUTC);
    gather_kernel<DOUTC, false, true, false><<<GW, T>>>((const __half*)bufA, b_out, node);

    // ----- fused mean pool + classifier -----
    poolfinish_kernel<<<NGRAPH, DOUTC>>>(node, batch, gsum, W_cls, b_cls, logit);
}